// round 2
// baseline (speedup 1.0000x reference)
#include <cuda_runtime.h>
#include <cuda_bf16.h>
#include <math.h>

// Problem constants
#define BB    512
#define OO    16
#define OBS   128
#define AA    4
#define HH    512
#define NNODE (BB*OO)          // 8192
#define LN_EPS 1e-5f

// ---------------- scratch (device globals; no allocations) ----------------
__device__ __align__(16) float g_PQ[(size_t)NNODE * 1024];  // [8192, 1024]: cols 0..511 = P, 512..1023 = Q
__device__ __align__(16) float g_S [(size_t)NNODE * HH];    // per-node sum of edge h2
__device__ __align__(16) float g_AGG[(size_t)NNODE * HH];   // agg = S@eW3 + 15*eb3
__device__ __align__(16) float g_H1[(size_t)NNODE * HH];    // node mlp hidden 1
__device__ __align__(16) float g_H2[(size_t)NNODE * HH];    // node mlp hidden 2

// ---------------- generic 64x64 tiled GEMM (up to two K segments) ----------------
// out[m,n] = sum_seg X_seg[m,:] @ W_seg  (+ bias[n]*bscale) (+ act row) (relu)
// X row-major with ld = K_seg; W row-major [K_seg, N] with ld = N.
__global__ void __launch_bounds__(256) gemm_kernel(
    const float* __restrict__ X0, int K0, const float* __restrict__ W0,
    const float* __restrict__ X1, int K1, const float* __restrict__ W1,
    int N,
    const float* __restrict__ bias, float bscale,
    const float* __restrict__ actW, const int* __restrict__ action,
    float* __restrict__ out, int ldout, int relu)
{
    __shared__ __align__(16) float Xs[16][64];
    __shared__ __align__(16) float Ws[16][64];

    const int tid = threadIdx.x;
    const int bm = blockIdx.y * 64, bn = blockIdx.x * 64;
    const int tr = tid >> 4, tc = tid & 15;

    float acc[4][4];
#pragma unroll
    for (int i = 0; i < 4; ++i)
#pragma unroll
        for (int j = 0; j < 4; ++j) acc[i][j] = 0.f;

    const int lr = tid >> 2;          // 0..63: X row in tile
    const int lk = (tid & 3) * 4;     // 0,4,8,12: k offset
    const int wr = tid >> 4;          // 0..15: W k-row
    const int wc = (tid & 15) * 4;    // col offset

#pragma unroll
    for (int seg = 0; seg < 2; ++seg) {
        const float* X = seg ? X1 : X0;
        const float* W = seg ? W1 : W0;
        const int K = seg ? K1 : K0;
        if (K == 0) continue;
        for (int kt = 0; kt < K; kt += 16) {
            float4 xv = *(const float4*)(X + (size_t)(bm + lr) * K + kt + lk);
            Xs[lk + 0][lr] = xv.x; Xs[lk + 1][lr] = xv.y;
            Xs[lk + 2][lr] = xv.z; Xs[lk + 3][lr] = xv.w;
            float4 wv = *(const float4*)(W + (size_t)(kt + wr) * N + bn + wc);
            *(float4*)&Ws[wr][wc] = wv;
            __syncthreads();
#pragma unroll
            for (int k = 0; k < 16; ++k) {
                float a[4], b4[4];
                *(float4*)a  = *(const float4*)&Xs[k][tr * 4];
                *(float4*)b4 = *(const float4*)&Ws[k][tc * 4];
#pragma unroll
                for (int i = 0; i < 4; ++i)
#pragma unroll
                    for (int j = 0; j < 4; ++j)
                        acc[i][j] += a[i] * b4[j];
            }
            __syncthreads();
        }
    }

#pragma unroll
    for (int i = 0; i < 4; ++i) {
        const int m = bm + tr * 4 + i;
        int t = -1;
        if (actW) {
            const int bidx = m >> 4, o = m & 15;
            const int a = action[bidx];
            t = a - 4 * o;
        }
#pragma unroll
        for (int j = 0; j < 4; ++j) {
            const int n = bn + tc * 4 + j;
            float v = acc[i][j];
            if (bias) v += bias[n] * bscale;
            if (actW && (unsigned)t < 4u) v += actW[(size_t)t * N + n];
            if (relu) v = fmaxf(v, 0.f);
            out[(size_t)m * ldout + n] = v;
        }
    }
}

// ---------------- fused edge layer-2 + LN + ReLU + per-node reduce ----------------
// One block per source node i. rows = 15 edges (j != i). Builds
// h1[15,512] = relu(P[i] + Q[j] + eb1) in smem (k-major), computes z2 = h1@eW2 + eb2,
// LN over 512, relu, and writes S[i] = sum over 15 rows. No edge_attr materialized.
__global__ void __launch_bounds__(256, 2) edge_fused_kernel(
    const float* __restrict__ eb1, const float* __restrict__ W,
    const float* __restrict__ b2, const float* __restrict__ gam,
    const float* __restrict__ bet)
{
    __shared__ __align__(16) float h1t[512 * 16];  // k-major, 16 padded rows (row 15 = 0)
    __shared__ float red_s[15 * 8];
    __shared__ float red_q[15 * 8];
    __shared__ float mu_s[15], rs_s[15];

    const int tid = threadIdx.x;
    const int g = blockIdx.x;
    const int b = g >> 4, o = g & 15;
    const float* Prow = g_PQ + (size_t)g * 1024;

    // fill h1 (transposed, padded)
#pragma unroll 4
    for (int it = 0; it < 32; ++it) {
        const int idx = tid + it * 256;
        const int k = idx >> 4, r = idx & 15;
        float v = 0.f;
        if (r < 15) {
            const int jj = r + (r >= o);
            const float* Qrow = g_PQ + ((size_t)(b * 16 + jj)) * 1024 + 512;
            v = fmaxf(Prow[k] + Qrow[k] + eb1[k], 0.f);
        }
        h1t[k * 16 + r] = v;
    }
    __syncthreads();

    const int c0 = tid, c1 = tid + 256;
    float acc0[15], acc1[15];
#pragma unroll
    for (int r = 0; r < 15; ++r) { acc0[r] = 0.f; acc1[r] = 0.f; }

    const float* w0p = W + c0;
    const float* w1p = W + c1;
#pragma unroll 2
    for (int k = 0; k < 512; ++k) {
        const float w0 = __ldg(w0p + (size_t)k * 512);
        const float w1 = __ldg(w1p + (size_t)k * 512);
        const float4* h4 = (const float4*)(h1t + k * 16);
        const float4 A = h4[0], B4 = h4[1], C = h4[2], D = h4[3];
        const float hv[15] = {A.x, A.y, A.z, A.w, B4.x, B4.y, B4.z, B4.w,
                              C.x, C.y, C.z, C.w, D.x, D.y, D.z};
#pragma unroll
        for (int r = 0; r < 15; ++r) {
            acc0[r] += hv[r] * w0;
            acc1[r] += hv[r] * w1;
        }
    }

    const float be0 = b2[c0], be1 = b2[c1];
    float ps[15], pq[15];
#pragma unroll
    for (int r = 0; r < 15; ++r) {
        const float z0 = acc0[r] + be0, z1 = acc1[r] + be1;
        acc0[r] = z0; acc1[r] = z1;
        ps[r] = z0 + z1;
        pq[r] = z0 * z0 + z1 * z1;
    }
    const int lane = tid & 31, wid = tid >> 5;
#pragma unroll
    for (int off = 16; off; off >>= 1) {
#pragma unroll
        for (int r = 0; r < 15; ++r) {
            ps[r] += __shfl_xor_sync(0xffffffffu, ps[r], off);
            pq[r] += __shfl_xor_sync(0xffffffffu, pq[r], off);
        }
    }
    if (lane == 0) {
#pragma unroll
        for (int r = 0; r < 15; ++r) { red_s[r * 8 + wid] = ps[r]; red_q[r * 8 + wid] = pq[r]; }
    }
    __syncthreads();
    if (tid < 15) {
        float s = 0.f, q = 0.f;
#pragma unroll
        for (int w = 0; w < 8; ++w) { s += red_s[tid * 8 + w]; q += red_q[tid * 8 + w]; }
        const float mu = s * (1.f / 512.f);
        const float var = q * (1.f / 512.f) - mu * mu;
        mu_s[tid] = mu;
        rs_s[tid] = rsqrtf(var + LN_EPS);
    }
    __syncthreads();

    const float g0 = gam[c0], g1 = gam[c1];
    const float bb0 = bet[c0], bb1 = bet[c1];
    float s0 = 0.f, s1 = 0.f;
#pragma unroll
    for (int r = 0; r < 15; ++r) {
        const float mu = mu_s[r], rs = rs_s[r];
        s0 += fmaxf((acc0[r] - mu) * rs * g0 + bb0, 0.f);
        s1 += fmaxf((acc1[r] - mu) * rs * g1 + bb1, 0.f);
    }
    g_S[(size_t)g * 512 + c0] = s0;
    g_S[(size_t)g * 512 + c1] = s1;
}

// ---------------- fused node layer-2 + LN + ReLU ----------------
// One block per 16 node rows; same GEMM structure; per-row output (no reduce).
__global__ void __launch_bounds__(256, 2) node_ln_kernel(
    const float* __restrict__ X, const float* __restrict__ W,
    const float* __restrict__ b2, const float* __restrict__ gam,
    const float* __restrict__ bet, float* __restrict__ Y)
{
    __shared__ __align__(16) float xt[512 * 16];
    __shared__ float red_s[16 * 8];
    __shared__ float red_q[16 * 8];
    __shared__ float mu_s[16], rs_s[16];

    const int tid = threadIdx.x;
    const int g0row = blockIdx.x * 16;

#pragma unroll 4
    for (int it = 0; it < 32; ++it) {
        const int idx = tid + it * 256;
        const int k = idx >> 4, r = idx & 15;
        xt[k * 16 + r] = X[(size_t)(g0row + r) * 512 + k];
    }
    __syncthreads();

    const int c0 = tid, c1 = tid + 256;
    float acc0[16], acc1[16];
#pragma unroll
    for (int r = 0; r < 16; ++r) { acc0[r] = 0.f; acc1[r] = 0.f; }

    const float* w0p = W + c0;
    const float* w1p = W + c1;
#pragma unroll 2
    for (int k = 0; k < 512; ++k) {
        const float w0 = __ldg(w0p + (size_t)k * 512);
        const float w1 = __ldg(w1p + (size_t)k * 512);
        const float4* h4 = (const float4*)(xt + k * 16);
        const float4 A = h4[0], B4 = h4[1], C = h4[2], D = h4[3];
        const float hv[16] = {A.x, A.y, A.z, A.w, B4.x, B4.y, B4.z, B4.w,
                              C.x, C.y, C.z, C.w, D.x, D.y, D.z, D.w};
#pragma unroll
        for (int r = 0; r < 16; ++r) {
            acc0[r] += hv[r] * w0;
            acc1[r] += hv[r] * w1;
        }
    }

    const float be0 = b2[c0], be1 = b2[c1];
    float ps[16], pq[16];
#pragma unroll
    for (int r = 0; r < 16; ++r) {
        const float z0 = acc0[r] + be0, z1 = acc1[r] + be1;
        acc0[r] = z0; acc1[r] = z1;
        ps[r] = z0 + z1;
        pq[r] = z0 * z0 + z1 * z1;
    }
    const int lane = tid & 31, wid = tid >> 5;
#pragma unroll
    for (int off = 16; off; off >>= 1) {
#pragma unroll
        for (int r = 0; r < 16; ++r) {
            ps[r] += __shfl_xor_sync(0xffffffffu, ps[r], off);
            pq[r] += __shfl_xor_sync(0xffffffffu, pq[r], off);
        }
    }
    if (lane == 0) {
#pragma unroll
        for (int r = 0; r < 16; ++r) { red_s[r * 8 + wid] = ps[r]; red_q[r * 8 + wid] = pq[r]; }
    }
    __syncthreads();
    if (tid < 16) {
        float s = 0.f, q = 0.f;
#pragma unroll
        for (int w = 0; w < 8; ++w) { s += red_s[tid * 8 + w]; q += red_q[tid * 8 + w]; }
        const float mu = s * (1.f / 512.f);
        const float var = q * (1.f / 512.f) - mu * mu;
        mu_s[tid] = mu;
        rs_s[tid] = rsqrtf(var + LN_EPS);
    }
    __syncthreads();

    const float gg0 = gam[c0], gg1 = gam[c1];
    const float bb0 = bet[c0], bb1 = bet[c1];
#pragma unroll
    for (int r = 0; r < 16; ++r) {
        const float mu = mu_s[r], rs = rs_s[r];
        Y[(size_t)(g0row + r) * 512 + c0] = fmaxf((acc0[r] - mu) * rs * gg0 + bb0, 0.f);
        Y[(size_t)(g0row + r) * 512 + c1] = fmaxf((acc1[r] - mu) * rs * gg1 + bb1, 0.f);
    }
}

// ---------------- launch ----------------
extern "C" void kernel_launch(void* const* d_in, const int* in_sizes, int n_in,
                              void* d_out, int out_size)
{
    const float* states = (const float*)d_in[0];
    const int*   action = (const int*)d_in[1];   // JAX x64 disabled -> int32 on device
    const float* eW1 = (const float*)d_in[2];
    const float* eb1 = (const float*)d_in[3];
    const float* eW2 = (const float*)d_in[4];
    const float* eb2 = (const float*)d_in[5];
    const float* eg  = (const float*)d_in[6];
    const float* ebt = (const float*)d_in[7];
    const float* eW3 = (const float*)d_in[8];
    const float* eb3 = (const float*)d_in[9];
    const float* nW1 = (const float*)d_in[10];
    const float* nb1 = (const float*)d_in[11];
    const float* nW2 = (const float*)d_in[12];
    const float* nb2 = (const float*)d_in[13];
    const float* ng  = (const float*)d_in[14];
    const float* nbt = (const float*)d_in[15];
    const float* nW3 = (const float*)d_in[16];
    const float* nb3 = (const float*)d_in[17];
    float* out = (float*)d_out;

    float *pPQ, *pS, *pAGG, *pH1, *pH2;
    cudaGetSymbolAddress((void**)&pPQ,  g_PQ);
    cudaGetSymbolAddress((void**)&pS,   g_S);
    cudaGetSymbolAddress((void**)&pAGG, g_AGG);
    cudaGetSymbolAddress((void**)&pH1,  g_H1);
    cudaGetSymbolAddress((void**)&pH2,  g_H2);

    dim3 blk(256);

    // 1) P = nodes @ eW1[:128]        -> PQ[:, 0:512]
    gemm_kernel<<<dim3(512 / 64, NNODE / 64), blk>>>(
        states, OBS, eW1, nullptr, 0, nullptr, 512,
        nullptr, 1.f, nullptr, nullptr, pPQ, 1024, 0);
    // 2) Q = nodes @ eW1[128:]        -> PQ[:, 512:1024]
    gemm_kernel<<<dim3(512 / 64, NNODE / 64), blk>>>(
        states, OBS, eW1 + 128 * 512, nullptr, 0, nullptr, 512,
        nullptr, 1.f, nullptr, nullptr, pPQ + 512, 1024, 0);
    // 3) fused edge layer (h1 -> z2 -> LN -> relu -> per-node sum) -> S
    edge_fused_kernel<<<NNODE, blk>>>(eb1, eW2, eb2, eg, ebt);
    // 4) AGG = S @ eW3 + 15*eb3
    gemm_kernel<<<dim3(512 / 64, NNODE / 64), blk>>>(
        pS, 512, eW3, nullptr, 0, nullptr, 512,
        eb3, 15.f, nullptr, nullptr, pAGG, 512, 0);
    // 5) H1 = relu(nodes@nW1a + act@nW1b + AGG@nW1c + nb1)
    gemm_kernel<<<dim3(512 / 64, NNODE / 64), blk>>>(
        states, OBS, nW1, pAGG, 512, nW1 + 132 * 512, 512,
        nb1, 1.f, nW1 + 128 * 512, action, pH1, 512, 1);
    // 6) H2 = relu(LN(H1@nW2 + nb2))
    node_ln_kernel<<<NNODE / 16, blk>>>(pH1, nW2, nb2, ng, nbt, pH2);
    // 7) out = H2 @ nW3 + nb3
    gemm_kernel<<<dim3(128 / 64, NNODE / 64), blk>>>(
        pH2, 512, nW3, nullptr, 0, nullptr, 128,
        nb3, 1.f, nullptr, nullptr, out, 128, 0);
}

// round 4
// speedup vs baseline: 2.8942x; 2.8942x over previous
#include <cuda_runtime.h>
#include <cuda_bf16.h>
#include <math.h>
#include <stdint.h>

// Problem constants
#define BB    512
#define OO    16
#define OBS   128
#define HH    512
#define NNODE (BB*OO)          // 8192
#define LN_EPS 1e-5f

// ---------------- scratch (device globals; no allocations) ----------------
__device__ __align__(16) float g_PQ[(size_t)NNODE * 1024];
__device__ __align__(16) float g_S [(size_t)NNODE * HH];
__device__ __align__(16) float g_AGG[(size_t)NNODE * HH];
__device__ __align__(16) float g_H1[(size_t)NNODE * HH];
__device__ __align__(16) float g_H2[(size_t)NNODE * HH];
// eW2 in mma-fragment order: [kstep(32)][ntile_pair(32)][lane(32)] uint4
__device__ __align__(16) uint4 g_BfH[32 * 32 * 32];
__device__ __align__(16) uint4 g_BfL[32 * 32 * 32];

// ---------------- helpers ----------------
__device__ __forceinline__ uint32_t smem_u32(const void* p) {
    uint32_t a;
    asm("{ .reg .u64 t; cvta.to.shared.u64 t, %1; cvt.u32.u64 %0, t; }" : "=r"(a) : "l"(p));
    return a;
}
__device__ __forceinline__ void ldsm4(uint32_t* r, uint32_t addr) {
    asm volatile("ldmatrix.sync.aligned.m8n8.x4.shared.b16 {%0,%1,%2,%3}, [%4];"
        : "=r"(r[0]), "=r"(r[1]), "=r"(r[2]), "=r"(r[3]) : "r"(addr));
}
__device__ __forceinline__ uint4 lds128(uint32_t a) {
    uint4 v;
    asm volatile("ld.shared.v4.b32 {%0,%1,%2,%3}, [%4];"
        : "=r"(v.x), "=r"(v.y), "=r"(v.z), "=r"(v.w) : "r"(a));
    return v;
}
__device__ __forceinline__ void mma16816(float* c, const uint32_t* a, uint32_t b0, uint32_t b1) {
    asm volatile(
        "mma.sync.aligned.m16n8k16.row.col.f32.bf16.bf16.f32 "
        "{%0,%1,%2,%3}, {%4,%5,%6,%7}, {%8,%9}, {%0,%1,%2,%3};"
        : "+f"(c[0]), "+f"(c[1]), "+f"(c[2]), "+f"(c[3])
        : "r"(a[0]), "r"(a[1]), "r"(a[2]), "r"(a[3]), "r"(b0), "r"(b1));
}
#define CP_ASYNC16(dst, src) \
    asm volatile("cp.async.cg.shared.global [%0], [%1], 16;" \
                 :: "r"(dst), "l"(__cvta_generic_to_global(src)))
#define CP_COMMIT() asm volatile("cp.async.commit_group;" ::: "memory")
#define CP_WAIT1()  asm volatile("cp.async.wait_group 1;" ::: "memory")
#define CP_WAIT0()  asm volatile("cp.async.wait_group 0;" ::: "memory")

__device__ __forceinline__ uint32_t pack_bf_pair(float a, float b, float& ra, float& rb) {
    const __nv_bfloat16 ha = __float2bfloat16(a), hb = __float2bfloat16(b);
    ra = a - __bfloat162float(ha);
    rb = b - __bfloat162float(hb);
    return (uint32_t)__bfloat16_as_ushort(ha) | ((uint32_t)__bfloat16_as_ushort(hb) << 16);
}

// ---------------- prep: eW2 [k][n] f32 -> fragment-ordered bf16 hi/lo ----------------
__global__ void prep_bfrag_kernel(const float* __restrict__ W)
{
    const int idx = blockIdx.x * 256 + threadIdx.x;   // 32768 total
    const int lane = idx & 31;
    const int gid = lane >> 2, tg = lane & 3;
    const int jp = (idx >> 5) & 31;
    const int s = idx >> 10;
    const int k0 = s * 16 + tg * 2;

    uint32_t h[4], l[4];
#pragma unroll
    for (int half = 0; half < 2; ++half) {
        const int n = (jp * 2 + half) * 8 + gid;
        const float f00 = W[(size_t)k0 * 512 + n];
        const float f01 = W[(size_t)(k0 + 1) * 512 + n];
        const float f10 = W[(size_t)(k0 + 8) * 512 + n];
        const float f11 = W[(size_t)(k0 + 9) * 512 + n];
        float r00, r01, r10, r11;
        h[half * 2 + 0] = pack_bf_pair(f00, f01, r00, r01);
        h[half * 2 + 1] = pack_bf_pair(f10, f11, r10, r11);
        float d0, d1;
        l[half * 2 + 0] = pack_bf_pair(r00, r01, d0, d1);
        l[half * 2 + 1] = pack_bf_pair(r10, r11, d0, d1);
    }
    g_BfH[idx] = make_uint4(h[0], h[1], h[2], h[3]);
    g_BfL[idx] = make_uint4(l[0], l[1], l[2], l[3]);
}

// ---------------- edge kernel smem layout ----------------
#define OFF_AHI  0
#define OFF_ALO  66560
#define OFF_BBUF 133120
#define OFF_B2   198656
#define OFF_GS   200704
#define OFF_BSS  202752
#define OFF_PS   204800
#define OFF_PQS  206848
#define OFF_MU   208896
#define OFF_RS   209152
#define SMEM_EDGE 209408
#define A_STRIDE 1040          // 512*2 + 16 pad (conflict-free ldmatrix)

__device__ __forceinline__ void stage_B(uint32_t sbase, int stage, int s, int w, int lane)
{
#pragma unroll
    for (int p = 0; p < 4; ++p) {
        const int jpg = w * 4 + p;
        const uint4* srcH = &g_BfH[(size_t)(s * 32 + jpg) * 32 + lane];
        const uint4* srcL = &g_BfL[(size_t)(s * 32 + jpg) * 32 + lane];
        const uint32_t dH = sbase + OFF_BBUF +
            ((uint32_t)((stage * 32 + jpg) * 2) * 32 + lane) * 16;
        CP_ASYNC16(dH, srcH);
        CP_ASYNC16(dH + 512, srcL);
    }
}

// ---------------- fused edge layer: split-bf16 mma + LN + relu + node reduce ----------------
__global__ void __launch_bounds__(256, 1) edge_mma_kernel(
    const float* __restrict__ eb1, const float* __restrict__ b2,
    const float* __restrict__ gam, const float* __restrict__ bet)
{
    extern __shared__ __align__(16) char smem[];
    const uint32_t sbase = smem_u32(smem);
    const int tid = threadIdx.x;
    const int nb = blockIdx.x;
    const int node_base = nb * 4;
    const int b16 = (nb >> 2) << 4;
    const int o0 = (nb & 3) * 4;

    float* b2s = (float*)(smem + OFF_B2);
    float* gss = (float*)(smem + OFF_GS);
    float* bss = (float*)(smem + OFF_BSS);
    float* ps  = (float*)(smem + OFF_PS);
    float* pq  = (float*)(smem + OFF_PQS);
    float* mus = (float*)(smem + OFF_MU);
    float* rss = (float*)(smem + OFF_RS);

    for (int i = tid; i < 512; i += 256) {
        b2s[i] = b2[i]; gss[i] = gam[i]; bss[i] = bet[i];
    }

    // ---- build A = relu(P + Q + eb1), split to bf16 hi/lo in smem ----
    const float4* eb1v = (const float4*)eb1;
#pragma unroll
    for (int i = 0; i < 32; ++i) {
        const int idx = tid + (i << 8);       // 0..8191
        const int m = idx >> 7;               // 0..63
        const int k4 = (idx & 127) << 2;      // 0..508
        const int ln = m >> 4, r = m & 15;
        float4 v = make_float4(0.f, 0.f, 0.f, 0.f);
        if (r < 15) {
            const int o = o0 + ln;
            const int jj = r + (r >= o);
            const float4 p4 = *(const float4*)&g_PQ[(size_t)(node_base + ln) * 1024 + k4];
            const float4 q4 = *(const float4*)&g_PQ[(size_t)(b16 + jj) * 1024 + 512 + k4];
            const float4 bb = __ldg(&eb1v[k4 >> 2]);
            v.x = fmaxf(p4.x + q4.x + bb.x, 0.f);
            v.y = fmaxf(p4.y + q4.y + bb.y, 0.f);
            v.z = fmaxf(p4.z + q4.z + bb.z, 0.f);
            v.w = fmaxf(p4.w + q4.w + bb.w, 0.f);
        }
        float rx, ry, rz, rw, d0, d1;
        uint2 hh, ll;
        hh.x = pack_bf_pair(v.x, v.y, rx, ry);
        hh.y = pack_bf_pair(v.z, v.w, rz, rw);
        ll.x = pack_bf_pair(rx, ry, d0, d1);
        ll.y = pack_bf_pair(rz, rw, d0, d1);
        const uint32_t off = (uint32_t)m * A_STRIDE + ((uint32_t)k4 << 1);
        *(uint2*)(smem + OFF_AHI + off) = hh;
        *(uint2*)(smem + OFF_ALO + off) = ll;
    }
    __syncthreads();

    // ---- mainloop ----
    const int w = tid >> 5, lane = tid & 31;
    const int gid = lane >> 2, tg = lane & 3;
    const int lrow = (lane & 8) + (lane & 7);
    const uint32_t a_base = sbase + OFF_AHI + (uint32_t)lrow * A_STRIDE + ((lane & 16) ? 16u : 0u);

    float acc[4][8][4];
#pragma unroll
    for (int mt = 0; mt < 4; ++mt)
#pragma unroll
        for (int nt = 0; nt < 8; ++nt)
#pragma unroll
            for (int j = 0; j < 4; ++j) acc[mt][nt][j] = 0.f;

    stage_B(sbase, 0, 0, w, lane);
    CP_COMMIT();

    for (int s = 0; s < 32; ++s) {
        const int cur = s & 1;
        if (s < 31) { stage_B(sbase, cur ^ 1, s + 1, w, lane); CP_COMMIT(); CP_WAIT1(); }
        else CP_WAIT0();

        uint4 vh[4], vl[4];
#pragma unroll
        for (int p = 0; p < 4; ++p) {
            const uint32_t aH = sbase + OFF_BBUF +
                ((uint32_t)((cur * 32 + w * 4 + p) * 2) * 32 + lane) * 16;
            vh[p] = lds128(aH);
            vl[p] = lds128(aH + 512);
        }
#pragma unroll
        for (int mt = 0; mt < 4; ++mt) {
            uint32_t ah[4], al[4];
            const uint32_t aoff = (uint32_t)mt * (16 * A_STRIDE) + (uint32_t)s * 32;
            ldsm4(ah, a_base + aoff);
            ldsm4(al, a_base + (OFF_ALO - OFF_AHI) + aoff);
#pragma unroll
            for (int p = 0; p < 4; ++p) {
                mma16816(acc[mt][2 * p],     ah, vh[p].x, vh[p].y);
                mma16816(acc[mt][2 * p],     ah, vl[p].x, vl[p].y);
                mma16816(acc[mt][2 * p],     al, vh[p].x, vh[p].y);
                mma16816(acc[mt][2 * p + 1], ah, vh[p].z, vh[p].w);
                mma16816(acc[mt][2 * p + 1], ah, vl[p].z, vl[p].w);
                mma16816(acc[mt][2 * p + 1], al, vh[p].z, vh[p].w);
            }
        }
    }

    // ---- epilogue: bias + LN stats + normalize + relu + 15-row node sum ----
    const int colb = w * 64 + tg * 2;
    float b2v[8][2];
#pragma unroll
    for (int nt = 0; nt < 8; ++nt) {
        b2v[nt][0] = b2s[colb + nt * 8];
        b2v[nt][1] = b2s[colb + nt * 8 + 1];
    }
#pragma unroll
    for (int mt = 0; mt < 4; ++mt) {
        float s0 = 0.f, q0 = 0.f, s1 = 0.f, q1 = 0.f;
#pragma unroll
        for (int nt = 0; nt < 8; ++nt) {
            const float v00 = acc[mt][nt][0] + b2v[nt][0];
            const float v01 = acc[mt][nt][1] + b2v[nt][1];
            const float v10 = acc[mt][nt][2] + b2v[nt][0];
            const float v11 = acc[mt][nt][3] + b2v[nt][1];
            acc[mt][nt][0] = v00; acc[mt][nt][1] = v01;
            acc[mt][nt][2] = v10; acc[mt][nt][3] = v11;
            s0 += v00 + v01; q0 += v00 * v00 + v01 * v01;
            s1 += v10 + v11; q1 += v10 * v10 + v11 * v11;
        }
#pragma unroll
        for (int off = 1; off <= 2; off <<= 1) {
            s0 += __shfl_xor_sync(0xffffffffu, s0, off);
            q0 += __shfl_xor_sync(0xffffffffu, q0, off);
            s1 += __shfl_xor_sync(0xffffffffu, s1, off);
            q1 += __shfl_xor_sync(0xffffffffu, q1, off);
        }
        if (tg == 0) {
            ps[(mt * 16 + gid) * 8 + w] = s0;     pq[(mt * 16 + gid) * 8 + w] = q0;
            ps[(mt * 16 + 8 + gid) * 8 + w] = s1; pq[(mt * 16 + 8 + gid) * 8 + w] = q1;
        }
    }
    __syncthreads();
    if (tid < 64) {
        float s = 0.f, q = 0.f;
#pragma unroll
        for (int ww = 0; ww < 8; ++ww) { s += ps[tid * 8 + ww]; q += pq[tid * 8 + ww]; }
        const float mu = s * (1.f / 512.f);
        mus[tid] = mu;
        rss[tid] = rsqrtf(q * (1.f / 512.f) - mu * mu + LN_EPS);
    }
    __syncthreads();

    float gv[8][2], bv[8][2];
#pragma unroll
    for (int nt = 0; nt < 8; ++nt) {
        gv[nt][0] = gss[colb + nt * 8];     gv[nt][1] = gss[colb + nt * 8 + 1];
        bv[nt][0] = bss[colb + nt * 8];     bv[nt][1] = bss[colb + nt * 8 + 1];
    }
#pragma unroll
    for (int mt = 0; mt < 4; ++mt) {
        const float mu0 = mus[mt * 16 + gid],     r0 = rss[mt * 16 + gid];
        const float mu1 = mus[mt * 16 + 8 + gid], r1 = rss[mt * 16 + 8 + gid];
        const bool last = (gid == 7);   // row 15 = zero pad, exclude
#pragma unroll
        for (int nt = 0; nt < 8; ++nt) {
            const float v00 = fmaxf((acc[mt][nt][0] - mu0) * r0 * gv[nt][0] + bv[nt][0], 0.f);
            const float v01 = fmaxf((acc[mt][nt][1] - mu0) * r0 * gv[nt][1] + bv[nt][1], 0.f);
            const float v10 = last ? 0.f : fmaxf((acc[mt][nt][2] - mu1) * r1 * gv[nt][0] + bv[nt][0], 0.f);
            const float v11 = last ? 0.f : fmaxf((acc[mt][nt][3] - mu1) * r1 * gv[nt][1] + bv[nt][1], 0.f);
            float t0 = v00 + v10, t1 = v01 + v11;
#pragma unroll
            for (int off = 4; off <= 16; off <<= 1) {
                t0 += __shfl_xor_sync(0xffffffffu, t0, off);
                t1 += __shfl_xor_sync(0xffffffffu, t1, off);
            }
            if (lane < 4)
                *(float2*)&g_S[(size_t)(node_base + mt) * 512 + colb + nt * 8] =
                    make_float2(t0, t1);
        }
    }
}

// ---------------- generic 64x64 tiled GEMM (up to two K segments) ----------------
__global__ void __launch_bounds__(256) gemm_kernel(
    const float* __restrict__ X0, int K0, const float* __restrict__ W0,
    const float* __restrict__ X1, int K1, const float* __restrict__ W1,
    int N,
    const float* __restrict__ bias, float bscale,
    const float* __restrict__ actW, const int* __restrict__ action,
    float* __restrict__ out, int ldout, int relu)
{
    __shared__ __align__(16) float Xs[16][64];
    __shared__ __align__(16) float Ws[16][64];

    const int tid = threadIdx.x;
    const int bm = blockIdx.y * 64, bn = blockIdx.x * 64;
    const int tr = tid >> 4, tc = tid & 15;

    float acc[4][4];
#pragma unroll
    for (int i = 0; i < 4; ++i)
#pragma unroll
        for (int j = 0; j < 4; ++j) acc[i][j] = 0.f;

    const int lr = tid >> 2;
    const int lk = (tid & 3) * 4;
    const int wr = tid >> 4;
    const int wc = (tid & 15) * 4;

#pragma unroll
    for (int seg = 0; seg < 2; ++seg) {
        const float* X = seg ? X1 : X0;
        const float* W = seg ? W1 : W0;
        const int K = seg ? K1 : K0;
        if (K == 0) continue;
        for (int kt = 0; kt < K; kt += 16) {
            float4 xv = *(const float4*)(X + (size_t)(bm + lr) * K + kt + lk);
            Xs[lk + 0][lr] = xv.x; Xs[lk + 1][lr] = xv.y;
            Xs[lk + 2][lr] = xv.z; Xs[lk + 3][lr] = xv.w;
            float4 wv = *(const float4*)(W + (size_t)(kt + wr) * N + bn + wc);
            *(float4*)&Ws[wr][wc] = wv;
            __syncthreads();
#pragma unroll
            for (int k = 0; k < 16; ++k) {
                float a[4], b4[4];
                *(float4*)a  = *(const float4*)&Xs[k][tr * 4];
                *(float4*)b4 = *(const float4*)&Ws[k][tc * 4];
#pragma unroll
                for (int i = 0; i < 4; ++i)
#pragma unroll
                    for (int j = 0; j < 4; ++j)
                        acc[i][j] += a[i] * b4[j];
            }
            __syncthreads();
        }
    }

#pragma unroll
    for (int i = 0; i < 4; ++i) {
        const int m = bm + tr * 4 + i;
        int t = -1;
        if (actW) {
            const int bidx = m >> 4, o = m & 15;
            const int a = action[bidx];
            t = a - 4 * o;
        }
#pragma unroll
        for (int j = 0; j < 4; ++j) {
            const int n = bn + tc * 4 + j;
            float v = acc[i][j];
            if (bias) v += bias[n] * bscale;
            if (actW && (unsigned)t < 4u) v += actW[(size_t)t * N + n];
            if (relu) v = fmaxf(v, 0.f);
            out[(size_t)m * ldout + n] = v;
        }
    }
}

// ---------------- fused node layer-2 + LN + ReLU (fp32) ----------------
__global__ void __launch_bounds__(256, 2) node_ln_kernel(
    const float* __restrict__ X, const float* __restrict__ W,
    const float* __restrict__ b2, const float* __restrict__ gam,
    const float* __restrict__ bet, float* __restrict__ Y)
{
    __shared__ __align__(16) float xt[512 * 16];
    __shared__ float red_s[16 * 8];
    __shared__ float red_q[16 * 8];
    __shared__ float mu_s[16], rs_s[16];

    const int tid = threadIdx.x;
    const int g0row = blockIdx.x * 16;

#pragma unroll 4
    for (int it = 0; it < 32; ++it) {
        const int idx = tid + it * 256;
        const int k = idx >> 4, r = idx & 15;
        xt[k * 16 + r] = X[(size_t)(g0row + r) * 512 + k];
    }
    __syncthreads();

    const int c0 = tid, c1 = tid + 256;
    float acc0[16], acc1[16];
#pragma unroll
    for (int r = 0; r < 16; ++r) { acc0[r] = 0.f; acc1[r] = 0.f; }

    const float* w0p = W + c0;
    const float* w1p = W + c1;
#pragma unroll 2
    for (int k = 0; k < 512; ++k) {
        const float w0 = __ldg(w0p + (size_t)k * 512);
        const float w1 = __ldg(w1p + (size_t)k * 512);
        const float4* h4 = (const float4*)(xt + k * 16);
        const float4 A = h4[0], B4 = h4[1], C = h4[2], D = h4[3];
        const float hv[16] = {A.x, A.y, A.z, A.w, B4.x, B4.y, B4.z, B4.w,
                              C.x, C.y, C.z, C.w, D.x, D.y, D.z, D.w};
#pragma unroll
        for (int r = 0; r < 16; ++r) {
            acc0[r] += hv[r] * w0;
            acc1[r] += hv[r] * w1;
        }
    }

    const float be0 = b2[c0], be1 = b2[c1];
    float psv[16], pqv[16];
#pragma unroll
    for (int r = 0; r < 16; ++r) {
        const float z0 = acc0[r] + be0, z1 = acc1[r] + be1;
        acc0[r] = z0; acc1[r] = z1;
        psv[r] = z0 + z1;
        pqv[r] = z0 * z0 + z1 * z1;
    }
    const int lane = tid & 31, wid = tid >> 5;
#pragma unroll
    for (int off = 16; off; off >>= 1) {
#pragma unroll
        for (int r = 0; r < 16; ++r) {
            psv[r] += __shfl_xor_sync(0xffffffffu, psv[r], off);
            pqv[r] += __shfl_xor_sync(0xffffffffu, pqv[r], off);
        }
    }
    if (lane == 0) {
#pragma unroll
        for (int r = 0; r < 16; ++r) { red_s[r * 8 + wid] = psv[r]; red_q[r * 8 + wid] = pqv[r]; }
    }
    __syncthreads();
    if (tid < 16) {
        float s = 0.f, q = 0.f;
#pragma unroll
        for (int wk = 0; wk < 8; ++wk) { s += red_s[tid * 8 + wk]; q += red_q[tid * 8 + wk]; }
        const float mu = s * (1.f / 512.f);
        const float var = q * (1.f / 512.f) - mu * mu;
        mu_s[tid] = mu;
        rs_s[tid] = rsqrtf(var + LN_EPS);
    }
    __syncthreads();

    const float gg0 = gam[c0], gg1 = gam[c1];
    const float bb0 = bet[c0], bb1 = bet[c1];
#pragma unroll
    for (int r = 0; r < 16; ++r) {
        const float mu = mu_s[r], rs = rs_s[r];
        Y[(size_t)(g0row + r) * 512 + c0] = fmaxf((acc0[r] - mu) * rs * gg0 + bb0, 0.f);
        Y[(size_t)(g0row + r) * 512 + c1] = fmaxf((acc1[r] - mu) * rs * gg1 + bb1, 0.f);
    }
}

// ---------------- launch ----------------
extern "C" void kernel_launch(void* const* d_in, const int* in_sizes, int n_in,
                              void* d_out, int out_size)
{
    const float* states = (const float*)d_in[0];
    const int*   action = (const int*)d_in[1];   // int64 in ref; x64-disabled JAX -> int32
    const float* eW1 = (const float*)d_in[2];
    const float* eb1 = (const float*)d_in[3];
    const float* eW2 = (const float*)d_in[4];
    const float* eb2 = (const float*)d_in[5];
    const float* eg  = (const float*)d_in[6];
    const float* ebt = (const float*)d_in[7];
    const float* eW3 = (const float*)d_in[8];
    const float* eb3 = (const float*)d_in[9];
    const float* nW1 = (const float*)d_in[10];
    const float* nb1 = (const float*)d_in[11];
    const float* nW2 = (const float*)d_in[12];
    const float* nb2 = (const float*)d_in[13];
    const float* ng  = (const float*)d_in[14];
    const float* nbt = (const float*)d_in[15];
    const float* nW3 = (const float*)d_in[16];
    const float* nb3 = (const float*)d_in[17];
    float* out = (float*)d_out;

    float *pPQ, *pS, *pAGG, *pH1, *pH2;
    cudaGetSymbolAddress((void**)&pPQ,  g_PQ);
    cudaGetSymbolAddress((void**)&pS,   g_S);
    cudaGetSymbolAddress((void**)&pAGG, g_AGG);
    cudaGetSymbolAddress((void**)&pH1,  g_H1);
    cudaGetSymbolAddress((void**)&pH2,  g_H2);

    static int configured = 0;
    if (!configured) {
        cudaFuncSetAttribute(edge_mma_kernel,
                             cudaFuncAttributeMaxDynamicSharedMemorySize, SMEM_EDGE);
        configured = 1;
    }

    dim3 blk(256);

    // 0) prep eW2 -> fragment-ordered bf16 hi/lo
    prep_bfrag_kernel<<<128, 256>>>(eW2);
    // 1) P = nodes @ eW1[:128]
    gemm_kernel<<<dim3(512 / 64, NNODE / 64), blk>>>(
        states, OBS, eW1, nullptr, 0, nullptr, 512,
        nullptr, 1.f, nullptr, nullptr, pPQ, 1024, 0);
    // 2) Q = nodes @ eW1[128:]
    gemm_kernel<<<dim3(512 / 64, NNODE / 64), blk>>>(
        states, OBS, eW1 + 128 * 512, nullptr, 0, nullptr, 512,
        nullptr, 1.f, nullptr, nullptr, pPQ + 512, 1024, 0);
    // 3) fused edge layer on HMMA tensor cores -> S
    edge_mma_kernel<<<NNODE / 4, blk, SMEM_EDGE>>>(eb1, eb2, eg, ebt);
    // 4) AGG = S @ eW3 + 15*eb3
    gemm_kernel<<<dim3(512 / 64, NNODE / 64), blk>>>(
        pS, 512, eW3, nullptr, 0, nullptr, 512,
        eb3, 15.f, nullptr, nullptr, pAGG, 512, 0);
    // 5) H1 = relu(nodes@nW1a + act@nW1b + AGG@nW1c + nb1)
    gemm_kernel<<<dim3(512 / 64, NNODE / 64), blk>>>(
        states, OBS, nW1, pAGG, 512, nW1 + 132 * 512, 512,
        nb1, 1.f, nW1 + 128 * 512, action, pH1, 512, 1);
    // 6) H2 = relu(LN(H1@nW2 + nb2))
    node_ln_kernel<<<NNODE / 16, blk>>>(pH1, nW2, nb2, ng, nbt, pH2);
    // 7) out = H2 @ nW3 + nb3
    gemm_kernel<<<dim3(128 / 64, NNODE / 64), blk>>>(
        pH2, 512, nW3, nullptr, 0, nullptr, 128,
        nb3, 1.f, nullptr, nullptr, out, 128, 0);
}

// round 5
// speedup vs baseline: 4.6328x; 1.6007x over previous
#include <cuda_runtime.h>
#include <cuda_bf16.h>
#include <math.h>
#include <stdint.h>

// Problem constants
#define BB    512
#define OO    16
#define OBS   128
#define HH    512
#define NNODE (BB*OO)          // 8192
#define LN_EPS 1e-5f

// ---------------- scratch (device globals; no allocations) ----------------
__device__ __align__(16) float g_PQ[(size_t)NNODE * 1024];
__device__ __align__(16) float g_S [(size_t)NNODE * HH];
__device__ __align__(16) float g_T [(size_t)NNODE * HH];    // states@nW1a + act + b'
__device__ __align__(16) float g_H1[(size_t)NNODE * HH];    // also reused as Wcomb fp32 temp
__device__ __align__(16) float g_H2[(size_t)NNODE * HH];
__device__ __align__(16) float g_bp[512];

// fragment-packed weights: [(kstep)*(N/16) + npair][lane] uint4, hi & lo
__device__ __align__(16) uint4 g_eW1aH[8192],  g_eW1aL[8192];    // K=128,N=512
__device__ __align__(16) uint4 g_eW1bH[8192],  g_eW1bL[8192];    // K=128,N=512
__device__ __align__(16) uint4 g_BfH[32768],   g_BfL[32768];     // eW2: K=512,N=512
__device__ __align__(16) uint4 g_nW1aH[8192],  g_nW1aL[8192];    // K=128,N=512
__device__ __align__(16) uint4 g_nW1cH[32768], g_nW1cL[32768];   // K=512,N=512
__device__ __align__(16) uint4 g_nW2H[32768],  g_nW2L[32768];    // K=512,N=512
__device__ __align__(16) uint4 g_nW3H[8192],   g_nW3L[8192];     // K=512,N=128
__device__ __align__(16) uint4 g_WcH[32768],   g_WcL[32768];     // Wcomb: K=512,N=512

// ---------------- helpers ----------------
__device__ __forceinline__ uint32_t smem_u32(const void* p) {
    uint32_t a;
    asm("{ .reg .u64 t; cvta.to.shared.u64 t, %1; cvt.u32.u64 %0, t; }" : "=r"(a) : "l"(p));
    return a;
}
__device__ __forceinline__ void ldsm4(uint32_t* r, uint32_t addr) {
    asm volatile("ldmatrix.sync.aligned.m8n8.x4.shared.b16 {%0,%1,%2,%3}, [%4];"
        : "=r"(r[0]), "=r"(r[1]), "=r"(r[2]), "=r"(r[3]) : "r"(addr));
}
__device__ __forceinline__ uint4 lds128(uint32_t a) {
    uint4 v;
    asm volatile("ld.shared.v4.b32 {%0,%1,%2,%3}, [%4];"
        : "=r"(v.x), "=r"(v.y), "=r"(v.z), "=r"(v.w) : "r"(a));
    return v;
}
__device__ __forceinline__ void mma16816(float* c, const uint32_t* a, uint32_t b0, uint32_t b1) {
    asm volatile(
        "mma.sync.aligned.m16n8k16.row.col.f32.bf16.bf16.f32 "
        "{%0,%1,%2,%3}, {%4,%5,%6,%7}, {%8,%9}, {%0,%1,%2,%3};"
        : "+f"(c[0]), "+f"(c[1]), "+f"(c[2]), "+f"(c[3])
        : "r"(a[0]), "r"(a[1]), "r"(a[2]), "r"(a[3]), "r"(b0), "r"(b1));
}
#define CP_ASYNC16(dst, src) \
    asm volatile("cp.async.cg.shared.global [%0], [%1], 16;" \
                 :: "r"(dst), "l"(__cvta_generic_to_global(src)))
#define CP_COMMIT() asm volatile("cp.async.commit_group;" ::: "memory")
#define CP_WAIT1()  asm volatile("cp.async.wait_group 1;" ::: "memory")
#define CP_WAIT0()  asm volatile("cp.async.wait_group 0;" ::: "memory")

__device__ __forceinline__ uint32_t pack_bf_pair(float a, float b, float& ra, float& rb) {
    const __nv_bfloat16 ha = __float2bfloat16(a), hb = __float2bfloat16(b);
    ra = a - __bfloat162float(ha);
    rb = b - __bfloat162float(hb);
    return (uint32_t)__bfloat16_as_ushort(ha) | ((uint32_t)__bfloat16_as_ushort(hb) << 16);
}

// ---------------- generic weight fragment packer ----------------
// W fp32 [K x N] row-major (ldW = N) -> frag layout [(s*(N/16)+jp)*32+lane] uint4 hi/lo
__global__ void pack_frag_kernel(const float* __restrict__ W, int K, int N, int ldW,
                                 uint4* __restrict__ dstH, uint4* __restrict__ dstL)
{
    const int total = (K / 16) * (N / 16) * 32;
    const int idx = blockIdx.x * 256 + threadIdx.x;
    if (idx >= total) return;
    const int lane = idx & 31;
    const int gid = lane >> 2, tg = lane & 3;
    const int npairs = N / 16;
    const int jp = (idx >> 5) % npairs;
    const int s = idx / (npairs * 32);
    const int k0 = s * 16 + tg * 2;

    uint32_t h[4], l[4];
#pragma unroll
    for (int half = 0; half < 2; ++half) {
        const int n = (jp * 2 + half) * 8 + gid;
        const float f00 = W[(size_t)k0 * ldW + n];
        const float f01 = W[(size_t)(k0 + 1) * ldW + n];
        const float f10 = W[(size_t)(k0 + 8) * ldW + n];
        const float f11 = W[(size_t)(k0 + 9) * ldW + n];
        float r00, r01, r10, r11, d0, d1;
        h[half * 2 + 0] = pack_bf_pair(f00, f01, r00, r01);
        h[half * 2 + 1] = pack_bf_pair(f10, f11, r10, r11);
        l[half * 2 + 0] = pack_bf_pair(r00, r01, d0, d1);
        l[half * 2 + 1] = pack_bf_pair(r10, r11, d0, d1);
    }
    dstH[idx] = make_uint4(h[0], h[1], h[2], h[3]);
    dstL[idx] = make_uint4(l[0], l[1], l[2], l[3]);
}

// ---------------- b' = nb1 + 15 * (eb3 @ nW1c) ----------------
__global__ void bprime_kernel(const float* __restrict__ eb3, const float* __restrict__ nW1,
                              const float* __restrict__ nb1)
{
    const int n = blockIdx.x * 256 + threadIdx.x;
    if (n >= 512) return;
    float acc = 0.f;
    for (int k = 0; k < 512; ++k)
        acc += eb3[k] * nW1[(size_t)(132 + k) * 512 + n];
    g_bp[n] = nb1[n] + 15.f * acc;
}

// ================= generic split-bf16 HMMA GEMM =================
// CTA: 64 rows x (128*PAIRS) cols (CTA covers full N). 8 warps.
// out = [relu]( [LN]( X@W + bias + addend + act_row ) )
template<int PAIRS, bool LN>
__global__ void __launch_bounds__(256, 1) mma_gemm_kernel(
    const float* __restrict__ X, int K,
    const uint4* __restrict__ WH, const uint4* __restrict__ WL,
    const float* __restrict__ bias,
    const float* __restrict__ addend, int ldadd,
    const float* __restrict__ actW, const int* __restrict__ action,
    const float* __restrict__ gam, const float* __restrict__ bet,
    float* __restrict__ out, int ldout, int relu)
{
    extern __shared__ __align__(16) char smem[];
    const uint32_t sbase = smem_u32(smem);
    const int tid = threadIdx.x;
    const int bm = blockIdx.x * 64;
    const int NP = 8 * PAIRS;
    const int A_ST = K * 2 + 16;
    const uint32_t offALO = (uint32_t)64 * A_ST;
    const uint32_t offB = 2 * offALO;
    const uint32_t offEpi = offB + (uint32_t)2 * NP * 1024;
    const int kst = K / 16;

    // ---- build A hi/lo in smem ----
    const int kd4 = K >> 2;
    for (int idx = tid; idx < 64 * kd4; idx += 256) {
        const int m = idx / kd4, k4 = (idx - m * kd4) * 4;
        const float4 v = *(const float4*)(X + (size_t)(bm + m) * K + k4);
        float rx, ry, rz, rw, d0, d1;
        uint2 hh, ll;
        hh.x = pack_bf_pair(v.x, v.y, rx, ry);
        hh.y = pack_bf_pair(v.z, v.w, rz, rw);
        ll.x = pack_bf_pair(rx, ry, d0, d1);
        ll.y = pack_bf_pair(rz, rw, d0, d1);
        const uint32_t off = (uint32_t)m * A_ST + ((uint32_t)k4 << 1);
        *(uint2*)(smem + off) = hh;
        *(uint2*)(smem + offALO + off) = ll;
    }
    __syncthreads();

    const int w = tid >> 5, lane = tid & 31;
    const int gid = lane >> 2, tg = lane & 3;
    const int lrow = (lane & 8) + (lane & 7);
    const uint32_t a_base = sbase + (uint32_t)lrow * A_ST + ((lane & 16) ? 16u : 0u);

    float acc[4][2 * PAIRS][4];
#pragma unroll
    for (int mt = 0; mt < 4; ++mt)
#pragma unroll
        for (int nt = 0; nt < 2 * PAIRS; ++nt)
#pragma unroll
            for (int j = 0; j < 4; ++j) acc[mt][nt][j] = 0.f;

    // stage B (warp-private)
    auto stageB = [&](int stage, int s) {
#pragma unroll
        for (int p = 0; p < PAIRS; ++p) {
            const int jpg = w * PAIRS + p;
            const uint32_t d = sbase + offB +
                ((uint32_t)((stage * NP + jpg) * 2) * 32 + lane) * 16;
            CP_ASYNC16(d, WH + ((size_t)(s * NP + jpg) * 32 + lane));
            CP_ASYNC16(d + 512, WL + ((size_t)(s * NP + jpg) * 32 + lane));
        }
    };

    stageB(0, 0); CP_COMMIT();

    for (int s = 0; s < kst; ++s) {
        const int cur = s & 1;
        if (s < kst - 1) { stageB(cur ^ 1, s + 1); CP_COMMIT(); CP_WAIT1(); }
        else CP_WAIT0();

        uint4 vh[PAIRS], vl[PAIRS];
#pragma unroll
        for (int p = 0; p < PAIRS; ++p) {
            const uint32_t aH = sbase + offB +
                ((uint32_t)((cur * NP + w * PAIRS + p) * 2) * 32 + lane) * 16;
            vh[p] = lds128(aH);
            vl[p] = lds128(aH + 512);
        }
#pragma unroll
        for (int mt = 0; mt < 4; ++mt) {
            uint32_t ah[4], al[4];
            const uint32_t aoff = (uint32_t)mt * 16 * A_ST + (uint32_t)s * 32;
            ldsm4(ah, a_base + aoff);
            ldsm4(al, a_base + offALO + aoff);
#pragma unroll
            for (int p = 0; p < PAIRS; ++p) {
                mma16816(acc[mt][2 * p],     ah, vh[p].x, vh[p].y);
                mma16816(acc[mt][2 * p],     ah, vl[p].x, vl[p].y);
                mma16816(acc[mt][2 * p],     al, vh[p].x, vh[p].y);
                mma16816(acc[mt][2 * p + 1], ah, vh[p].z, vh[p].w);
                mma16816(acc[mt][2 * p + 1], ah, vl[p].z, vl[p].w);
                mma16816(acc[mt][2 * p + 1], al, vh[p].z, vh[p].w);
            }
        }
    }

    // ---- epilogue ----
    const int colb = w * (16 * PAIRS) + tg * 2;
    float* ps  = (float*)(smem + offEpi);
    float* pq  = ps + 512;
    float* mus = pq + 512;
    float* rss = mus + 64;

#pragma unroll
    for (int mt = 0; mt < 4; ++mt) {
        const int r0 = bm + mt * 16 + gid;
        const int r1 = r0 + 8;
        int t0 = 5, t1 = 5;
        if (actW) {
            const int a = action[r0 >> 4];
            t0 = a - 4 * (r0 & 15);
            t1 = a - 4 * (r1 & 15);
        }
#pragma unroll
        for (int nt = 0; nt < 2 * PAIRS; ++nt) {
            const int col = colb + nt * 8;
            float b0 = 0.f, b1 = 0.f;
            if (bias) { b0 = __ldg(bias + col); b1 = __ldg(bias + col + 1); }
            float v00 = acc[mt][nt][0] + b0, v01 = acc[mt][nt][1] + b1;
            float v10 = acc[mt][nt][2] + b0, v11 = acc[mt][nt][3] + b1;
            if (addend) {
                const float2 a0 = *(const float2*)(addend + (size_t)r0 * ldadd + col);
                const float2 a1 = *(const float2*)(addend + (size_t)r1 * ldadd + col);
                v00 += a0.x; v01 += a0.y; v10 += a1.x; v11 += a1.y;
            }
            if (actW) {
                if ((unsigned)t0 < 4u) {
                    v00 += __ldg(actW + (size_t)t0 * 512 + col);
                    v01 += __ldg(actW + (size_t)t0 * 512 + col + 1);
                }
                if ((unsigned)t1 < 4u) {
                    v10 += __ldg(actW + (size_t)t1 * 512 + col);
                    v11 += __ldg(actW + (size_t)t1 * 512 + col + 1);
                }
            }
            acc[mt][nt][0] = v00; acc[mt][nt][1] = v01;
            acc[mt][nt][2] = v10; acc[mt][nt][3] = v11;
        }
    }

    if (LN) {
#pragma unroll
        for (int mt = 0; mt < 4; ++mt) {
            float s0 = 0.f, q0 = 0.f, s1 = 0.f, q1 = 0.f;
#pragma unroll
            for (int nt = 0; nt < 2 * PAIRS; ++nt) {
                s0 += acc[mt][nt][0] + acc[mt][nt][1];
                q0 += acc[mt][nt][0] * acc[mt][nt][0] + acc[mt][nt][1] * acc[mt][nt][1];
                s1 += acc[mt][nt][2] + acc[mt][nt][3];
                q1 += acc[mt][nt][2] * acc[mt][nt][2] + acc[mt][nt][3] * acc[mt][nt][3];
            }
#pragma unroll
            for (int off = 1; off <= 2; off <<= 1) {
                s0 += __shfl_xor_sync(0xffffffffu, s0, off);
                q0 += __shfl_xor_sync(0xffffffffu, q0, off);
                s1 += __shfl_xor_sync(0xffffffffu, s1, off);
                q1 += __shfl_xor_sync(0xffffffffu, q1, off);
            }
            if (tg == 0) {
                ps[(mt * 16 + gid) * 8 + w] = s0;     pq[(mt * 16 + gid) * 8 + w] = q0;
                ps[(mt * 16 + 8 + gid) * 8 + w] = s1; pq[(mt * 16 + 8 + gid) * 8 + w] = q1;
            }
        }
        __syncthreads();
        if (tid < 64) {
            float s = 0.f, q = 0.f;
#pragma unroll
            for (int ww = 0; ww < 8; ++ww) { s += ps[tid * 8 + ww]; q += pq[tid * 8 + ww]; }
            const float mu = s * (1.f / 512.f);
            mus[tid] = mu;
            rss[tid] = rsqrtf(q * (1.f / 512.f) - mu * mu + LN_EPS);
        }
        __syncthreads();
#pragma unroll
        for (int mt = 0; mt < 4; ++mt) {
            const int r0 = bm + mt * 16 + gid, r1 = r0 + 8;
            const float mu0 = mus[mt * 16 + gid],     rv0 = rss[mt * 16 + gid];
            const float mu1 = mus[mt * 16 + 8 + gid], rv1 = rss[mt * 16 + 8 + gid];
#pragma unroll
            for (int nt = 0; nt < 2 * PAIRS; ++nt) {
                const int col = colb + nt * 8;
                const float g0 = __ldg(gam + col), g1 = __ldg(gam + col + 1);
                const float be0 = __ldg(bet + col), be1 = __ldg(bet + col + 1);
                float v00 = (acc[mt][nt][0] - mu0) * rv0 * g0 + be0;
                float v01 = (acc[mt][nt][1] - mu0) * rv0 * g1 + be1;
                float v10 = (acc[mt][nt][2] - mu1) * rv1 * g0 + be0;
                float v11 = (acc[mt][nt][3] - mu1) * rv1 * g1 + be1;
                if (relu) {
                    v00 = fmaxf(v00, 0.f); v01 = fmaxf(v01, 0.f);
                    v10 = fmaxf(v10, 0.f); v11 = fmaxf(v11, 0.f);
                }
                *(float2*)(out + (size_t)r0 * ldout + col) = make_float2(v00, v01);
                *(float2*)(out + (size_t)r1 * ldout + col) = make_float2(v10, v11);
            }
        }
    } else {
#pragma unroll
        for (int mt = 0; mt < 4; ++mt) {
            const int r0 = bm + mt * 16 + gid, r1 = r0 + 8;
#pragma unroll
            for (int nt = 0; nt < 2 * PAIRS; ++nt) {
                const int col = colb + nt * 8;
                float v00 = acc[mt][nt][0], v01 = acc[mt][nt][1];
                float v10 = acc[mt][nt][2], v11 = acc[mt][nt][3];
                if (relu) {
                    v00 = fmaxf(v00, 0.f); v01 = fmaxf(v01, 0.f);
                    v10 = fmaxf(v10, 0.f); v11 = fmaxf(v11, 0.f);
                }
                *(float2*)(out + (size_t)r0 * ldout + col) = make_float2(v00, v01);
                *(float2*)(out + (size_t)r1 * ldout + col) = make_float2(v10, v11);
            }
        }
    }
}

// ---------------- edge kernel (unchanged from round 4) ----------------
#define OFF_AHI  0
#define OFF_ALO  66560
#define OFF_BBUF 133120
#define OFF_B2   198656
#define OFF_GS   200704
#define OFF_BSS  202752
#define OFF_PS   204800
#define OFF_PQS  206848
#define OFF_MU   208896
#define OFF_RS   209152
#define SMEM_EDGE 209408
#define A_STRIDE 1040

__device__ __forceinline__ void stage_B(uint32_t sbase, int stage, int s, int w, int lane)
{
#pragma unroll
    for (int p = 0; p < 4; ++p) {
        const int jpg = w * 4 + p;
        const uint4* srcH = &g_BfH[(size_t)(s * 32 + jpg) * 32 + lane];
        const uint4* srcL = &g_BfL[(size_t)(s * 32 + jpg) * 32 + lane];
        const uint32_t dH = sbase + OFF_BBUF +
            ((uint32_t)((stage * 32 + jpg) * 2) * 32 + lane) * 16;
        CP_ASYNC16(dH, srcH);
        CP_ASYNC16(dH + 512, srcL);
    }
}

__global__ void __launch_bounds__(256, 1) edge_mma_kernel(
    const float* __restrict__ eb1, const float* __restrict__ b2,
    const float* __restrict__ gam, const float* __restrict__ bet)
{
    extern __shared__ __align__(16) char smem[];
    const uint32_t sbase = smem_u32(smem);
    const int tid = threadIdx.x;
    const int nb = blockIdx.x;
    const int node_base = nb * 4;
    const int b16 = (nb >> 2) << 4;
    const int o0 = (nb & 3) * 4;

    float* b2s = (float*)(smem + OFF_B2);
    float* gss = (float*)(smem + OFF_GS);
    float* bss = (float*)(smem + OFF_BSS);
    float* ps  = (float*)(smem + OFF_PS);
    float* pq  = (float*)(smem + OFF_PQS);
    float* mus = (float*)(smem + OFF_MU);
    float* rss = (float*)(smem + OFF_RS);

    for (int i = tid; i < 512; i += 256) {
        b2s[i] = b2[i]; gss[i] = gam[i]; bss[i] = bet[i];
    }

    const float4* eb1v = (const float4*)eb1;
#pragma unroll
    for (int i = 0; i < 32; ++i) {
        const int idx = tid + (i << 8);
        const int m = idx >> 7;
        const int k4 = (idx & 127) << 2;
        const int ln = m >> 4, r = m & 15;
        float4 v = make_float4(0.f, 0.f, 0.f, 0.f);
        if (r < 15) {
            const int o = o0 + ln;
            const int jj = r + (r >= o);
            const float4 p4 = *(const float4*)&g_PQ[(size_t)(node_base + ln) * 1024 + k4];
            const float4 q4 = *(const float4*)&g_PQ[(size_t)(b16 + jj) * 1024 + 512 + k4];
            const float4 bb = __ldg(&eb1v[k4 >> 2]);
            v.x = fmaxf(p4.x + q4.x + bb.x, 0.f);
            v.y = fmaxf(p4.y + q4.y + bb.y, 0.f);
            v.z = fmaxf(p4.z + q4.z + bb.z, 0.f);
            v.w = fmaxf(p4.w + q4.w + bb.w, 0.f);
        }
        float rx, ry, rz, rw, d0, d1;
        uint2 hh, ll;
        hh.x = pack_bf_pair(v.x, v.y, rx, ry);
        hh.y = pack_bf_pair(v.z, v.w, rz, rw);
        ll.x = pack_bf_pair(rx, ry, d0, d1);
        ll.y = pack_bf_pair(rz, rw, d0, d1);
        const uint32_t off = (uint32_t)m * A_STRIDE + ((uint32_t)k4 << 1);
        *(uint2*)(smem + OFF_AHI + off) = hh;
        *(uint2*)(smem + OFF_ALO + off) = ll;
    }
    __syncthreads();

    const int w = tid >> 5, lane = tid & 31;
    const int gid = lane >> 2, tg = lane & 3;
    const int lrow = (lane & 8) + (lane & 7);
    const uint32_t a_base = sbase + OFF_AHI + (uint32_t)lrow * A_STRIDE + ((lane & 16) ? 16u : 0u);

    float acc[4][8][4];
#pragma unroll
    for (int mt = 0; mt < 4; ++mt)
#pragma unroll
        for (int nt = 0; nt < 8; ++nt)
#pragma unroll
            for (int j = 0; j < 4; ++j) acc[mt][nt][j] = 0.f;

    stage_B(sbase, 0, 0, w, lane);
    CP_COMMIT();

    for (int s = 0; s < 32; ++s) {
        const int cur = s & 1;
        if (s < 31) { stage_B(sbase, cur ^ 1, s + 1, w, lane); CP_COMMIT(); CP_WAIT1(); }
        else CP_WAIT0();

        uint4 vh[4], vl[4];
#pragma unroll
        for (int p = 0; p < 4; ++p) {
            const uint32_t aH = sbase + OFF_BBUF +
                ((uint32_t)((cur * 32 + w * 4 + p) * 2) * 32 + lane) * 16;
            vh[p] = lds128(aH);
            vl[p] = lds128(aH + 512);
        }
#pragma unroll
        for (int mt = 0; mt < 4; ++mt) {
            uint32_t ah[4], al[4];
            const uint32_t aoff = (uint32_t)mt * (16 * A_STRIDE) + (uint32_t)s * 32;
            ldsm4(ah, a_base + aoff);
            ldsm4(al, a_base + (OFF_ALO - OFF_AHI) + aoff);
#pragma unroll
            for (int p = 0; p < 4; ++p) {
                mma16816(acc[mt][2 * p],     ah, vh[p].x, vh[p].y);
                mma16816(acc[mt][2 * p],     ah, vl[p].x, vl[p].y);
                mma16816(acc[mt][2 * p],     al, vh[p].x, vh[p].y);
                mma16816(acc[mt][2 * p + 1], ah, vh[p].z, vh[p].w);
                mma16816(acc[mt][2 * p + 1], ah, vl[p].z, vl[p].w);
                mma16816(acc[mt][2 * p + 1], al, vh[p].z, vh[p].w);
            }
        }
    }

    const int colb = w * 64 + tg * 2;
    float b2v[8][2];
#pragma unroll
    for (int nt = 0; nt < 8; ++nt) {
        b2v[nt][0] = b2s[colb + nt * 8];
        b2v[nt][1] = b2s[colb + nt * 8 + 1];
    }
#pragma unroll
    for (int mt = 0; mt < 4; ++mt) {
        float s0 = 0.f, q0 = 0.f, s1 = 0.f, q1 = 0.f;
#pragma unroll
        for (int nt = 0; nt < 8; ++nt) {
            const float v00 = acc[mt][nt][0] + b2v[nt][0];
            const float v01 = acc[mt][nt][1] + b2v[nt][1];
            const float v10 = acc[mt][nt][2] + b2v[nt][0];
            const float v11 = acc[mt][nt][3] + b2v[nt][1];
            acc[mt][nt][0] = v00; acc[mt][nt][1] = v01;
            acc[mt][nt][2] = v10; acc[mt][nt][3] = v11;
            s0 += v00 + v01; q0 += v00 * v00 + v01 * v01;
            s1 += v10 + v11; q1 += v10 * v10 + v11 * v11;
        }
#pragma unroll
        for (int off = 1; off <= 2; off <<= 1) {
            s0 += __shfl_xor_sync(0xffffffffu, s0, off);
            q0 += __shfl_xor_sync(0xffffffffu, q0, off);
            s1 += __shfl_xor_sync(0xffffffffu, s1, off);
            q1 += __shfl_xor_sync(0xffffffffu, q1, off);
        }
        if (tg == 0) {
            ps[(mt * 16 + gid) * 8 + w] = s0;     pq[(mt * 16 + gid) * 8 + w] = q0;
            ps[(mt * 16 + 8 + gid) * 8 + w] = s1; pq[(mt * 16 + 8 + gid) * 8 + w] = q1;
        }
    }
    __syncthreads();
    if (tid < 64) {
        float s = 0.f, q = 0.f;
#pragma unroll
        for (int ww = 0; ww < 8; ++ww) { s += ps[tid * 8 + ww]; q += pq[tid * 8 + ww]; }
        const float mu = s * (1.f / 512.f);
        mus[tid] = mu;
        rss[tid] = rsqrtf(q * (1.f / 512.f) - mu * mu + LN_EPS);
    }
    __syncthreads();

    float gv[8][2], bv[8][2];
#pragma unroll
    for (int nt = 0; nt < 8; ++nt) {
        gv[nt][0] = gss[colb + nt * 8];     gv[nt][1] = gss[colb + nt * 8 + 1];
        bv[nt][0] = bss[colb + nt * 8];     bv[nt][1] = bss[colb + nt * 8 + 1];
    }
#pragma unroll
    for (int mt = 0; mt < 4; ++mt) {
        const float mu0 = mus[mt * 16 + gid],     r0 = rss[mt * 16 + gid];
        const float mu1 = mus[mt * 16 + 8 + gid], r1 = rss[mt * 16 + 8 + gid];
        const bool last = (gid == 7);
#pragma unroll
        for (int nt = 0; nt < 8; ++nt) {
            const float v00 = fmaxf((acc[mt][nt][0] - mu0) * r0 * gv[nt][0] + bv[nt][0], 0.f);
            const float v01 = fmaxf((acc[mt][nt][1] - mu0) * r0 * gv[nt][1] + bv[nt][1], 0.f);
            const float v10 = last ? 0.f : fmaxf((acc[mt][nt][2] - mu1) * r1 * gv[nt][0] + bv[nt][0], 0.f);
            const float v11 = last ? 0.f : fmaxf((acc[mt][nt][3] - mu1) * r1 * gv[nt][1] + bv[nt][1], 0.f);
            float t0 = v00 + v10, t1 = v01 + v11;
#pragma unroll
            for (int off = 4; off <= 16; off <<= 1) {
                t0 += __shfl_xor_sync(0xffffffffu, t0, off);
                t1 += __shfl_xor_sync(0xffffffffu, t1, off);
            }
            if (lane < 4)
                *(float2*)&g_S[(size_t)(node_base + mt) * 512 + colb + nt * 8] =
                    make_float2(t0, t1);
        }
    }
}

// ---------------- launch ----------------
static inline int smem_for(int K, int PAIRS) {
    return 128 * (2 * K + 16) + PAIRS * 16384 + 5120;
}

extern "C" void kernel_launch(void* const* d_in, const int* in_sizes, int n_in,
                              void* d_out, int out_size)
{
    const float* states = (const float*)d_in[0];
    const int*   action = (const int*)d_in[1];   // int64 in ref; x64-disabled JAX -> int32
    const float* eW1 = (const float*)d_in[2];
    const float* eb1 = (const float*)d_in[3];
    const float* eW2 = (const float*)d_in[4];
    const float* eb2 = (const float*)d_in[5];
    const float* eg  = (const float*)d_in[6];
    const float* ebt = (const float*)d_in[7];
    const float* eW3 = (const float*)d_in[8];
    const float* eb3 = (const float*)d_in[9];
    const float* nW1 = (const float*)d_in[10];
    const float* nb1 = (const float*)d_in[11];
    const float* nW2 = (const float*)d_in[12];
    const float* nb2 = (const float*)d_in[13];
    const float* ng  = (const float*)d_in[14];
    const float* nbt = (const float*)d_in[15];
    const float* nW3 = (const float*)d_in[16];
    const float* nb3 = (const float*)d_in[17];
    float* out = (float*)d_out;

    float *pPQ, *pS, *pT, *pH1, *pH2, *pBP;
    cudaGetSymbolAddress((void**)&pPQ, g_PQ);
    cudaGetSymbolAddress((void**)&pS,  g_S);
    cudaGetSymbolAddress((void**)&pT,  g_T);
    cudaGetSymbolAddress((void**)&pH1, g_H1);
    cudaGetSymbolAddress((void**)&pH2, g_H2);
    cudaGetSymbolAddress((void**)&pBP, g_bp);

    uint4 *eW1aH, *eW1aL, *eW1bH, *eW1bL, *BfH, *BfL, *nW1aH, *nW1aL;
    uint4 *nW1cH, *nW1cL, *nW2H, *nW2L, *nW3H, *nW3L, *WcH, *WcL;
    cudaGetSymbolAddress((void**)&eW1aH, g_eW1aH); cudaGetSymbolAddress((void**)&eW1aL, g_eW1aL);
    cudaGetSymbolAddress((void**)&eW1bH, g_eW1bH); cudaGetSymbolAddress((void**)&eW1bL, g_eW1bL);
    cudaGetSymbolAddress((void**)&BfH,   g_BfH);   cudaGetSymbolAddress((void**)&BfL,   g_BfL);
    cudaGetSymbolAddress((void**)&nW1aH, g_nW1aH); cudaGetSymbolAddress((void**)&nW1aL, g_nW1aL);
    cudaGetSymbolAddress((void**)&nW1cH, g_nW1cH); cudaGetSymbolAddress((void**)&nW1cL, g_nW1cL);
    cudaGetSymbolAddress((void**)&nW2H,  g_nW2H);  cudaGetSymbolAddress((void**)&nW2L,  g_nW2L);
    cudaGetSymbolAddress((void**)&nW3H,  g_nW3H);  cudaGetSymbolAddress((void**)&nW3L,  g_nW3L);
    cudaGetSymbolAddress((void**)&WcH,   g_WcH);   cudaGetSymbolAddress((void**)&WcL,   g_WcL);

    static int configured = 0;
    if (!configured) {
        cudaFuncSetAttribute(edge_mma_kernel,
                             cudaFuncAttributeMaxDynamicSharedMemorySize, SMEM_EDGE);
        cudaFuncSetAttribute(mma_gemm_kernel<4, false>,
                             cudaFuncAttributeMaxDynamicSharedMemorySize, smem_for(512, 4));
        cudaFuncSetAttribute(mma_gemm_kernel<4, true>,
                             cudaFuncAttributeMaxDynamicSharedMemorySize, smem_for(512, 4));
        cudaFuncSetAttribute(mma_gemm_kernel<1, false>,
                             cudaFuncAttributeMaxDynamicSharedMemorySize, smem_for(512, 1));
        configured = 1;
    }

    const int S512 = smem_for(512, 4);
    const int S128 = smem_for(128, 4);
    const int SOUT = smem_for(512, 1);

    // ---- pack all weights into mma fragments ----
    pack_frag_kernel<<<32, 256>>>(eW1, 128, 512, 512, eW1aH, eW1aL);
    pack_frag_kernel<<<32, 256>>>(eW1 + 128 * 512, 128, 512, 512, eW1bH, eW1bL);
    pack_frag_kernel<<<128, 256>>>(eW2, 512, 512, 512, BfH, BfL);
    pack_frag_kernel<<<32, 256>>>(nW1, 128, 512, 512, nW1aH, nW1aL);
    pack_frag_kernel<<<128, 256>>>(nW1 + 132 * 512, 512, 512, 512, nW1cH, nW1cL);
    pack_frag_kernel<<<128, 256>>>(nW2, 512, 512, 512, nW2H, nW2L);
    pack_frag_kernel<<<32, 256>>>(nW3, 512, 128, 128, nW3H, nW3L);
    // b' = nb1 + 15*(eb3 @ nW1c)
    bprime_kernel<<<2, 256>>>(eb3, nW1, nb1);

    // ---- Wcomb = eW3 @ nW1c (fp32 out into g_H1 temp), then pack ----
    mma_gemm_kernel<4, false><<<8, 256, S512>>>(
        eW3, 512, nW1cH, nW1cL, nullptr, nullptr, 0,
        nullptr, nullptr, nullptr, nullptr, pH1, 512, 0);
    pack_frag_kernel<<<128, 256>>>(pH1, 512, 512, 512, WcH, WcL);

    // ---- P / Q ----
    mma_gemm_kernel<4, false><<<NNODE / 64, 256, S128>>>(
        states, 128, eW1aH, eW1aL, nullptr, nullptr, 0,
        nullptr, nullptr, nullptr, nullptr, pPQ, 1024, 0);
    mma_gemm_kernel<4, false><<<NNODE / 64, 256, S128>>>(
        states, 128, eW1bH, eW1bL, nullptr, nullptr, 0,
        nullptr, nullptr, nullptr, nullptr, pPQ + 512, 1024, 0);

    // ---- fused edge layer -> S ----
    edge_mma_kernel<<<NNODE / 4, 256, SMEM_EDGE>>>(eb1, eb2, eg, ebt);

    // ---- T = states@nW1a + act + b' ----
    mma_gemm_kernel<4, false><<<NNODE / 64, 256, S128>>>(
        states, 128, nW1aH, nW1aL, pBP, nullptr, 0,
        nW1 + 128 * 512, action, nullptr, nullptr, pT, 512, 0);

    // ---- H1 = relu(S@Wcomb + T) ----
    mma_gemm_kernel<4, false><<<NNODE / 64, 256, S512>>>(
        pS, 512, WcH, WcL, nullptr, pT, 512,
        nullptr, nullptr, nullptr, nullptr, pH1, 512, 1);

    // ---- H2 = relu(LN(H1@nW2 + nb2)) ----
    mma_gemm_kernel<4, true><<<NNODE / 64, 256, S512>>>(
        pH1, 512, nW2H, nW2L, nb2, nullptr, 0,
        nullptr, nullptr, ng, nbt, pH2, 512, 1);

    // ---- out = H2@nW3 + nb3 ----
    mma_gemm_kernel<1, false><<<NNODE / 64, 256, SOUT>>>(
        pH2, 512, nW3H, nW3L, nb3, nullptr, 0,
        nullptr, nullptr, nullptr, nullptr, out, 128, 0);
}

// round 6
// speedup vs baseline: 6.1292x; 1.3230x over previous
#include <cuda_runtime.h>
#include <cuda_bf16.h>
#include <cuda_fp16.h>
#include <math.h>
#include <stdint.h>

#define BB    512
#define OO    16
#define OBS   128
#define HH    512
#define NNODE (BB*OO)
#define LN_EPS 1e-5f

// ---------------- scratch ----------------
__device__ __align__(16) float g_PQ[(size_t)NNODE * 1024];
__device__ __align__(16) float g_S [(size_t)NNODE * HH];
__device__ __align__(16) float g_T [(size_t)NNODE * HH];
__device__ __align__(16) float g_H1[(size_t)NNODE * HH];
__device__ __align__(16) float g_H2[(size_t)NNODE * HH];
__device__ __align__(16) float g_bp[512];

// fragment-packed weights
__device__ __align__(16) uint4 g_eW1aH[8192],  g_eW1aL[8192];    // bf16
__device__ __align__(16) uint4 g_eW1bH[8192],  g_eW1bL[8192];    // bf16
__device__ __align__(16) uint4 g_W2H[32768],   g_W2L[32768];     // fp16 (edge)
__device__ __align__(16) uint4 g_nW1aH[8192],  g_nW1aL[8192];    // bf16
__device__ __align__(16) uint4 g_nW1cH[32768], g_nW1cL[32768];   // bf16
__device__ __align__(16) uint4 g_nW2H[32768],  g_nW2L[32768];    // fp16
__device__ __align__(16) uint4 g_nW3H[8192],   g_nW3L[8192];     // bf16
__device__ __align__(16) uint4 g_WcH[32768],   g_WcL[32768];     // fp16

// ---------------- helpers ----------------
__device__ __forceinline__ uint32_t smem_u32(const void* p) {
    uint32_t a;
    asm("{ .reg .u64 t; cvta.to.shared.u64 t, %1; cvt.u32.u64 %0, t; }" : "=r"(a) : "l"(p));
    return a;
}
__device__ __forceinline__ void ldsm4(uint32_t* r, uint32_t addr) {
    asm volatile("ldmatrix.sync.aligned.m8n8.x4.shared.b16 {%0,%1,%2,%3}, [%4];"
        : "=r"(r[0]), "=r"(r[1]), "=r"(r[2]), "=r"(r[3]) : "r"(addr));
}
__device__ __forceinline__ uint4 lds128(uint32_t a) {
    uint4 v;
    asm volatile("ld.shared.v4.b32 {%0,%1,%2,%3}, [%4];"
        : "=r"(v.x), "=r"(v.y), "=r"(v.z), "=r"(v.w) : "r"(a));
    return v;
}
__device__ __forceinline__ void mma_bf16(float* c, const uint32_t* a, uint32_t b0, uint32_t b1) {
    asm volatile(
        "mma.sync.aligned.m16n8k16.row.col.f32.bf16.bf16.f32 "
        "{%0,%1,%2,%3}, {%4,%5,%6,%7}, {%8,%9}, {%0,%1,%2,%3};"
        : "+f"(c[0]), "+f"(c[1]), "+f"(c[2]), "+f"(c[3])
        : "r"(a[0]), "r"(a[1]), "r"(a[2]), "r"(a[3]), "r"(b0), "r"(b1));
}
__device__ __forceinline__ void mma_f16(float* c, const uint32_t* a, uint32_t b0, uint32_t b1) {
    asm volatile(
        "mma.sync.aligned.m16n8k16.row.col.f32.f16.f16.f32 "
        "{%0,%1,%2,%3}, {%4,%5,%6,%7}, {%8,%9}, {%0,%1,%2,%3};"
        : "+f"(c[0]), "+f"(c[1]), "+f"(c[2]), "+f"(c[3])
        : "r"(a[0]), "r"(a[1]), "r"(a[2]), "r"(a[3]), "r"(b0), "r"(b1));
}
#define CP_ASYNC16(dst, src) \
    asm volatile("cp.async.cg.shared.global [%0], [%1], 16;" \
                 :: "r"(dst), "l"(__cvta_generic_to_global(src)))
#define CP_COMMIT() asm volatile("cp.async.commit_group;" ::: "memory")
#define CP_WAIT1()  asm volatile("cp.async.wait_group 1;" ::: "memory")
#define CP_WAIT0()  asm volatile("cp.async.wait_group 0;" ::: "memory")

__device__ __forceinline__ uint32_t pack_bf_pair(float a, float b, float& ra, float& rb) {
    const __nv_bfloat16 ha = __float2bfloat16(a), hb = __float2bfloat16(b);
    ra = a - __bfloat162float(ha);
    rb = b - __bfloat162float(hb);
    return (uint32_t)__bfloat16_as_ushort(ha) | ((uint32_t)__bfloat16_as_ushort(hb) << 16);
}
__device__ __forceinline__ uint32_t pack_h_pair(float a, float b, float& ra, float& rb) {
    const __half ha = __float2half_rn(a), hb = __float2half_rn(b);
    ra = a - __half2float(ha);
    rb = b - __half2float(hb);
    return (uint32_t)__half_as_ushort(ha) | ((uint32_t)__half_as_ushort(hb) << 16);
}

// ---------------- pack one fragment item ----------------
__device__ __forceinline__ void pack_item(
    const float* __restrict__ W, int ldW, int npairs,
    uint4* __restrict__ dH, uint4* __restrict__ dL, bool f16, int item)
{
    const int lane = item & 31;
    const int gid = lane >> 2, tg = lane & 3;
    const int jp = (item >> 5) % npairs;
    const int s = item / (npairs * 32);
    const int k0 = s * 16 + tg * 2;

    uint32_t h[4], l[4];
#pragma unroll
    for (int half = 0; half < 2; ++half) {
        const int n = (jp * 2 + half) * 8 + gid;
        const float f00 = W[(size_t)k0 * ldW + n];
        const float f01 = W[(size_t)(k0 + 1) * ldW + n];
        const float f10 = W[(size_t)(k0 + 8) * ldW + n];
        const float f11 = W[(size_t)(k0 + 9) * ldW + n];
        float r00, r01, r10, r11, d0, d1;
        if (f16) {
            h[half * 2 + 0] = pack_h_pair(f00, f01, r00, r01);
            h[half * 2 + 1] = pack_h_pair(f10, f11, r10, r11);
            l[half * 2 + 0] = pack_h_pair(r00, r01, d0, d1);
            l[half * 2 + 1] = pack_h_pair(r10, r11, d0, d1);
        } else {
            h[half * 2 + 0] = pack_bf_pair(f00, f01, r00, r01);
            h[half * 2 + 1] = pack_bf_pair(f10, f11, r10, r11);
            l[half * 2 + 0] = pack_bf_pair(r00, r01, d0, d1);
            l[half * 2 + 1] = pack_bf_pair(r10, r11, d0, d1);
        }
    }
    const int dst = (s * npairs + jp) * 32 + lane;
    dH[dst] = make_uint4(h[0], h[1], h[2], h[3]);
    dL[dst] = make_uint4(l[0], l[1], l[2], l[3]);
}

// ---------------- mega pack: all weights + bprime, one launch ----------------
__global__ void mega_pack_kernel(const float* __restrict__ eW1, const float* __restrict__ eW2,
                                 const float* __restrict__ nW1, const float* __restrict__ nW2,
                                 const float* __restrict__ nW3,
                                 const float* __restrict__ eb3, const float* __restrict__ nb1)
{
    const int idx = blockIdx.x * 256 + threadIdx.x;
    if (idx < 8192)        pack_item(eW1,             512, 32, g_eW1aH, g_eW1aL, false, idx);
    else if (idx < 16384)  pack_item(eW1 + 128 * 512, 512, 32, g_eW1bH, g_eW1bL, false, idx - 8192);
    else if (idx < 49152)  pack_item(eW2,             512, 32, g_W2H,   g_W2L,   true,  idx - 16384);
    else if (idx < 57344)  pack_item(nW1,             512, 32, g_nW1aH, g_nW1aL, false, idx - 49152);
    else if (idx < 90112)  pack_item(nW1 + 132 * 512, 512, 32, g_nW1cH, g_nW1cL, false, idx - 57344);
    else if (idx < 122880) pack_item(nW2,             512, 32, g_nW2H,  g_nW2L,  true,  idx - 90112);
    else if (idx < 131072) pack_item(nW3,             128, 8,  g_nW3H,  g_nW3L,  false, idx - 122880);
    else if (idx < 131584) {
        const int n = idx - 131072;
        float acc = 0.f;
#pragma unroll 8
        for (int k = 0; k < 512; ++k)
            acc += eb3[k] * nW1[(size_t)(132 + k) * 512 + n];
        g_bp[n] = nb1[n] + 15.f * acc;
    }
}

// ---------------- standalone packer (for Wcomb) ----------------
__global__ void pack_frag_kernel(const float* __restrict__ W, int npairs,
                                 uint4* __restrict__ dstH, uint4* __restrict__ dstL, int f16)
{
    const int idx = blockIdx.x * 256 + threadIdx.x;
    pack_item(W, npairs * 16, npairs, dstH, dstL, f16 != 0, idx);
}

// ================= generic split HMMA GEMM =================
// F16=false: bf16 3-term. F16=true: fp16 2-term (A hi only).
template<int PAIRS, bool LN, bool F16>
__global__ void __launch_bounds__(256, 1) mma_gemm_kernel(
    const float* __restrict__ X, int K,
    const uint4* __restrict__ WH, const uint4* __restrict__ WL,
    const float* __restrict__ bias,
    const float* __restrict__ addend, int ldadd,
    const float* __restrict__ actW, const int* __restrict__ action,
    const float* __restrict__ gam, const float* __restrict__ bet,
    float* __restrict__ out, int ldout, int relu)
{
    extern __shared__ __align__(16) char smem[];
    const uint32_t sbase = smem_u32(smem);
    const int tid = threadIdx.x;
    const int bm = blockIdx.x * 64;
    const int NP = 8 * PAIRS;
    const int A_ST = K * 2 + 16;
    const uint32_t offALO = (uint32_t)64 * A_ST;
    const uint32_t offB = F16 ? offALO : 2 * offALO;
    const uint32_t offEpi = offB + (uint32_t)2 * NP * 1024;
    const int kst = K / 16;

    // ---- build A in smem ----
    const int kd4 = K >> 2;
    for (int idx = tid; idx < 64 * kd4; idx += 256) {
        const int m = idx / kd4, k4 = (idx - m * kd4) * 4;
        const float4 v = *(const float4*)(X + (size_t)(bm + m) * K + k4);
        const uint32_t off = (uint32_t)m * A_ST + ((uint32_t)k4 << 1);
        float rx, ry, rz, rw, d0, d1;
        uint2 hh;
        if (F16) {
            hh.x = pack_h_pair(v.x, v.y, rx, ry);
            hh.y = pack_h_pair(v.z, v.w, rz, rw);
            *(uint2*)(smem + off) = hh;
        } else {
            uint2 ll;
            hh.x = pack_bf_pair(v.x, v.y, rx, ry);
            hh.y = pack_bf_pair(v.z, v.w, rz, rw);
            ll.x = pack_bf_pair(rx, ry, d0, d1);
            ll.y = pack_bf_pair(rz, rw, d0, d1);
            *(uint2*)(smem + off) = hh;
            *(uint2*)(smem + offALO + off) = ll;
        }
    }
    __syncthreads();

    const int w = tid >> 5, lane = tid & 31;
    const int gid = lane >> 2, tg = lane & 3;
    const int lrow = (lane & 8) + (lane & 7);
    const uint32_t a_base = sbase + (uint32_t)lrow * A_ST + ((lane & 16) ? 16u : 0u);

    float acc[4][2 * PAIRS][4];
#pragma unroll
    for (int mt = 0; mt < 4; ++mt)
#pragma unroll
        for (int nt = 0; nt < 2 * PAIRS; ++nt)
#pragma unroll
            for (int j = 0; j < 4; ++j) acc[mt][nt][j] = 0.f;

    auto stageB = [&](int stage, int s) {
#pragma unroll
        for (int p = 0; p < PAIRS; ++p) {
            const int jpg = w * PAIRS + p;
            const uint32_t d = sbase + offB +
                ((uint32_t)((stage * NP + jpg) * 2) * 32 + lane) * 16;
            CP_ASYNC16(d, WH + ((size_t)(s * NP + jpg) * 32 + lane));
            CP_ASYNC16(d + 512, WL + ((size_t)(s * NP + jpg) * 32 + lane));
        }
    };

    stageB(0, 0); CP_COMMIT();

    for (int s = 0; s < kst; ++s) {
        const int cur = s & 1;
        if (s < kst - 1) { stageB(cur ^ 1, s + 1); CP_COMMIT(); CP_WAIT1(); }
        else CP_WAIT0();

        uint4 vh[PAIRS], vl[PAIRS];
#pragma unroll
        for (int p = 0; p < PAIRS; ++p) {
            const uint32_t aH = sbase + offB +
                ((uint32_t)((cur * NP + w * PAIRS + p) * 2) * 32 + lane) * 16;
            vh[p] = lds128(aH);
            vl[p] = lds128(aH + 512);
        }
#pragma unroll
        for (int mt = 0; mt < 4; ++mt) {
            uint32_t ah[4], al[4];
            const uint32_t aoff = (uint32_t)mt * 16 * A_ST + (uint32_t)s * 32;
            ldsm4(ah, a_base + aoff);
            if (!F16) ldsm4(al, a_base + offALO + aoff);
#pragma unroll
            for (int p = 0; p < PAIRS; ++p) {
                if (F16) {
                    mma_f16(acc[mt][2 * p],     ah, vh[p].x, vh[p].y);
                    mma_f16(acc[mt][2 * p],     ah, vl[p].x, vl[p].y);
                    mma_f16(acc[mt][2 * p + 1], ah, vh[p].z, vh[p].w);
                    mma_f16(acc[mt][2 * p + 1], ah, vl[p].z, vl[p].w);
                } else {
                    mma_bf16(acc[mt][2 * p],     ah, vh[p].x, vh[p].y);
                    mma_bf16(acc[mt][2 * p],     ah, vl[p].x, vl[p].y);
                    mma_bf16(acc[mt][2 * p],     al, vh[p].x, vh[p].y);
                    mma_bf16(acc[mt][2 * p + 1], ah, vh[p].z, vh[p].w);
                    mma_bf16(acc[mt][2 * p + 1], ah, vl[p].z, vl[p].w);
                    mma_bf16(acc[mt][2 * p + 1], al, vh[p].z, vh[p].w);
                }
            }
        }
    }

    // ---- epilogue ----
    const int colb = w * (16 * PAIRS) + tg * 2;
    float* ps  = (float*)(smem + offEpi);
    float* pq  = ps + 512;
    float* mus = pq + 512;
    float* rss = mus + 64;

#pragma unroll
    for (int mt = 0; mt < 4; ++mt) {
        const int r0 = bm + mt * 16 + gid;
        const int r1 = r0 + 8;
        int t0 = 5, t1 = 5;
        if (actW) {
            const int a = action[r0 >> 4];
            t0 = a - 4 * (r0 & 15);
            t1 = a - 4 * (r1 & 15);
        }
#pragma unroll
        for (int nt = 0; nt < 2 * PAIRS; ++nt) {
            const int col = colb + nt * 8;
            float b0 = 0.f, b1 = 0.f;
            if (bias) { b0 = __ldg(bias + col); b1 = __ldg(bias + col + 1); }
            float v00 = acc[mt][nt][0] + b0, v01 = acc[mt][nt][1] + b1;
            float v10 = acc[mt][nt][2] + b0, v11 = acc[mt][nt][3] + b1;
            if (addend) {
                const float2 a0 = *(const float2*)(addend + (size_t)r0 * ldadd + col);
                const float2 a1 = *(const float2*)(addend + (size_t)r1 * ldadd + col);
                v00 += a0.x; v01 += a0.y; v10 += a1.x; v11 += a1.y;
            }
            if (actW) {
                if ((unsigned)t0 < 4u) {
                    v00 += __ldg(actW + (size_t)t0 * 512 + col);
                    v01 += __ldg(actW + (size_t)t0 * 512 + col + 1);
                }
                if ((unsigned)t1 < 4u) {
                    v10 += __ldg(actW + (size_t)t1 * 512 + col);
                    v11 += __ldg(actW + (size_t)t1 * 512 + col + 1);
                }
            }
            acc[mt][nt][0] = v00; acc[mt][nt][1] = v01;
            acc[mt][nt][2] = v10; acc[mt][nt][3] = v11;
        }
    }

    if (LN) {
#pragma unroll
        for (int mt = 0; mt < 4; ++mt) {
            float s0 = 0.f, q0 = 0.f, s1 = 0.f, q1 = 0.f;
#pragma unroll
            for (int nt = 0; nt < 2 * PAIRS; ++nt) {
                s0 += acc[mt][nt][0] + acc[mt][nt][1];
                q0 += acc[mt][nt][0] * acc[mt][nt][0] + acc[mt][nt][1] * acc[mt][nt][1];
                s1 += acc[mt][nt][2] + acc[mt][nt][3];
                q1 += acc[mt][nt][2] * acc[mt][nt][2] + acc[mt][nt][3] * acc[mt][nt][3];
            }
#pragma unroll
            for (int off = 1; off <= 2; off <<= 1) {
                s0 += __shfl_xor_sync(0xffffffffu, s0, off);
                q0 += __shfl_xor_sync(0xffffffffu, q0, off);
                s1 += __shfl_xor_sync(0xffffffffu, s1, off);
                q1 += __shfl_xor_sync(0xffffffffu, q1, off);
            }
            if (tg == 0) {
                ps[(mt * 16 + gid) * 8 + w] = s0;     pq[(mt * 16 + gid) * 8 + w] = q0;
                ps[(mt * 16 + 8 + gid) * 8 + w] = s1; pq[(mt * 16 + 8 + gid) * 8 + w] = q1;
            }
        }
        __syncthreads();
        if (tid < 64) {
            float s = 0.f, q = 0.f;
#pragma unroll
            for (int ww = 0; ww < 8; ++ww) { s += ps[tid * 8 + ww]; q += pq[tid * 8 + ww]; }
            const float mu = s * (1.f / 512.f);
            mus[tid] = mu;
            rss[tid] = rsqrtf(q * (1.f / 512.f) - mu * mu + LN_EPS);
        }
        __syncthreads();
#pragma unroll
        for (int mt = 0; mt < 4; ++mt) {
            const int r0 = bm + mt * 16 + gid, r1 = r0 + 8;
            const float mu0 = mus[mt * 16 + gid],     rv0 = rss[mt * 16 + gid];
            const float mu1 = mus[mt * 16 + 8 + gid], rv1 = rss[mt * 16 + 8 + gid];
#pragma unroll
            for (int nt = 0; nt < 2 * PAIRS; ++nt) {
                const int col = colb + nt * 8;
                const float g0 = __ldg(gam + col), g1 = __ldg(gam + col + 1);
                const float be0 = __ldg(bet + col), be1 = __ldg(bet + col + 1);
                float v00 = (acc[mt][nt][0] - mu0) * rv0 * g0 + be0;
                float v01 = (acc[mt][nt][1] - mu0) * rv0 * g1 + be1;
                float v10 = (acc[mt][nt][2] - mu1) * rv1 * g0 + be0;
                float v11 = (acc[mt][nt][3] - mu1) * rv1 * g1 + be1;
                if (relu) {
                    v00 = fmaxf(v00, 0.f); v01 = fmaxf(v01, 0.f);
                    v10 = fmaxf(v10, 0.f); v11 = fmaxf(v11, 0.f);
                }
                *(float2*)(out + (size_t)r0 * ldout + col) = make_float2(v00, v01);
                *(float2*)(out + (size_t)r1 * ldout + col) = make_float2(v10, v11);
            }
        }
    } else {
#pragma unroll
        for (int mt = 0; mt < 4; ++mt) {
            const int r0 = bm + mt * 16 + gid, r1 = r0 + 8;
#pragma unroll
            for (int nt = 0; nt < 2 * PAIRS; ++nt) {
                const int col = colb + nt * 8;
                float v00 = acc[mt][nt][0], v01 = acc[mt][nt][1];
                float v10 = acc[mt][nt][2], v11 = acc[mt][nt][3];
                if (relu) {
                    v00 = fmaxf(v00, 0.f); v01 = fmaxf(v01, 0.f);
                    v10 = fmaxf(v10, 0.f); v11 = fmaxf(v11, 0.f);
                }
                *(float2*)(out + (size_t)r0 * ldout + col) = make_float2(v00, v01);
                *(float2*)(out + (size_t)r1 * ldout + col) = make_float2(v10, v11);
            }
        }
    }
}

// ---------------- edge kernel: fp16 2-term ----------------
#define A_STRIDE 1040
#define OFF_AHI   0
#define OFF_BBUF  66560
#define OFF_B2    132096
#define OFF_GS    134144
#define OFF_BSS   136192
#define OFF_PS    138240
#define OFF_PQS   140288
#define OFF_MU    142336
#define OFF_RS    142592
#define SMEM_EDGE 142848

__device__ __forceinline__ void stage_B_edge(uint32_t sbase, int stage, int s, int w, int lane)
{
#pragma unroll
    for (int p = 0; p < 4; ++p) {
        const int jpg = w * 4 + p;
        const uint32_t dH = sbase + OFF_BBUF +
            ((uint32_t)((stage * 32 + jpg) * 2) * 32 + lane) * 16;
        CP_ASYNC16(dH, g_W2H + ((size_t)(s * 32 + jpg) * 32 + lane));
        CP_ASYNC16(dH + 512, g_W2L + ((size_t)(s * 32 + jpg) * 32 + lane));
    }
}

__global__ void __launch_bounds__(256, 1) edge_mma_kernel(
    const float* __restrict__ eb1, const float* __restrict__ b2,
    const float* __restrict__ gam, const float* __restrict__ bet)
{
    extern __shared__ __align__(16) char smem[];
    const uint32_t sbase = smem_u32(smem);
    const int tid = threadIdx.x;
    const int nb = blockIdx.x;
    const int node_base = nb * 4;
    const int b16 = (nb >> 2) << 4;
    const int o0 = (nb & 3) * 4;

    float* b2s = (float*)(smem + OFF_B2);
    float* gss = (float*)(smem + OFF_GS);
    float* bss = (float*)(smem + OFF_BSS);
    float* ps  = (float*)(smem + OFF_PS);
    float* pq  = (float*)(smem + OFF_PQS);
    float* mus = (float*)(smem + OFF_MU);
    float* rss = (float*)(smem + OFF_RS);

    for (int i = tid; i < 512; i += 256) {
        b2s[i] = b2[i]; gss[i] = gam[i]; bss[i] = bet[i];
    }

    // A = relu(P + Q + eb1) -> fp16 hi only
    const float4* eb1v = (const float4*)eb1;
#pragma unroll
    for (int i = 0; i < 32; ++i) {
        const int idx = tid + (i << 8);
        const int m = idx >> 7;
        const int k4 = (idx & 127) << 2;
        const int ln = m >> 4, r = m & 15;
        float4 v = make_float4(0.f, 0.f, 0.f, 0.f);
        if (r < 15) {
            const int o = o0 + ln;
            const int jj = r + (r >= o);
            const float4 p4 = *(const float4*)&g_PQ[(size_t)(node_base + ln) * 1024 + k4];
            const float4 q4 = *(const float4*)&g_PQ[(size_t)(b16 + jj) * 1024 + 512 + k4];
            const float4 bb = __ldg(&eb1v[k4 >> 2]);
            v.x = fmaxf(p4.x + q4.x + bb.x, 0.f);
            v.y = fmaxf(p4.y + q4.y + bb.y, 0.f);
            v.z = fmaxf(p4.z + q4.z + bb.z, 0.f);
            v.w = fmaxf(p4.w + q4.w + bb.w, 0.f);
        }
        float rx, ry, rz, rw;
        uint2 hh;
        hh.x = pack_h_pair(v.x, v.y, rx, ry);
        hh.y = pack_h_pair(v.z, v.w, rz, rw);
        *(uint2*)(smem + OFF_AHI + (uint32_t)m * A_STRIDE + ((uint32_t)k4 << 1)) = hh;
    }
    __syncthreads();

    const int w = tid >> 5, lane = tid & 31;
    const int gid = lane >> 2, tg = lane & 3;
    const int lrow = (lane & 8) + (lane & 7);
    const uint32_t a_base = sbase + OFF_AHI + (uint32_t)lrow * A_STRIDE + ((lane & 16) ? 16u : 0u);

    float acc[4][8][4];
#pragma unroll
    for (int mt = 0; mt < 4; ++mt)
#pragma unroll
        for (int nt = 0; nt < 8; ++nt)
#pragma unroll
            for (int j = 0; j < 4; ++j) acc[mt][nt][j] = 0.f;

    stage_B_edge(sbase, 0, 0, w, lane);
    CP_COMMIT();

    for (int s = 0; s < 32; ++s) {
        const int cur = s & 1;
        if (s < 31) { stage_B_edge(sbase, cur ^ 1, s + 1, w, lane); CP_COMMIT(); CP_WAIT1(); }
        else CP_WAIT0();

        uint4 vh[4], vl[4];
#pragma unroll
        for (int p = 0; p < 4; ++p) {
            const uint32_t aH = sbase + OFF_BBUF +
                ((uint32_t)((cur * 32 + w * 4 + p) * 2) * 32 + lane) * 16;
            vh[p] = lds128(aH);
            vl[p] = lds128(aH + 512);
        }
#pragma unroll
        for (int mt = 0; mt < 4; ++mt) {
            uint32_t ah[4];
            ldsm4(ah, a_base + (uint32_t)mt * (16 * A_STRIDE) + (uint32_t)s * 32);
#pragma unroll
            for (int p = 0; p < 4; ++p) {
                mma_f16(acc[mt][2 * p],     ah, vh[p].x, vh[p].y);
                mma_f16(acc[mt][2 * p],     ah, vl[p].x, vl[p].y);
                mma_f16(acc[mt][2 * p + 1], ah, vh[p].z, vh[p].w);
                mma_f16(acc[mt][2 * p + 1], ah, vl[p].z, vl[p].w);
            }
        }
    }

    // epilogue: bias + LN + relu + 15-row node sum
    const int colb = w * 64 + tg * 2;
    float b2v[8][2];
#pragma unroll
    for (int nt = 0; nt < 8; ++nt) {
        b2v[nt][0] = b2s[colb + nt * 8];
        b2v[nt][1] = b2s[colb + nt * 8 + 1];
    }
#pragma unroll
    for (int mt = 0; mt < 4; ++mt) {
        float s0 = 0.f, q0 = 0.f, s1 = 0.f, q1 = 0.f;
#pragma unroll
        for (int nt = 0; nt < 8; ++nt) {
            const float v00 = acc[mt][nt][0] + b2v[nt][0];
            const float v01 = acc[mt][nt][1] + b2v[nt][1];
            const float v10 = acc[mt][nt][2] + b2v[nt][0];
            const float v11 = acc[mt][nt][3] + b2v[nt][1];
            acc[mt][nt][0] = v00; acc[mt][nt][1] = v01;
            acc[mt][nt][2] = v10; acc[mt][nt][3] = v11;
            s0 += v00 + v01; q0 += v00 * v00 + v01 * v01;
            s1 += v10 + v11; q1 += v10 * v10 + v11 * v11;
        }
#pragma unroll
        for (int off = 1; off <= 2; off <<= 1) {
            s0 += __shfl_xor_sync(0xffffffffu, s0, off);
            q0 += __shfl_xor_sync(0xffffffffu, q0, off);
            s1 += __shfl_xor_sync(0xffffffffu, s1, off);
            q1 += __shfl_xor_sync(0xffffffffu, q1, off);
        }
        if (tg == 0) {
            ps[(mt * 16 + gid) * 8 + w] = s0;     pq[(mt * 16 + gid) * 8 + w] = q0;
            ps[(mt * 16 + 8 + gid) * 8 + w] = s1; pq[(mt * 16 + 8 + gid) * 8 + w] = q1;
        }
    }
    __syncthreads();
    if (tid < 64) {
        float s = 0.f, q = 0.f;
#pragma unroll
        for (int ww = 0; ww < 8; ++ww) { s += ps[tid * 8 + ww]; q += pq[tid * 8 + ww]; }
        const float mu = s * (1.f / 512.f);
        mus[tid] = mu;
        rss[tid] = rsqrtf(q * (1.f / 512.f) - mu * mu + LN_EPS);
    }
    __syncthreads();

    float gv[8][2], bv[8][2];
#pragma unroll
    for (int nt = 0; nt < 8; ++nt) {
        gv[nt][0] = gss[colb + nt * 8];     gv[nt][1] = gss[colb + nt * 8 + 1];
        bv[nt][0] = bss[colb + nt * 8];     bv[nt][1] = bss[colb + nt * 8 + 1];
    }
#pragma unroll
    for (int mt = 0; mt < 4; ++mt) {
        const float mu0 = mus[mt * 16 + gid],     r0 = rss[mt * 16 + gid];
        const float mu1 = mus[mt * 16 + 8 + gid], r1 = rss[mt * 16 + 8 + gid];
        const bool last = (gid == 7);
#pragma unroll
        for (int nt = 0; nt < 8; ++nt) {
            const float v00 = fmaxf((acc[mt][nt][0] - mu0) * r0 * gv[nt][0] + bv[nt][0], 0.f);
            const float v01 = fmaxf((acc[mt][nt][1] - mu0) * r0 * gv[nt][1] + bv[nt][1], 0.f);
            const float v10 = last ? 0.f : fmaxf((acc[mt][nt][2] - mu1) * r1 * gv[nt][0] + bv[nt][0], 0.f);
            const float v11 = last ? 0.f : fmaxf((acc[mt][nt][3] - mu1) * r1 * gv[nt][1] + bv[nt][1], 0.f);
            float t0 = v00 + v10, t1 = v01 + v11;
#pragma unroll
            for (int off = 4; off <= 16; off <<= 1) {
                t0 += __shfl_xor_sync(0xffffffffu, t0, off);
                t1 += __shfl_xor_sync(0xffffffffu, t1, off);
            }
            if (lane < 4)
                *(float2*)&g_S[(size_t)(node_base + mt) * 512 + colb + nt * 8] =
                    make_float2(t0, t1);
        }
    }
}

// ---------------- launch ----------------
static inline int smem_for(int K, int PAIRS) {
    return 128 * (2 * K + 16) + PAIRS * 16384 + 5120;
}

extern "C" void kernel_launch(void* const* d_in, const int* in_sizes, int n_in,
                              void* d_out, int out_size)
{
    const float* states = (const float*)d_in[0];
    const int*   action = (const int*)d_in[1];
    const float* eW1 = (const float*)d_in[2];
    const float* eb1 = (const float*)d_in[3];
    const float* eW2 = (const float*)d_in[4];
    const float* eb2 = (const float*)d_in[5];
    const float* eg  = (const float*)d_in[6];
    const float* ebt = (const float*)d_in[7];
    const float* eW3 = (const float*)d_in[8];
    const float* eb3 = (const float*)d_in[9];
    const float* nW1 = (const float*)d_in[10];
    const float* nb1 = (const float*)d_in[11];
    const float* nW2 = (const float*)d_in[12];
    const float* nb2 = (const float*)d_in[13];
    const float* ng  = (const float*)d_in[14];
    const float* nbt = (const float*)d_in[15];
    const float* nW3 = (const float*)d_in[16];
    const float* nb3 = (const float*)d_in[17];
    float* out = (float*)d_out;

    float *pPQ, *pS, *pT, *pH1, *pH2, *pBP;
    cudaGetSymbolAddress((void**)&pPQ, g_PQ);
    cudaGetSymbolAddress((void**)&pS,  g_S);
    cudaGetSymbolAddress((void**)&pT,  g_T);
    cudaGetSymbolAddress((void**)&pH1, g_H1);
    cudaGetSymbolAddress((void**)&pH2, g_H2);
    cudaGetSymbolAddress((void**)&pBP, g_bp);

    uint4 *eW1aH, *eW1aL, *eW1bH, *eW1bL, *nW1aH, *nW1aL;
    uint4 *nW2H, *nW2L, *nW3H, *nW3L, *WcH, *WcL, *nW1cH, *nW1cL;
    cudaGetSymbolAddress((void**)&eW1aH, g_eW1aH); cudaGetSymbolAddress((void**)&eW1aL, g_eW1aL);
    cudaGetSymbolAddress((void**)&eW1bH, g_eW1bH); cudaGetSymbolAddress((void**)&eW1bL, g_eW1bL);
    cudaGetSymbolAddress((void**)&nW1aH, g_nW1aH); cudaGetSymbolAddress((void**)&nW1aL, g_nW1aL);
    cudaGetSymbolAddress((void**)&nW1cH, g_nW1cH); cudaGetSymbolAddress((void**)&nW1cL, g_nW1cL);
    cudaGetSymbolAddress((void**)&nW2H,  g_nW2H);  cudaGetSymbolAddress((void**)&nW2L,  g_nW2L);
    cudaGetSymbolAddress((void**)&nW3H,  g_nW3H);  cudaGetSymbolAddress((void**)&nW3L,  g_nW3L);
    cudaGetSymbolAddress((void**)&WcH,   g_WcH);   cudaGetSymbolAddress((void**)&WcL,   g_WcL);

    static int configured = 0;
    if (!configured) {
        cudaFuncSetAttribute(edge_mma_kernel,
                             cudaFuncAttributeMaxDynamicSharedMemorySize, SMEM_EDGE);
        cudaFuncSetAttribute(mma_gemm_kernel<4, false, false>,
                             cudaFuncAttributeMaxDynamicSharedMemorySize, smem_for(512, 4));
        cudaFuncSetAttribute(mma_gemm_kernel<4, false, true>,
                             cudaFuncAttributeMaxDynamicSharedMemorySize, smem_for(512, 4));
        cudaFuncSetAttribute(mma_gemm_kernel<4, true, true>,
                             cudaFuncAttributeMaxDynamicSharedMemorySize, smem_for(512, 4));
        cudaFuncSetAttribute(mma_gemm_kernel<1, false, false>,
                             cudaFuncAttributeMaxDynamicSharedMemorySize, smem_for(512, 1));
        configured = 1;
    }

    const int S512 = smem_for(512, 4);
    const int S128 = smem_for(128, 4);
    const int SOUT = smem_for(512, 1);

    // 1) pack all weights + bprime (one launch)
    mega_pack_kernel<<<514, 256>>>(eW1, eW2, nW1, nW2, nW3, eb3, nb1);

    // 2) Wcomb = eW3 @ nW1c (bf16 3-term, fp32 out to g_H1 temp), pack to fp16
    mma_gemm_kernel<4, false, false><<<8, 256, S512>>>(
        eW3, 512, nW1cH, nW1cL, nullptr, nullptr, 0,
        nullptr, nullptr, nullptr, nullptr, pH1, 512, 0);
    pack_frag_kernel<<<128, 256>>>(pH1, 32, WcH, WcL, 1);

    // 3) P / Q (bf16 3-term)
    mma_gemm_kernel<4, false, false><<<NNODE / 64, 256, S128>>>(
        states, 128, eW1aH, eW1aL, nullptr, nullptr, 0,
        nullptr, nullptr, nullptr, nullptr, pPQ, 1024, 0);
    mma_gemm_kernel<4, false, false><<<NNODE / 64, 256, S128>>>(
        states, 128, eW1bH, eW1bL, nullptr, nullptr, 0,
        nullptr, nullptr, nullptr, nullptr, pPQ + 512, 1024, 0);

    // 4) fused edge layer (fp16 2-term) -> S
    edge_mma_kernel<<<NNODE / 4, 256, SMEM_EDGE>>>(eb1, eb2, eg, ebt);

    // 5) T = states@nW1a + act + b' (bf16 3-term)
    mma_gemm_kernel<4, false, false><<<NNODE / 64, 256, S128>>>(
        states, 128, nW1aH, nW1aL, pBP, nullptr, 0,
        nW1 + 128 * 512, action, nullptr, nullptr, pT, 512, 0);

    // 6) H1 = relu(S@Wcomb + T) (fp16 2-term)
    mma_gemm_kernel<4, false, true><<<NNODE / 64, 256, S512>>>(
        pS, 512, WcH, WcL, nullptr, pT, 512,
        nullptr, nullptr, nullptr, nullptr, pH1, 512, 1);

    // 7) H2 = relu(LN(H1@nW2 + nb2)) (fp16 2-term)
    mma_gemm_kernel<4, true, true><<<NNODE / 64, 256, S512>>>(
        pH1, 512, nW2H, nW2L, nb2, nullptr, 0,
        nullptr, nullptr, ng, nbt, pH2, 512, 1);

    // 8) out = H2@nW3 + nb3 (bf16 3-term)
    mma_gemm_kernel<1, false, false><<<NNODE / 64, 256, SOUT>>>(
        pH2, 512, nW3H, nW3L, nb3, nullptr, 0,
        nullptr, nullptr, nullptr, nullptr, out, 128, 0);
}

// round 7
// speedup vs baseline: 6.1865x; 1.0094x over previous
#include <cuda_runtime.h>
#include <cuda_bf16.h>
#include <cuda_fp16.h>
#include <math.h>
#include <stdint.h>

#define BB    512
#define OO    16
#define OBS   128
#define HH    512
#define NNODE (BB*OO)
#define LN_EPS 1e-5f

// ---------------- scratch ----------------
__device__ __align__(16) float g_PQ[(size_t)NNODE * 1024];
__device__ __align__(16) float g_S [(size_t)NNODE * HH];
__device__ __align__(16) float g_T [(size_t)NNODE * HH];
__device__ __align__(16) float g_H1[(size_t)NNODE * HH];
__device__ __align__(16) float g_H2[(size_t)NNODE * HH];
__device__ __align__(16) float g_bp[512];

// fragment-packed weights
__device__ __align__(16) uint4 g_eW1aH[8192],  g_eW1aL[8192];    // bf16
__device__ __align__(16) uint4 g_eW1bH[8192],  g_eW1bL[8192];    // bf16
__device__ __align__(16) uint4 g_W2H[32768],   g_W2L[32768];     // fp16 (edge)
__device__ __align__(16) uint4 g_nW1aH[8192],  g_nW1aL[8192];    // bf16
__device__ __align__(16) uint4 g_nW1cH[32768], g_nW1cL[32768];   // bf16
__device__ __align__(16) uint4 g_nW2H[32768],  g_nW2L[32768];    // fp16
__device__ __align__(16) uint4 g_nW3H[8192],   g_nW3L[8192];     // bf16
__device__ __align__(16) uint4 g_WcH[32768],   g_WcL[32768];     // fp16

// ---------------- helpers ----------------
__device__ __forceinline__ uint32_t smem_u32(const void* p) {
    uint32_t a;
    asm("{ .reg .u64 t; cvta.to.shared.u64 t, %1; cvt.u32.u64 %0, t; }" : "=r"(a) : "l"(p));
    return a;
}
__device__ __forceinline__ void ldsm4(uint32_t* r, uint32_t addr) {
    asm volatile("ldmatrix.sync.aligned.m8n8.x4.shared.b16 {%0,%1,%2,%3}, [%4];"
        : "=r"(r[0]), "=r"(r[1]), "=r"(r[2]), "=r"(r[3]) : "r"(addr));
}
__device__ __forceinline__ uint4 lds128(uint32_t a) {
    uint4 v;
    asm volatile("ld.shared.v4.b32 {%0,%1,%2,%3}, [%4];"
        : "=r"(v.x), "=r"(v.y), "=r"(v.z), "=r"(v.w) : "r"(a));
    return v;
}
__device__ __forceinline__ void mma_bf16(float* c, const uint32_t* a, uint32_t b0, uint32_t b1) {
    asm volatile(
        "mma.sync.aligned.m16n8k16.row.col.f32.bf16.bf16.f32 "
        "{%0,%1,%2,%3}, {%4,%5,%6,%7}, {%8,%9}, {%0,%1,%2,%3};"
        : "+f"(c[0]), "+f"(c[1]), "+f"(c[2]), "+f"(c[3])
        : "r"(a[0]), "r"(a[1]), "r"(a[2]), "r"(a[3]), "r"(b0), "r"(b1));
}
__device__ __forceinline__ void mma_f16(float* c, const uint32_t* a, uint32_t b0, uint32_t b1) {
    asm volatile(
        "mma.sync.aligned.m16n8k16.row.col.f32.f16.f16.f32 "
        "{%0,%1,%2,%3}, {%4,%5,%6,%7}, {%8,%9}, {%0,%1,%2,%3};"
        : "+f"(c[0]), "+f"(c[1]), "+f"(c[2]), "+f"(c[3])
        : "r"(a[0]), "r"(a[1]), "r"(a[2]), "r"(a[3]), "r"(b0), "r"(b1));
}
#define CP_ASYNC16(dst, src) \
    asm volatile("cp.async.cg.shared.global [%0], [%1], 16;" \
                 :: "r"(dst), "l"(__cvta_generic_to_global(src)))
#define CP_COMMIT() asm volatile("cp.async.commit_group;" ::: "memory")
#define CP_WAIT1()  asm volatile("cp.async.wait_group 1;" ::: "memory")
#define CP_WAIT0()  asm volatile("cp.async.wait_group 0;" ::: "memory")

__device__ __forceinline__ uint32_t pack_bf_pair(float a, float b, float& ra, float& rb) {
    const __nv_bfloat16 ha = __float2bfloat16(a), hb = __float2bfloat16(b);
    ra = a - __bfloat162float(ha);
    rb = b - __bfloat162float(hb);
    return (uint32_t)__bfloat16_as_ushort(ha) | ((uint32_t)__bfloat16_as_ushort(hb) << 16);
}
__device__ __forceinline__ uint32_t pack_h_pair(float a, float b, float& ra, float& rb) {
    const __half ha = __float2half_rn(a), hb = __float2half_rn(b);
    ra = a - __half2float(ha);
    rb = b - __half2float(hb);
    return (uint32_t)__half_as_ushort(ha) | ((uint32_t)__half_as_ushort(hb) << 16);
}

// ---------------- pack one fragment item ----------------
__device__ __forceinline__ void pack_item(
    const float* __restrict__ W, int ldW, int npairs,
    uint4* __restrict__ dH, uint4* __restrict__ dL, bool f16, int item)
{
    const int lane = item & 31;
    const int gid = lane >> 2, tg = lane & 3;
    const int jp = (item >> 5) % npairs;
    const int s = item / (npairs * 32);
    const int k0 = s * 16 + tg * 2;

    uint32_t h[4], l[4];
#pragma unroll
    for (int half = 0; half < 2; ++half) {
        const int n = (jp * 2 + half) * 8 + gid;
        const float f00 = W[(size_t)k0 * ldW + n];
        const float f01 = W[(size_t)(k0 + 1) * ldW + n];
        const float f10 = W[(size_t)(k0 + 8) * ldW + n];
        const float f11 = W[(size_t)(k0 + 9) * ldW + n];
        float r00, r01, r10, r11, d0, d1;
        if (f16) {
            h[half * 2 + 0] = pack_h_pair(f00, f01, r00, r01);
            h[half * 2 + 1] = pack_h_pair(f10, f11, r10, r11);
            l[half * 2 + 0] = pack_h_pair(r00, r01, d0, d1);
            l[half * 2 + 1] = pack_h_pair(r10, r11, d0, d1);
        } else {
            h[half * 2 + 0] = pack_bf_pair(f00, f01, r00, r01);
            h[half * 2 + 1] = pack_bf_pair(f10, f11, r10, r11);
            l[half * 2 + 0] = pack_bf_pair(r00, r01, d0, d1);
            l[half * 2 + 1] = pack_bf_pair(r10, r11, d0, d1);
        }
    }
    const int dst = (s * npairs + jp) * 32 + lane;
    dH[dst] = make_uint4(h[0], h[1], h[2], h[3]);
    dL[dst] = make_uint4(l[0], l[1], l[2], l[3]);
}

// ---------------- mega pack ----------------
__global__ void mega_pack_kernel(const float* __restrict__ eW1, const float* __restrict__ eW2,
                                 const float* __restrict__ nW1, const float* __restrict__ nW2,
                                 const float* __restrict__ nW3,
                                 const float* __restrict__ eb3, const float* __restrict__ nb1)
{
    const int idx = blockIdx.x * 256 + threadIdx.x;
    if (idx < 8192)        pack_item(eW1,             512, 32, g_eW1aH, g_eW1aL, false, idx);
    else if (idx < 16384)  pack_item(eW1 + 128 * 512, 512, 32, g_eW1bH, g_eW1bL, false, idx - 8192);
    else if (idx < 49152)  pack_item(eW2,             512, 32, g_W2H,   g_W2L,   true,  idx - 16384);
    else if (idx < 57344)  pack_item(nW1,             512, 32, g_nW1aH, g_nW1aL, false, idx - 49152);
    else if (idx < 90112)  pack_item(nW1 + 132 * 512, 512, 32, g_nW1cH, g_nW1cL, false, idx - 57344);
    else if (idx < 122880) pack_item(nW2,             512, 32, g_nW2H,  g_nW2L,  true,  idx - 90112);
    else if (idx < 131072) pack_item(nW3,             128, 8,  g_nW3H,  g_nW3L,  false, idx - 122880);
    else if (idx < 131584) {
        const int n = idx - 131072;
        float acc = 0.f;
#pragma unroll 8
        for (int k = 0; k < 512; ++k)
            acc += eb3[k] * nW1[(size_t)(132 + k) * 512 + n];
        g_bp[n] = nb1[n] + 15.f * acc;
    }
}

__global__ void pack_frag_kernel(const float* __restrict__ W, int npairs,
                                 uint4* __restrict__ dstH, uint4* __restrict__ dstL, int f16)
{
    const int idx = blockIdx.x * 256 + threadIdx.x;
    pack_item(W, npairs * 16, npairs, dstH, dstL, f16 != 0, idx);
}

// ================= generic split HMMA GEMM (reordered MMA issue) =================
template<int PAIRS, bool LN, bool F16>
__global__ void __launch_bounds__(256, 1) mma_gemm_kernel(
    const float* __restrict__ X, int K,
    const uint4* __restrict__ WH, const uint4* __restrict__ WL,
    const float* __restrict__ bias,
    const float* __restrict__ addend, int ldadd,
    const float* __restrict__ actW, const int* __restrict__ action,
    const float* __restrict__ gam, const float* __restrict__ bet,
    float* __restrict__ out, int ldout, int relu)
{
    extern __shared__ __align__(16) char smem[];
    const uint32_t sbase = smem_u32(smem);
    const int tid = threadIdx.x;
    const int bm = blockIdx.x * 64;
    const int NP = 8 * PAIRS;
    const int A_ST = K * 2 + 16;
    const uint32_t offALO = (uint32_t)64 * A_ST;
    const uint32_t offB = F16 ? offALO : 2 * offALO;
    const uint32_t offEpi = offB + (uint32_t)2 * NP * 1024;
    const int kst = K / 16;

    const int kd4 = K >> 2;
    for (int idx = tid; idx < 64 * kd4; idx += 256) {
        const int m = idx / kd4, k4 = (idx - m * kd4) * 4;
        const float4 v = *(const float4*)(X + (size_t)(bm + m) * K + k4);
        const uint32_t off = (uint32_t)m * A_ST + ((uint32_t)k4 << 1);
        float rx, ry, rz, rw, d0, d1;
        uint2 hh;
        if (F16) {
            hh.x = pack_h_pair(v.x, v.y, rx, ry);
            hh.y = pack_h_pair(v.z, v.w, rz, rw);
            *(uint2*)(smem + off) = hh;
        } else {
            uint2 ll;
            hh.x = pack_bf_pair(v.x, v.y, rx, ry);
            hh.y = pack_bf_pair(v.z, v.w, rz, rw);
            ll.x = pack_bf_pair(rx, ry, d0, d1);
            ll.y = pack_bf_pair(rz, rw, d0, d1);
            *(uint2*)(smem + off) = hh;
            *(uint2*)(smem + offALO + off) = ll;
        }
    }
    __syncthreads();

    const int w = tid >> 5, lane = tid & 31;
    const int gid = lane >> 2, tg = lane & 3;
    const int lrow = (lane & 8) + (lane & 7);
    const uint32_t a_base = sbase + (uint32_t)lrow * A_ST + ((lane & 16) ? 16u : 0u);

    float acc[4][2 * PAIRS][4];
#pragma unroll
    for (int mt = 0; mt < 4; ++mt)
#pragma unroll
        for (int nt = 0; nt < 2 * PAIRS; ++nt)
#pragma unroll
            for (int j = 0; j < 4; ++j) acc[mt][nt][j] = 0.f;

    auto stageB = [&](int stage, int s) {
#pragma unroll
        for (int p = 0; p < PAIRS; ++p) {
            const int jpg = w * PAIRS + p;
            const uint32_t d = sbase + offB +
                ((uint32_t)((stage * NP + jpg) * 2) * 32 + lane) * 16;
            CP_ASYNC16(d, WH + ((size_t)(s * NP + jpg) * 32 + lane));
            CP_ASYNC16(d + 512, WL + ((size_t)(s * NP + jpg) * 32 + lane));
        }
    };

    stageB(0, 0); CP_COMMIT();

    for (int s = 0; s < kst; ++s) {
        const int cur = s & 1;
        if (s < kst - 1) { stageB(cur ^ 1, s + 1); CP_COMMIT(); CP_WAIT1(); }
        else CP_WAIT0();

        uint4 vh[PAIRS], vl[PAIRS];
#pragma unroll
        for (int p = 0; p < PAIRS; ++p) {
            const uint32_t aH = sbase + offB +
                ((uint32_t)((cur * NP + w * PAIRS + p) * 2) * 32 + lane) * 16;
            vh[p] = lds128(aH);
            vl[p] = lds128(aH + 512);
        }
        uint32_t ah[4][4], al[4][4];
#pragma unroll
        for (int mt = 0; mt < 4; ++mt) {
            const uint32_t aoff = (uint32_t)mt * 16 * A_ST + (uint32_t)s * 32;
            ldsm4(ah[mt], a_base + aoff);
            if (!F16) ldsm4(al[mt], a_base + offALO + aoff);
        }
        // hi pass: all accumulators independent
#pragma unroll
        for (int mt = 0; mt < 4; ++mt)
#pragma unroll
            for (int p = 0; p < PAIRS; ++p) {
                if (F16) {
                    mma_f16(acc[mt][2 * p],     ah[mt], vh[p].x, vh[p].y);
                    mma_f16(acc[mt][2 * p + 1], ah[mt], vh[p].z, vh[p].w);
                } else {
                    mma_bf16(acc[mt][2 * p],     ah[mt], vh[p].x, vh[p].y);
                    mma_bf16(acc[mt][2 * p + 1], ah[mt], vh[p].z, vh[p].w);
                }
            }
        // lo pass
#pragma unroll
        for (int mt = 0; mt < 4; ++mt)
#pragma unroll
            for (int p = 0; p < PAIRS; ++p) {
                if (F16) {
                    mma_f16(acc[mt][2 * p],     ah[mt], vl[p].x, vl[p].y);
                    mma_f16(acc[mt][2 * p + 1], ah[mt], vl[p].z, vl[p].w);
                } else {
                    mma_bf16(acc[mt][2 * p],     ah[mt], vl[p].x, vl[p].y);
                    mma_bf16(acc[mt][2 * p + 1], ah[mt], vl[p].z, vl[p].w);
                }
            }
        // al pass (bf16 3-term only)
        if (!F16) {
#pragma unroll
            for (int mt = 0; mt < 4; ++mt)
#pragma unroll
                for (int p = 0; p < PAIRS; ++p) {
                    mma_bf16(acc[mt][2 * p],     al[mt], vh[p].x, vh[p].y);
                    mma_bf16(acc[mt][2 * p + 1], al[mt], vh[p].z, vh[p].w);
                }
        }
    }

    // ---- epilogue ----
    const int colb = w * (16 * PAIRS) + tg * 2;
    float* ps  = (float*)(smem + offEpi);
    float* pq  = ps + 512;
    float* mus = pq + 512;
    float* rss = mus + 64;

#pragma unroll
    for (int mt = 0; mt < 4; ++mt) {
        const int r0 = bm + mt * 16 + gid;
        const int r1 = r0 + 8;
        int t0 = 5, t1 = 5;
        if (actW) {
            const int a = action[r0 >> 4];
            t0 = a - 4 * (r0 & 15);
            t1 = a - 4 * (r1 & 15);
        }
#pragma unroll
        for (int nt = 0; nt < 2 * PAIRS; ++nt) {
            const int col = colb + nt * 8;
            float b0 = 0.f, b1 = 0.f;
            if (bias) { b0 = __ldg(bias + col); b1 = __ldg(bias + col + 1); }
            float v00 = acc[mt][nt][0] + b0, v01 = acc[mt][nt][1] + b1;
            float v10 = acc[mt][nt][2] + b0, v11 = acc[mt][nt][3] + b1;
            if (addend) {
                const float2 a0 = *(const float2*)(addend + (size_t)r0 * ldadd + col);
                const float2 a1 = *(const float2*)(addend + (size_t)r1 * ldadd + col);
                v00 += a0.x; v01 += a0.y; v10 += a1.x; v11 += a1.y;
            }
            if (actW) {
                if ((unsigned)t0 < 4u) {
                    v00 += __ldg(actW + (size_t)t0 * 512 + col);
                    v01 += __ldg(actW + (size_t)t0 * 512 + col + 1);
                }
                if ((unsigned)t1 < 4u) {
                    v10 += __ldg(actW + (size_t)t1 * 512 + col);
                    v11 += __ldg(actW + (size_t)t1 * 512 + col + 1);
                }
            }
            acc[mt][nt][0] = v00; acc[mt][nt][1] = v01;
            acc[mt][nt][2] = v10; acc[mt][nt][3] = v11;
        }
    }

    if (LN) {
#pragma unroll
        for (int mt = 0; mt < 4; ++mt) {
            float s0 = 0.f, q0 = 0.f, s1 = 0.f, q1 = 0.f;
#pragma unroll
            for (int nt = 0; nt < 2 * PAIRS; ++nt) {
                s0 += acc[mt][nt][0] + acc[mt][nt][1];
                q0 += acc[mt][nt][0] * acc[mt][nt][0] + acc[mt][nt][1] * acc[mt][nt][1];
                s1 += acc[mt][nt][2] + acc[mt][nt][3];
                q1 += acc[mt][nt][2] * acc[mt][nt][2] + acc[mt][nt][3] * acc[mt][nt][3];
            }
#pragma unroll
            for (int off = 1; off <= 2; off <<= 1) {
                s0 += __shfl_xor_sync(0xffffffffu, s0, off);
                q0 += __shfl_xor_sync(0xffffffffu, q0, off);
                s1 += __shfl_xor_sync(0xffffffffu, s1, off);
                q1 += __shfl_xor_sync(0xffffffffu, q1, off);
            }
            if (tg == 0) {
                ps[(mt * 16 + gid) * 8 + w] = s0;     pq[(mt * 16 + gid) * 8 + w] = q0;
                ps[(mt * 16 + 8 + gid) * 8 + w] = s1; pq[(mt * 16 + 8 + gid) * 8 + w] = q1;
            }
        }
        __syncthreads();
        if (tid < 64) {
            float s = 0.f, q = 0.f;
#pragma unroll
            for (int ww = 0; ww < 8; ++ww) { s += ps[tid * 8 + ww]; q += pq[tid * 8 + ww]; }
            const float mu = s * (1.f / 512.f);
            mus[tid] = mu;
            rss[tid] = rsqrtf(q * (1.f / 512.f) - mu * mu + LN_EPS);
        }
        __syncthreads();
#pragma unroll
        for (int mt = 0; mt < 4; ++mt) {
            const int r0 = bm + mt * 16 + gid, r1 = r0 + 8;
            const float mu0 = mus[mt * 16 + gid],     rv0 = rss[mt * 16 + gid];
            const float mu1 = mus[mt * 16 + 8 + gid], rv1 = rss[mt * 16 + 8 + gid];
#pragma unroll
            for (int nt = 0; nt < 2 * PAIRS; ++nt) {
                const int col = colb + nt * 8;
                const float g0 = __ldg(gam + col), g1 = __ldg(gam + col + 1);
                const float be0 = __ldg(bet + col), be1 = __ldg(bet + col + 1);
                float v00 = (acc[mt][nt][0] - mu0) * rv0 * g0 + be0;
                float v01 = (acc[mt][nt][1] - mu0) * rv0 * g1 + be1;
                float v10 = (acc[mt][nt][2] - mu1) * rv1 * g0 + be0;
                float v11 = (acc[mt][nt][3] - mu1) * rv1 * g1 + be1;
                if (relu) {
                    v00 = fmaxf(v00, 0.f); v01 = fmaxf(v01, 0.f);
                    v10 = fmaxf(v10, 0.f); v11 = fmaxf(v11, 0.f);
                }
                *(float2*)(out + (size_t)r0 * ldout + col) = make_float2(v00, v01);
                *(float2*)(out + (size_t)r1 * ldout + col) = make_float2(v10, v11);
            }
        }
    } else {
#pragma unroll
        for (int mt = 0; mt < 4; ++mt) {
            const int r0 = bm + mt * 16 + gid, r1 = r0 + 8;
#pragma unroll
            for (int nt = 0; nt < 2 * PAIRS; ++nt) {
                const int col = colb + nt * 8;
                float v00 = acc[mt][nt][0], v01 = acc[mt][nt][1];
                float v10 = acc[mt][nt][2], v11 = acc[mt][nt][3];
                if (relu) {
                    v00 = fmaxf(v00, 0.f); v01 = fmaxf(v01, 0.f);
                    v10 = fmaxf(v10, 0.f); v11 = fmaxf(v11, 0.f);
                }
                *(float2*)(out + (size_t)r0 * ldout + col) = make_float2(v00, v01);
                *(float2*)(out + (size_t)r1 * ldout + col) = make_float2(v10, v11);
            }
        }
    }
}

// ================= fused P/Q/T kernel (K=128, bf16 3-term, 3 phases) =================
__global__ void __launch_bounds__(256, 1) pqt_kernel(
    const float* __restrict__ X, const float* __restrict__ actW,
    const int* __restrict__ action)
{
    extern __shared__ __align__(16) char smem[];
    const uint32_t sbase = smem_u32(smem);
    const int tid = threadIdx.x;
    const int bm = blockIdx.x * 64;
    const int A_ST = 128 * 2 + 16;               // 272
    const uint32_t offALO = 64 * 272;            // 17408
    const uint32_t offB = 2 * offALO;            // 34816

    // build A (states, K=128) hi/lo
    for (int idx = tid; idx < 64 * 32; idx += 256) {
        const int m = idx >> 5, k4 = (idx & 31) << 2;
        const float4 v = *(const float4*)(X + (size_t)(bm + m) * 128 + k4);
        float rx, ry, rz, rw, d0, d1;
        uint2 hh, ll;
        hh.x = pack_bf_pair(v.x, v.y, rx, ry);
        hh.y = pack_bf_pair(v.z, v.w, rz, rw);
        ll.x = pack_bf_pair(rx, ry, d0, d1);
        ll.y = pack_bf_pair(rz, rw, d0, d1);
        const uint32_t off = (uint32_t)m * A_ST + ((uint32_t)k4 << 1);
        *(uint2*)(smem + off) = hh;
        *(uint2*)(smem + offALO + off) = ll;
    }
    __syncthreads();

    const int w = tid >> 5, lane = tid & 31;
    const int gid = lane >> 2, tg = lane & 3;
    const int lrow = (lane & 8) + (lane & 7);
    const uint32_t a_base = sbase + (uint32_t)lrow * A_ST + ((lane & 16) ? 16u : 0u);
    const int colb = w * 64 + tg * 2;

    const uint4* WHs[3]; const uint4* WLs[3];
    WHs[0] = g_eW1aH; WLs[0] = g_eW1aL;
    WHs[1] = g_eW1bH; WLs[1] = g_eW1bL;
    WHs[2] = g_nW1aH; WLs[2] = g_nW1aL;

    for (int ph = 0; ph < 3; ++ph) {
        const uint4* WH = WHs[ph];
        const uint4* WL = WLs[ph];

        float acc[4][8][4];
#pragma unroll
        for (int mt = 0; mt < 4; ++mt)
#pragma unroll
            for (int nt = 0; nt < 8; ++nt)
#pragma unroll
                for (int j = 0; j < 4; ++j) acc[mt][nt][j] = 0.f;

        auto stageB = [&](int stage, int s) {
#pragma unroll
            for (int p = 0; p < 4; ++p) {
                const int jpg = w * 4 + p;
                const uint32_t d = sbase + offB +
                    ((uint32_t)((stage * 32 + jpg) * 2) * 32 + lane) * 16;
                CP_ASYNC16(d, WH + ((size_t)(s * 32 + jpg) * 32 + lane));
                CP_ASYNC16(d + 512, WL + ((size_t)(s * 32 + jpg) * 32 + lane));
            }
        };

        stageB(0, 0); CP_COMMIT();
        for (int s = 0; s < 8; ++s) {
            const int cur = s & 1;
            if (s < 7) { stageB(cur ^ 1, s + 1); CP_COMMIT(); CP_WAIT1(); }
            else CP_WAIT0();

            uint4 vh[4], vl[4];
#pragma unroll
            for (int p = 0; p < 4; ++p) {
                const uint32_t aH = sbase + offB +
                    ((uint32_t)((cur * 32 + w * 4 + p) * 2) * 32 + lane) * 16;
                vh[p] = lds128(aH);
                vl[p] = lds128(aH + 512);
            }
            uint32_t ah[4][4], al[4][4];
#pragma unroll
            for (int mt = 0; mt < 4; ++mt) {
                const uint32_t aoff = (uint32_t)mt * 16 * A_ST + (uint32_t)s * 32;
                ldsm4(ah[mt], a_base + aoff);
                ldsm4(al[mt], a_base + offALO + aoff);
            }
#pragma unroll
            for (int mt = 0; mt < 4; ++mt)
#pragma unroll
                for (int p = 0; p < 4; ++p) {
                    mma_bf16(acc[mt][2 * p],     ah[mt], vh[p].x, vh[p].y);
                    mma_bf16(acc[mt][2 * p + 1], ah[mt], vh[p].z, vh[p].w);
                }
#pragma unroll
            for (int mt = 0; mt < 4; ++mt)
#pragma unroll
                for (int p = 0; p < 4; ++p) {
                    mma_bf16(acc[mt][2 * p],     ah[mt], vl[p].x, vl[p].y);
                    mma_bf16(acc[mt][2 * p + 1], ah[mt], vl[p].z, vl[p].w);
                }
#pragma unroll
            for (int mt = 0; mt < 4; ++mt)
#pragma unroll
                for (int p = 0; p < 4; ++p) {
                    mma_bf16(acc[mt][2 * p],     al[mt], vh[p].x, vh[p].y);
                    mma_bf16(acc[mt][2 * p + 1], al[mt], vh[p].z, vh[p].w);
                }
        }

        // phase epilogue
#pragma unroll
        for (int mt = 0; mt < 4; ++mt) {
            const int r0 = bm + mt * 16 + gid, r1 = r0 + 8;
#pragma unroll
            for (int nt = 0; nt < 8; ++nt) {
                const int col = colb + nt * 8;
                float v00 = acc[mt][nt][0], v01 = acc[mt][nt][1];
                float v10 = acc[mt][nt][2], v11 = acc[mt][nt][3];
                if (ph == 2) {
                    const float b0 = g_bp[col], b1 = g_bp[col + 1];
                    v00 += b0; v01 += b1; v10 += b0; v11 += b1;
                    const int a = action[r0 >> 4];
                    const int t0 = a - 4 * (r0 & 15);
                    const int t1 = a - 4 * (r1 & 15);
                    if ((unsigned)t0 < 4u) {
                        v00 += __ldg(actW + (size_t)t0 * 512 + col);
                        v01 += __ldg(actW + (size_t)t0 * 512 + col + 1);
                    }
                    if ((unsigned)t1 < 4u) {
                        v10 += __ldg(actW + (size_t)t1 * 512 + col);
                        v11 += __ldg(actW + (size_t)t1 * 512 + col + 1);
                    }
                    *(float2*)&g_T[(size_t)r0 * 512 + col] = make_float2(v00, v01);
                    *(float2*)&g_T[(size_t)r1 * 512 + col] = make_float2(v10, v11);
                } else {
                    const int co = (ph == 1) ? 512 : 0;
                    *(float2*)&g_PQ[(size_t)r0 * 1024 + co + col] = make_float2(v00, v01);
                    *(float2*)&g_PQ[(size_t)r1 * 1024 + co + col] = make_float2(v10, v11);
                }
            }
        }
    }
}

// ---------------- edge kernel: fp16 2-term, reordered ----------------
#define A_STRIDE 1040
#define OFF_AHI   0
#define OFF_BBUF  66560
#define OFF_B2    132096
#define OFF_GS    134144
#define OFF_BSS   136192
#define OFF_PS    138240
#define OFF_PQS   140288
#define OFF_MU    142336
#define OFF_RS    142592
#define SMEM_EDGE 142848

__device__ __forceinline__ void stage_B_edge(uint32_t sbase, int stage, int s, int w, int lane)
{
#pragma unroll
    for (int p = 0; p < 4; ++p) {
        const int jpg = w * 4 + p;
        const uint32_t dH = sbase + OFF_BBUF +
            ((uint32_t)((stage * 32 + jpg) * 2) * 32 + lane) * 16;
        CP_ASYNC16(dH, g_W2H + ((size_t)(s * 32 + jpg) * 32 + lane));
        CP_ASYNC16(dH + 512, g_W2L + ((size_t)(s * 32 + jpg) * 32 + lane));
    }
}

__global__ void __launch_bounds__(256, 1) edge_mma_kernel(
    const float* __restrict__ eb1, const float* __restrict__ b2,
    const float* __restrict__ gam, const float* __restrict__ bet)
{
    extern __shared__ __align__(16) char smem[];
    const uint32_t sbase = smem_u32(smem);
    const int tid = threadIdx.x;
    const int nb = blockIdx.x;
    const int node_base = nb * 4;
    const int b16 = (nb >> 2) << 4;
    const int o0 = (nb & 3) * 4;

    float* b2s = (float*)(smem + OFF_B2);
    float* gss = (float*)(smem + OFF_GS);
    float* bss = (float*)(smem + OFF_BSS);
    float* ps  = (float*)(smem + OFF_PS);
    float* pq  = (float*)(smem + OFF_PQS);
    float* mus = (float*)(smem + OFF_MU);
    float* rss = (float*)(smem + OFF_RS);

    for (int i = tid; i < 512; i += 256) {
        b2s[i] = b2[i]; gss[i] = gam[i]; bss[i] = bet[i];
    }

    const float4* eb1v = (const float4*)eb1;
#pragma unroll
    for (int i = 0; i < 32; ++i) {
        const int idx = tid + (i << 8);
        const int m = idx >> 7;
        const int k4 = (idx & 127) << 2;
        const int ln = m >> 4, r = m & 15;
        float4 v = make_float4(0.f, 0.f, 0.f, 0.f);
        if (r < 15) {
            const int o = o0 + ln;
            const int jj = r + (r >= o);
            const float4 p4 = *(const float4*)&g_PQ[(size_t)(node_base + ln) * 1024 + k4];
            const float4 q4 = *(const float4*)&g_PQ[(size_t)(b16 + jj) * 1024 + 512 + k4];
            const float4 bb = __ldg(&eb1v[k4 >> 2]);
            v.x = fmaxf(p4.x + q4.x + bb.x, 0.f);
            v.y = fmaxf(p4.y + q4.y + bb.y, 0.f);
            v.z = fmaxf(p4.z + q4.z + bb.z, 0.f);
            v.w = fmaxf(p4.w + q4.w + bb.w, 0.f);
        }
        float rx, ry, rz, rw;
        uint2 hh;
        hh.x = pack_h_pair(v.x, v.y, rx, ry);
        hh.y = pack_h_pair(v.z, v.w, rz, rw);
        *(uint2*)(smem + OFF_AHI + (uint32_t)m * A_STRIDE + ((uint32_t)k4 << 1)) = hh;
    }
    __syncthreads();

    const int w = tid >> 5, lane = tid & 31;
    const int gid = lane >> 2, tg = lane & 3;
    const int lrow = (lane & 8) + (lane & 7);
    const uint32_t a_base = sbase + OFF_AHI + (uint32_t)lrow * A_STRIDE + ((lane & 16) ? 16u : 0u);

    float acc[4][8][4];
#pragma unroll
    for (int mt = 0; mt < 4; ++mt)
#pragma unroll
        for (int nt = 0; nt < 8; ++nt)
#pragma unroll
            for (int j = 0; j < 4; ++j) acc[mt][nt][j] = 0.f;

    stage_B_edge(sbase, 0, 0, w, lane);
    CP_COMMIT();

    for (int s = 0; s < 32; ++s) {
        const int cur = s & 1;
        if (s < 31) { stage_B_edge(sbase, cur ^ 1, s + 1, w, lane); CP_COMMIT(); CP_WAIT1(); }
        else CP_WAIT0();

        uint4 vh[4], vl[4];
#pragma unroll
        for (int p = 0; p < 4; ++p) {
            const uint32_t aH = sbase + OFF_BBUF +
                ((uint32_t)((cur * 32 + w * 4 + p) * 2) * 32 + lane) * 16;
            vh[p] = lds128(aH);
            vl[p] = lds128(aH + 512);
        }
        uint32_t ah[4][4];
#pragma unroll
        for (int mt = 0; mt < 4; ++mt)
            ldsm4(ah[mt], a_base + (uint32_t)mt * (16 * A_STRIDE) + (uint32_t)s * 32);
        // hi pass (32 independent MMAs)
#pragma unroll
        for (int mt = 0; mt < 4; ++mt)
#pragma unroll
            for (int p = 0; p < 4; ++p) {
                mma_f16(acc[mt][2 * p],     ah[mt], vh[p].x, vh[p].y);
                mma_f16(acc[mt][2 * p + 1], ah[mt], vh[p].z, vh[p].w);
            }
        // lo pass
#pragma unroll
        for (int mt = 0; mt < 4; ++mt)
#pragma unroll
            for (int p = 0; p < 4; ++p) {
                mma_f16(acc[mt][2 * p],     ah[mt], vl[p].x, vl[p].y);
                mma_f16(acc[mt][2 * p + 1], ah[mt], vl[p].z, vl[p].w);
            }
    }

    const int colb = w * 64 + tg * 2;
    float b2v[8][2];
#pragma unroll
    for (int nt = 0; nt < 8; ++nt) {
        b2v[nt][0] = b2s[colb + nt * 8];
        b2v[nt][1] = b2s[colb + nt * 8 + 1];
    }
#pragma unroll
    for (int mt = 0; mt < 4; ++mt) {
        float s0 = 0.f, q0 = 0.f, s1 = 0.f, q1 = 0.f;
#pragma unroll
        for (int nt = 0; nt < 8; ++nt) {
            const float v00 = acc[mt][nt][0] + b2v[nt][0];
            const float v01 = acc[mt][nt][1] + b2v[nt][1];
            const float v10 = acc[mt][nt][2] + b2v[nt][0];
            const float v11 = acc[mt][nt][3] + b2v[nt][1];
            acc[mt][nt][0] = v00; acc[mt][nt][1] = v01;
            acc[mt][nt][2] = v10; acc[mt][nt][3] = v11;
            s0 += v00 + v01; q0 += v00 * v00 + v01 * v01;
            s1 += v10 + v11; q1 += v10 * v10 + v11 * v11;
        }
#pragma unroll
        for (int off = 1; off <= 2; off <<= 1) {
            s0 += __shfl_xor_sync(0xffffffffu, s0, off);
            q0 += __shfl_xor_sync(0xffffffffu, q0, off);
            s1 += __shfl_xor_sync(0xffffffffu, s1, off);
            q1 += __shfl_xor_sync(0xffffffffu, q1, off);
        }
        if (tg == 0) {
            ps[(mt * 16 + gid) * 8 + w] = s0;     pq[(mt * 16 + gid) * 8 + w] = q0;
            ps[(mt * 16 + 8 + gid) * 8 + w] = s1; pq[(mt * 16 + 8 + gid) * 8 + w] = q1;
        }
    }
    __syncthreads();
    if (tid < 64) {
        float s = 0.f, q = 0.f;
#pragma unroll
        for (int ww = 0; ww < 8; ++ww) { s += ps[tid * 8 + ww]; q += pq[tid * 8 + ww]; }
        const float mu = s * (1.f / 512.f);
        mus[tid] = mu;
        rss[tid] = rsqrtf(q * (1.f / 512.f) - mu * mu + LN_EPS);
    }
    __syncthreads();

    float gv[8][2], bv[8][2];
#pragma unroll
    for (int nt = 0; nt < 8; ++nt) {
        gv[nt][0] = gss[colb + nt * 8];     gv[nt][1] = gss[colb + nt * 8 + 1];
        bv[nt][0] = bss[colb + nt * 8];     bv[nt][1] = bss[colb + nt * 8 + 1];
    }
#pragma unroll
    for (int mt = 0; mt < 4; ++mt) {
        const float mu0 = mus[mt * 16 + gid],     r0 = rss[mt * 16 + gid];
        const float mu1 = mus[mt * 16 + 8 + gid], r1 = rss[mt * 16 + 8 + gid];
        const bool last = (gid == 7);
#pragma unroll
        for (int nt = 0; nt < 8; ++nt) {
            const float v00 = fmaxf((acc[mt][nt][0] - mu0) * r0 * gv[nt][0] + bv[nt][0], 0.f);
            const float v01 = fmaxf((acc[mt][nt][1] - mu0) * r0 * gv[nt][1] + bv[nt][1], 0.f);
            const float v10 = last ? 0.f : fmaxf((acc[mt][nt][2] - mu1) * r1 * gv[nt][0] + bv[nt][0], 0.f);
            const float v11 = last ? 0.f : fmaxf((acc[mt][nt][3] - mu1) * r1 * gv[nt][1] + bv[nt][1], 0.f);
            float t0 = v00 + v10, t1 = v01 + v11;
#pragma unroll
            for (int off = 4; off <= 16; off <<= 1) {
                t0 += __shfl_xor_sync(0xffffffffu, t0, off);
                t1 += __shfl_xor_sync(0xffffffffu, t1, off);
            }
            if (lane < 4)
                *(float2*)&g_S[(size_t)(node_base + mt) * 512 + colb + nt * 8] =
                    make_float2(t0, t1);
        }
    }
}

// ---------------- launch ----------------
static inline int smem_for(int K, int PAIRS) {
    return 128 * (2 * K + 16) + PAIRS * 16384 + 5120;
}
#define SMEM_PQT (2 * 64 * 272 + 65536 + 1024)

extern "C" void kernel_launch(void* const* d_in, const int* in_sizes, int n_in,
                              void* d_out, int out_size)
{
    const float* states = (const float*)d_in[0];
    const int*   action = (const int*)d_in[1];
    const float* eW1 = (const float*)d_in[2];
    const float* eb1 = (const float*)d_in[3];
    const float* eW2 = (const float*)d_in[4];
    const float* eb2 = (const float*)d_in[5];
    const float* eg  = (const float*)d_in[6];
    const float* ebt = (const float*)d_in[7];
    const float* eW3 = (const float*)d_in[8];
    const float* eb3 = (const float*)d_in[9];
    const float* nW1 = (const float*)d_in[10];
    const float* nb1 = (const float*)d_in[11];
    const float* nW2 = (const float*)d_in[12];
    const float* nb2 = (const float*)d_in[13];
    const float* ng  = (const float*)d_in[14];
    const float* nbt = (const float*)d_in[15];
    const float* nW3 = (const float*)d_in[16];
    const float* nb3 = (const float*)d_in[17];
    float* out = (float*)d_out;

    float *pS, *pT, *pH1, *pH2;
    cudaGetSymbolAddress((void**)&pS,  g_S);
    cudaGetSymbolAddress((void**)&pT,  g_T);
    cudaGetSymbolAddress((void**)&pH1, g_H1);
    cudaGetSymbolAddress((void**)&pH2, g_H2);

    uint4 *nW2H, *nW2L, *nW3H, *nW3L, *WcH, *WcL, *nW1cH, *nW1cL;
    cudaGetSymbolAddress((void**)&nW1cH, g_nW1cH); cudaGetSymbolAddress((void**)&nW1cL, g_nW1cL);
    cudaGetSymbolAddress((void**)&nW2H,  g_nW2H);  cudaGetSymbolAddress((void**)&nW2L,  g_nW2L);
    cudaGetSymbolAddress((void**)&nW3H,  g_nW3H);  cudaGetSymbolAddress((void**)&nW3L,  g_nW3L);
    cudaGetSymbolAddress((void**)&WcH,   g_WcH);   cudaGetSymbolAddress((void**)&WcL,   g_WcL);

    static int configured = 0;
    if (!configured) {
        cudaFuncSetAttribute(edge_mma_kernel,
                             cudaFuncAttributeMaxDynamicSharedMemorySize, SMEM_EDGE);
        cudaFuncSetAttribute(pqt_kernel,
                             cudaFuncAttributeMaxDynamicSharedMemorySize, SMEM_PQT);
        cudaFuncSetAttribute(mma_gemm_kernel<4, false, false>,
                             cudaFuncAttributeMaxDynamicSharedMemorySize, smem_for(512, 4));
        cudaFuncSetAttribute(mma_gemm_kernel<4, false, true>,
                             cudaFuncAttributeMaxDynamicSharedMemorySize, smem_for(512, 4));
        cudaFuncSetAttribute(mma_gemm_kernel<4, true, true>,
                             cudaFuncAttributeMaxDynamicSharedMemorySize, smem_for(512, 4));
        cudaFuncSetAttribute(mma_gemm_kernel<1, false, false>,
                             cudaFuncAttributeMaxDynamicSharedMemorySize, smem_for(512, 1));
        configured = 1;
    }

    const int S512 = smem_for(512, 4);
    const int SOUT = smem_for(512, 1);

    // 1) pack all weights + bprime
    mega_pack_kernel<<<514, 256>>>(eW1, eW2, nW1, nW2, nW3, eb3, nb1);

    // 2) Wcomb = eW3 @ nW1c (bf16 3-term -> g_H1 temp) then pack to fp16
    mma_gemm_kernel<4, false, false><<<8, 256, S512>>>(
        eW3, 512, nW1cH, nW1cL, nullptr, nullptr, 0,
        nullptr, nullptr, nullptr, nullptr, pH1, 512, 0);
    pack_frag_kernel<<<128, 256>>>(pH1, 32, WcH, WcL, 1);

    // 3) fused P/Q/T (one launch, shared A)
    pqt_kernel<<<NNODE / 64, 256, SMEM_PQT>>>(states, nW1 + 128 * 512, action);

    // 4) fused edge layer (fp16 2-term) -> S
    edge_mma_kernel<<<NNODE / 4, 256, SMEM_EDGE>>>(eb1, eb2, eg, ebt);

    // 5) H1 = relu(S@Wcomb + T) (fp16 2-term)
    mma_gemm_kernel<4, false, true><<<NNODE / 64, 256, S512>>>(
        pS, 512, WcH, WcL, nullptr, pT, 512,
        nullptr, nullptr, nullptr, nullptr, pH1, 512, 1);

    // 6) H2 = relu(LN(H1@nW2 + nb2)) (fp16 2-term)
    mma_gemm_kernel<4, true, true><<<NNODE / 64, 256, S512>>>(
        pH1, 512, nW2H, nW2L, nb2, nullptr, 0,
        nullptr, nullptr, ng, nbt, pH2, 512, 1);

    // 7) out = H2@nW3 + nb3 (bf16 3-term)
    mma_gemm_kernel<1, false, false><<<NNODE / 64, 256, SOUT>>>(
        pH2, 512, nW3H, nW3L, nb3, nullptr, 0,
        nullptr, nullptr, nullptr, nullptr, out, 128, 0);
}

// round 8
// speedup vs baseline: 6.3707x; 1.0298x over previous
#include <cuda_runtime.h>
#include <cuda_bf16.h>
#include <cuda_fp16.h>
#include <math.h>
#include <stdint.h>

#define BB    512
#define OO    16
#define OBS   128
#define HH    512
#define NNODE (BB*OO)
#define LN_EPS 1e-5f

// ---------------- scratch ----------------
__device__ __align__(16) float g_PQ[(size_t)NNODE * 1024];
__device__ __align__(16) float g_S [(size_t)NNODE * HH];
__device__ __align__(16) float g_T [(size_t)NNODE * HH];
__device__ __align__(16) float g_H1[(size_t)NNODE * HH];   // Wcomb fp32 temp
__device__ __align__(16) float g_bp[512];

// fragment-packed weights
__device__ __align__(16) uint4 g_eW1aH[8192],  g_eW1aL[8192];    // bf16
__device__ __align__(16) uint4 g_eW1bH[8192],  g_eW1bL[8192];    // bf16
__device__ __align__(16) uint4 g_W2H[32768],   g_W2L[32768];     // fp16 (edge)
__device__ __align__(16) uint4 g_nW1aH[8192],  g_nW1aL[8192];    // bf16
__device__ __align__(16) uint4 g_nW1cH[32768], g_nW1cL[32768];   // bf16
__device__ __align__(16) uint4 g_nW2H[32768],  g_nW2L[32768];    // fp16
__device__ __align__(16) uint4 g_nW3H[8192],   g_nW3L[8192];     // fp16
__device__ __align__(16) uint4 g_WcH[32768],   g_WcL[32768];     // fp16

// ---------------- helpers ----------------
__device__ __forceinline__ uint32_t smem_u32(const void* p) {
    uint32_t a;
    asm("{ .reg .u64 t; cvta.to.shared.u64 t, %1; cvt.u32.u64 %0, t; }" : "=r"(a) : "l"(p));
    return a;
}
__device__ __forceinline__ void ldsm4(uint32_t* r, uint32_t addr) {
    asm volatile("ldmatrix.sync.aligned.m8n8.x4.shared.b16 {%0,%1,%2,%3}, [%4];"
        : "=r"(r[0]), "=r"(r[1]), "=r"(r[2]), "=r"(r[3]) : "r"(addr));
}
__device__ __forceinline__ uint4 lds128(uint32_t a) {
    uint4 v;
    asm volatile("ld.shared.v4.b32 {%0,%1,%2,%3}, [%4];"
        : "=r"(v.x), "=r"(v.y), "=r"(v.z), "=r"(v.w) : "r"(a));
    return v;
}
__device__ __forceinline__ void mma_bf16(float* c, const uint32_t* a, uint32_t b0, uint32_t b1) {
    asm volatile(
        "mma.sync.aligned.m16n8k16.row.col.f32.bf16.bf16.f32 "
        "{%0,%1,%2,%3}, {%4,%5,%6,%7}, {%8,%9}, {%0,%1,%2,%3};"
        : "+f"(c[0]), "+f"(c[1]), "+f"(c[2]), "+f"(c[3])
        : "r"(a[0]), "r"(a[1]), "r"(a[2]), "r"(a[3]), "r"(b0), "r"(b1));
}
__device__ __forceinline__ void mma_f16(float* c, const uint32_t* a, uint32_t b0, uint32_t b1) {
    asm volatile(
        "mma.sync.aligned.m16n8k16.row.col.f32.f16.f16.f32 "
        "{%0,%1,%2,%3}, {%4,%5,%6,%7}, {%8,%9}, {%0,%1,%2,%3};"
        : "+f"(c[0]), "+f"(c[1]), "+f"(c[2]), "+f"(c[3])
        : "r"(a[0]), "r"(a[1]), "r"(a[2]), "r"(a[3]), "r"(b0), "r"(b1));
}
#define CP_ASYNC16(dst, src) \
    asm volatile("cp.async.cg.shared.global [%0], [%1], 16;" \
                 :: "r"(dst), "l"(__cvta_generic_to_global(src)))
#define CP_COMMIT() asm volatile("cp.async.commit_group;" ::: "memory")
#define CP_WAIT0()  asm volatile("cp.async.wait_group 0;" ::: "memory")
#define CP_WAIT1()  asm volatile("cp.async.wait_group 1;" ::: "memory")
#define CP_WAIT2()  asm volatile("cp.async.wait_group 2;" ::: "memory")
#define CP_WAIT3()  asm volatile("cp.async.wait_group 3;" ::: "memory")

__device__ __forceinline__ uint32_t pack_bf_pair(float a, float b, float& ra, float& rb) {
    const __nv_bfloat16 ha = __float2bfloat16(a), hb = __float2bfloat16(b);
    ra = a - __bfloat162float(ha);
    rb = b - __bfloat162float(hb);
    return (uint32_t)__bfloat16_as_ushort(ha) | ((uint32_t)__bfloat16_as_ushort(hb) << 16);
}
__device__ __forceinline__ uint32_t pack_h_pair(float a, float b, float& ra, float& rb) {
    const __half ha = __float2half_rn(a), hb = __float2half_rn(b);
    ra = a - __half2float(ha);
    rb = b - __half2float(hb);
    return (uint32_t)__half_as_ushort(ha) | ((uint32_t)__half_as_ushort(hb) << 16);
}

// ---------------- pack one fragment item ----------------
__device__ __forceinline__ void pack_item(
    const float* __restrict__ W, int ldW, int npairs,
    uint4* __restrict__ dH, uint4* __restrict__ dL, bool f16, int item)
{
    const int lane = item & 31;
    const int gid = lane >> 2, tg = lane & 3;
    const int jp = (item >> 5) % npairs;
    const int s = item / (npairs * 32);
    const int k0 = s * 16 + tg * 2;

    uint32_t h[4], l[4];
#pragma unroll
    for (int half = 0; half < 2; ++half) {
        const int n = (jp * 2 + half) * 8 + gid;
        const float f00 = W[(size_t)k0 * ldW + n];
        const float f01 = W[(size_t)(k0 + 1) * ldW + n];
        const float f10 = W[(size_t)(k0 + 8) * ldW + n];
        const float f11 = W[(size_t)(k0 + 9) * ldW + n];
        float r00, r01, r10, r11, d0, d1;
        if (f16) {
            h[half * 2 + 0] = pack_h_pair(f00, f01, r00, r01);
            h[half * 2 + 1] = pack_h_pair(f10, f11, r10, r11);
            l[half * 2 + 0] = pack_h_pair(r00, r01, d0, d1);
            l[half * 2 + 1] = pack_h_pair(r10, r11, d0, d1);
        } else {
            h[half * 2 + 0] = pack_bf_pair(f00, f01, r00, r01);
            h[half * 2 + 1] = pack_bf_pair(f10, f11, r10, r11);
            l[half * 2 + 0] = pack_bf_pair(r00, r01, d0, d1);
            l[half * 2 + 1] = pack_bf_pair(r10, r11, d0, d1);
        }
    }
    const int dst = (s * npairs + jp) * 32 + lane;
    dH[dst] = make_uint4(h[0], h[1], h[2], h[3]);
    dL[dst] = make_uint4(l[0], l[1], l[2], l[3]);
}

__global__ void mega_pack_kernel(const float* __restrict__ eW1, const float* __restrict__ eW2,
                                 const float* __restrict__ nW1, const float* __restrict__ nW2,
                                 const float* __restrict__ nW3,
                                 const float* __restrict__ eb3, const float* __restrict__ nb1)
{
    const int idx = blockIdx.x * 256 + threadIdx.x;
    if (idx < 8192)        pack_item(eW1,             512, 32, g_eW1aH, g_eW1aL, false, idx);
    else if (idx < 16384)  pack_item(eW1 + 128 * 512, 512, 32, g_eW1bH, g_eW1bL, false, idx - 8192);
    else if (idx < 49152)  pack_item(eW2,             512, 32, g_W2H,   g_W2L,   true,  idx - 16384);
    else if (idx < 57344)  pack_item(nW1,             512, 32, g_nW1aH, g_nW1aL, false, idx - 49152);
    else if (idx < 90112)  pack_item(nW1 + 132 * 512, 512, 32, g_nW1cH, g_nW1cL, false, idx - 57344);
    else if (idx < 122880) pack_item(nW2,             512, 32, g_nW2H,  g_nW2L,  true,  idx - 90112);
    else if (idx < 131072) pack_item(nW3,             128, 8,  g_nW3H,  g_nW3L,  true,  idx - 122880);
    else if (idx < 131584) {
        const int n = idx - 131072;
        float acc = 0.f;
#pragma unroll 8
        for (int k = 0; k < 512; ++k)
            acc += eb3[k] * nW1[(size_t)(132 + k) * 512 + n];
        g_bp[n] = nb1[n] + 15.f * acc;
    }
}

__global__ void pack_frag_kernel(const float* __restrict__ W, int npairs,
                                 uint4* __restrict__ dstH, uint4* __restrict__ dstL, int f16)
{
    const int idx = blockIdx.x * 256 + threadIdx.x;
    pack_item(W, npairs * 16, npairs, dstH, dstL, f16 != 0, idx);
}

// ================= generic bf16 3-term GEMM (Wcomb only, 2-stage) =================
__global__ void __launch_bounds__(256, 1) wc_gemm_kernel(
    const float* __restrict__ X,
    const uint4* __restrict__ WH, const uint4* __restrict__ WL,
    float* __restrict__ out)
{
    extern __shared__ __align__(16) char smem[];
    const uint32_t sbase = smem_u32(smem);
    const int tid = threadIdx.x;
    const int bm = blockIdx.x * 64;
    const int A_ST = 1040;
    const uint32_t offALO = 64 * 1040;
    const uint32_t offB = 2 * offALO;

    for (int idx = tid; idx < 64 * 128; idx += 256) {
        const int m = idx >> 7, k4 = (idx & 127) << 2;
        const float4 v = *(const float4*)(X + (size_t)(bm + m) * 512 + k4);
        float rx, ry, rz, rw, d0, d1;
        uint2 hh, ll;
        hh.x = pack_bf_pair(v.x, v.y, rx, ry);
        hh.y = pack_bf_pair(v.z, v.w, rz, rw);
        ll.x = pack_bf_pair(rx, ry, d0, d1);
        ll.y = pack_bf_pair(rz, rw, d0, d1);
        const uint32_t off = (uint32_t)m * A_ST + ((uint32_t)k4 << 1);
        *(uint2*)(smem + off) = hh;
        *(uint2*)(smem + offALO + off) = ll;
    }
    __syncthreads();

    const int w = tid >> 5, lane = tid & 31;
    const int gid = lane >> 2, tg = lane & 3;
    const int lrow = (lane & 8) + (lane & 7);
    const uint32_t a_base = sbase + (uint32_t)lrow * A_ST + ((lane & 16) ? 16u : 0u);

    float acc[4][8][4];
#pragma unroll
    for (int mt = 0; mt < 4; ++mt)
#pragma unroll
        for (int nt = 0; nt < 8; ++nt)
#pragma unroll
            for (int j = 0; j < 4; ++j) acc[mt][nt][j] = 0.f;

    auto stageB = [&](int stage, int s) {
#pragma unroll
        for (int p = 0; p < 4; ++p) {
            const int jpg = w * 4 + p;
            const uint32_t d = sbase + offB +
                ((uint32_t)((stage * 32 + jpg) * 2) * 32 + lane) * 16;
            CP_ASYNC16(d, WH + ((size_t)(s * 32 + jpg) * 32 + lane));
            CP_ASYNC16(d + 512, WL + ((size_t)(s * 32 + jpg) * 32 + lane));
        }
    };
    stageB(0, 0); CP_COMMIT();
    for (int s = 0; s < 32; ++s) {
        const int cur = s & 1;
        if (s < 31) { stageB(cur ^ 1, s + 1); CP_COMMIT(); CP_WAIT1(); }
        else CP_WAIT0();
        uint4 vh[4], vl[4];
#pragma unroll
        for (int p = 0; p < 4; ++p) {
            const uint32_t aH = sbase + offB +
                ((uint32_t)((cur * 32 + w * 4 + p) * 2) * 32 + lane) * 16;
            vh[p] = lds128(aH);
            vl[p] = lds128(aH + 512);
        }
        uint32_t ah[4][4], al[4][4];
#pragma unroll
        for (int mt = 0; mt < 4; ++mt) {
            const uint32_t aoff = (uint32_t)mt * 16 * A_ST + (uint32_t)s * 32;
            ldsm4(ah[mt], a_base + aoff);
            ldsm4(al[mt], a_base + offALO + aoff);
        }
#pragma unroll
        for (int mt = 0; mt < 4; ++mt)
#pragma unroll
            for (int p = 0; p < 4; ++p) {
                mma_bf16(acc[mt][2 * p],     ah[mt], vh[p].x, vh[p].y);
                mma_bf16(acc[mt][2 * p + 1], ah[mt], vh[p].z, vh[p].w);
                mma_bf16(acc[mt][2 * p],     ah[mt], vl[p].x, vl[p].y);
                mma_bf16(acc[mt][2 * p + 1], ah[mt], vl[p].z, vl[p].w);
                mma_bf16(acc[mt][2 * p],     al[mt], vh[p].x, vh[p].y);
                mma_bf16(acc[mt][2 * p + 1], al[mt], vh[p].z, vh[p].w);
            }
    }
    const int colb = w * 64 + tg * 2;
#pragma unroll
    for (int mt = 0; mt < 4; ++mt) {
        const int r0 = bm + mt * 16 + gid, r1 = r0 + 8;
#pragma unroll
        for (int nt = 0; nt < 8; ++nt) {
            const int col = colb + nt * 8;
            *(float2*)(out + (size_t)r0 * 512 + col) = make_float2(acc[mt][nt][0], acc[mt][nt][1]);
            *(float2*)(out + (size_t)r1 * 512 + col) = make_float2(acc[mt][nt][2], acc[mt][nt][3]);
        }
    }
}

// ================= fused P/Q/T kernel (K=128, bf16 3-term, 4-stage) =================
#define PQT_A_ST 272
#define PQT_OFFALO (64 * 272)
#define PQT_OFFB   (2 * PQT_OFFALO)
#define SMEM_PQT (PQT_OFFB + 4 * 32768)

__global__ void __launch_bounds__(256, 1) pqt_kernel(
    const float* __restrict__ X, const float* __restrict__ actW,
    const int* __restrict__ action)
{
    extern __shared__ __align__(16) char smem[];
    const uint32_t sbase = smem_u32(smem);
    const int tid = threadIdx.x;
    const int bm = blockIdx.x * 64;
    const int w = tid >> 5, lane = tid & 31;
    const int gid = lane >> 2, tg = lane & 3;

    const uint4* WHs[3] = {g_eW1aH, g_eW1bH, g_nW1aH};
    const uint4* WLs[3] = {g_eW1aL, g_eW1bL, g_nW1aL};

    auto stageB = [&](const uint4* WH, const uint4* WL, int stage, int s) {
#pragma unroll
        for (int p = 0; p < 4; ++p) {
            const int jpg = w * 4 + p;
            const uint32_t d = sbase + PQT_OFFB +
                ((uint32_t)((stage * 32 + jpg) * 2) * 32 + lane) * 16;
            CP_ASYNC16(d, WH + ((size_t)(s * 32 + jpg) * 32 + lane));
            CP_ASYNC16(d + 512, WL + ((size_t)(s * 32 + jpg) * 32 + lane));
        }
    };

    // prologue staging of phase 0 overlaps A build
    stageB(WHs[0], WLs[0], 0, 0); CP_COMMIT();
    stageB(WHs[0], WLs[0], 1, 1); CP_COMMIT();
    stageB(WHs[0], WLs[0], 2, 2); CP_COMMIT();

    for (int idx = tid; idx < 64 * 32; idx += 256) {
        const int m = idx >> 5, k4 = (idx & 31) << 2;
        const float4 v = *(const float4*)(X + (size_t)(bm + m) * 128 + k4);
        float rx, ry, rz, rw, d0, d1;
        uint2 hh, ll;
        hh.x = pack_bf_pair(v.x, v.y, rx, ry);
        hh.y = pack_bf_pair(v.z, v.w, rz, rw);
        ll.x = pack_bf_pair(rx, ry, d0, d1);
        ll.y = pack_bf_pair(rz, rw, d0, d1);
        const uint32_t off = (uint32_t)m * PQT_A_ST + ((uint32_t)k4 << 1);
        *(uint2*)(smem + off) = hh;
        *(uint2*)(smem + PQT_OFFALO + off) = ll;
    }
    __syncthreads();

    const int lrow = (lane & 8) + (lane & 7);
    const uint32_t a_base = sbase + (uint32_t)lrow * PQT_A_ST + ((lane & 16) ? 16u : 0u);
    const int colb = w * 64 + tg * 2;

    for (int ph = 0; ph < 3; ++ph) {
        const uint4* WH = WHs[ph];
        const uint4* WL = WLs[ph];
        float acc[4][8][4];
#pragma unroll
        for (int mt = 0; mt < 4; ++mt)
#pragma unroll
            for (int nt = 0; nt < 8; ++nt)
#pragma unroll
                for (int j = 0; j < 4; ++j) acc[mt][nt][j] = 0.f;

        if (ph > 0) {   // prologue for phases 1,2
            stageB(WH, WL, 0, 0); CP_COMMIT();
            stageB(WH, WL, 1, 1); CP_COMMIT();
            stageB(WH, WL, 2, 2); CP_COMMIT();
        }
        for (int s = 0; s < 8; ++s) {
            if (s + 3 < 8) { stageB(WH, WL, (s + 3) & 3, s + 3); CP_COMMIT(); }
            const int rem = 7 - s;
            if (rem >= 3) CP_WAIT3(); else if (rem == 2) CP_WAIT2();
            else if (rem == 1) CP_WAIT1(); else CP_WAIT0();

            const int cur = s & 3;
            uint4 vh[4], vl[4];
#pragma unroll
            for (int p = 0; p < 4; ++p) {
                const uint32_t aH = sbase + PQT_OFFB +
                    ((uint32_t)((cur * 32 + w * 4 + p) * 2) * 32 + lane) * 16;
                vh[p] = lds128(aH);
                vl[p] = lds128(aH + 512);
            }
            uint32_t ah[4][4], al[4][4];
#pragma unroll
            for (int mt = 0; mt < 4; ++mt) {
                const uint32_t aoff = (uint32_t)mt * 16 * PQT_A_ST + (uint32_t)s * 32;
                ldsm4(ah[mt], a_base + aoff);
                ldsm4(al[mt], a_base + PQT_OFFALO + aoff);
            }
#pragma unroll
            for (int mt = 0; mt < 4; ++mt)
#pragma unroll
                for (int p = 0; p < 4; ++p) {
                    mma_bf16(acc[mt][2 * p],     ah[mt], vh[p].x, vh[p].y);
                    mma_bf16(acc[mt][2 * p + 1], ah[mt], vh[p].z, vh[p].w);
                    mma_bf16(acc[mt][2 * p],     ah[mt], vl[p].x, vl[p].y);
                    mma_bf16(acc[mt][2 * p + 1], ah[mt], vl[p].z, vl[p].w);
                    mma_bf16(acc[mt][2 * p],     al[mt], vh[p].x, vh[p].y);
                    mma_bf16(acc[mt][2 * p + 1], al[mt], vh[p].z, vh[p].w);
                }
        }

#pragma unroll
        for (int mt = 0; mt < 4; ++mt) {
            const int r0 = bm + mt * 16 + gid, r1 = r0 + 8;
#pragma unroll
            for (int nt = 0; nt < 8; ++nt) {
                const int col = colb + nt * 8;
                float v00 = acc[mt][nt][0], v01 = acc[mt][nt][1];
                float v10 = acc[mt][nt][2], v11 = acc[mt][nt][3];
                if (ph == 2) {
                    const float b0 = g_bp[col], b1 = g_bp[col + 1];
                    v00 += b0; v01 += b1; v10 += b0; v11 += b1;
                    const int a = action[r0 >> 4];
                    const int t0 = a - 4 * (r0 & 15);
                    const int t1 = a - 4 * (r1 & 15);
                    if ((unsigned)t0 < 4u) {
                        v00 += __ldg(actW + (size_t)t0 * 512 + col);
                        v01 += __ldg(actW + (size_t)t0 * 512 + col + 1);
                    }
                    if ((unsigned)t1 < 4u) {
                        v10 += __ldg(actW + (size_t)t1 * 512 + col);
                        v11 += __ldg(actW + (size_t)t1 * 512 + col + 1);
                    }
                    *(float2*)&g_T[(size_t)r0 * 512 + col] = make_float2(v00, v01);
                    *(float2*)&g_T[(size_t)r1 * 512 + col] = make_float2(v10, v11);
                } else {
                    const int co = (ph == 1) ? 512 : 0;
                    *(float2*)&g_PQ[(size_t)r0 * 1024 + co + col] = make_float2(v00, v01);
                    *(float2*)&g_PQ[(size_t)r1 * 1024 + co + col] = make_float2(v10, v11);
                }
            }
        }
    }
}

// ---------------- edge kernel: fp16 2-term, 4-stage ----------------
#define A_STRIDE 1040
#define OFF_BBUF  66560
#define OFF_B2    197632
#define OFF_GS    199680
#define OFF_BSS   201728
#define OFF_PS    203776
#define OFF_PQS   205824
#define OFF_MU    207872
#define OFF_RS    208128
#define SMEM_EDGE 208384

__device__ __forceinline__ void stage_B_edge(uint32_t sbase, int stage, int s, int w, int lane)
{
#pragma unroll
    for (int p = 0; p < 4; ++p) {
        const int jpg = w * 4 + p;
        const uint32_t dH = sbase + OFF_BBUF +
            ((uint32_t)((stage * 32 + jpg) * 2) * 32 + lane) * 16;
        CP_ASYNC16(dH, g_W2H + ((size_t)(s * 32 + jpg) * 32 + lane));
        CP_ASYNC16(dH + 512, g_W2L + ((size_t)(s * 32 + jpg) * 32 + lane));
    }
}

__global__ void __launch_bounds__(256, 1) edge_mma_kernel(
    const float* __restrict__ eb1, const float* __restrict__ b2,
    const float* __restrict__ gam, const float* __restrict__ bet)
{
    extern __shared__ __align__(16) char smem[];
    const uint32_t sbase = smem_u32(smem);
    const int tid = threadIdx.x;
    const int nb = blockIdx.x;
    const int node_base = nb * 4;
    const int b16 = (nb >> 2) << 4;
    const int o0 = (nb & 3) * 4;
    const int w = tid >> 5, lane = tid & 31;

    float* b2s = (float*)(smem + OFF_B2);
    float* gss = (float*)(smem + OFF_GS);
    float* bss = (float*)(smem + OFF_BSS);
    float* ps  = (float*)(smem + OFF_PS);
    float* pq  = (float*)(smem + OFF_PQS);
    float* mus = (float*)(smem + OFF_MU);
    float* rss = (float*)(smem + OFF_RS);

    // prologue staging overlaps A build
    stage_B_edge(sbase, 0, 0, w, lane); CP_COMMIT();
    stage_B_edge(sbase, 1, 1, w, lane); CP_COMMIT();
    stage_B_edge(sbase, 2, 2, w, lane); CP_COMMIT();

    for (int i = tid; i < 512; i += 256) {
        b2s[i] = b2[i]; gss[i] = gam[i]; bss[i] = bet[i];
    }
    const float4* eb1v = (const float4*)eb1;
#pragma unroll
    for (int i = 0; i < 32; ++i) {
        const int idx = tid + (i << 8);
        const int m = idx >> 7;
        const int k4 = (idx & 127) << 2;
        const int ln = m >> 4, r = m & 15;
        float4 v = make_float4(0.f, 0.f, 0.f, 0.f);
        if (r < 15) {
            const int o = o0 + ln;
            const int jj = r + (r >= o);
            const float4 p4 = *(const float4*)&g_PQ[(size_t)(node_base + ln) * 1024 + k4];
            const float4 q4 = *(const float4*)&g_PQ[(size_t)(b16 + jj) * 1024 + 512 + k4];
            const float4 bb = __ldg(&eb1v[k4 >> 2]);
            v.x = fmaxf(p4.x + q4.x + bb.x, 0.f);
            v.y = fmaxf(p4.y + q4.y + bb.y, 0.f);
            v.z = fmaxf(p4.z + q4.z + bb.z, 0.f);
            v.w = fmaxf(p4.w + q4.w + bb.w, 0.f);
        }
        float rx, ry, rz, rw;
        uint2 hh;
        hh.x = pack_h_pair(v.x, v.y, rx, ry);
        hh.y = pack_h_pair(v.z, v.w, rz, rw);
        *(uint2*)(smem + (uint32_t)m * A_STRIDE + ((uint32_t)k4 << 1)) = hh;
    }
    __syncthreads();

    const int gid = lane >> 2, tg = lane & 3;
    const int lrow = (lane & 8) + (lane & 7);
    const uint32_t a_base = sbase + (uint32_t)lrow * A_STRIDE + ((lane & 16) ? 16u : 0u);

    float acc[4][8][4];
#pragma unroll
    for (int mt = 0; mt < 4; ++mt)
#pragma unroll
        for (int nt = 0; nt < 8; ++nt)
#pragma unroll
            for (int j = 0; j < 4; ++j) acc[mt][nt][j] = 0.f;

    for (int s = 0; s < 32; ++s) {
        if (s < 29) { stage_B_edge(sbase, (s + 3) & 3, s + 3, w, lane); CP_COMMIT(); CP_WAIT3(); }
        else if (s == 29) CP_WAIT2();
        else if (s == 30) CP_WAIT1();
        else CP_WAIT0();

        const int cur = s & 3;
        uint4 vh[4], vl[4];
#pragma unroll
        for (int p = 0; p < 4; ++p) {
            const uint32_t aH = sbase + OFF_BBUF +
                ((uint32_t)((cur * 32 + w * 4 + p) * 2) * 32 + lane) * 16;
            vh[p] = lds128(aH);
            vl[p] = lds128(aH + 512);
        }
        uint32_t ah[4][4];
#pragma unroll
        for (int mt = 0; mt < 4; ++mt)
            ldsm4(ah[mt], a_base + (uint32_t)mt * (16 * A_STRIDE) + (uint32_t)s * 32);
#pragma unroll
        for (int mt = 0; mt < 4; ++mt)
#pragma unroll
            for (int p = 0; p < 4; ++p) {
                mma_f16(acc[mt][2 * p],     ah[mt], vh[p].x, vh[p].y);
                mma_f16(acc[mt][2 * p + 1], ah[mt], vh[p].z, vh[p].w);
            }
#pragma unroll
        for (int mt = 0; mt < 4; ++mt)
#pragma unroll
            for (int p = 0; p < 4; ++p) {
                mma_f16(acc[mt][2 * p],     ah[mt], vl[p].x, vl[p].y);
                mma_f16(acc[mt][2 * p + 1], ah[mt], vl[p].z, vl[p].w);
            }
    }

    const int colb = w * 64 + tg * 2;
    float b2v[8][2];
#pragma unroll
    for (int nt = 0; nt < 8; ++nt) {
        b2v[nt][0] = b2s[colb + nt * 8];
        b2v[nt][1] = b2s[colb + nt * 8 + 1];
    }
#pragma unroll
    for (int mt = 0; mt < 4; ++mt) {
        float s0 = 0.f, q0 = 0.f, s1 = 0.f, q1 = 0.f;
#pragma unroll
        for (int nt = 0; nt < 8; ++nt) {
            const float v00 = acc[mt][nt][0] + b2v[nt][0];
            const float v01 = acc[mt][nt][1] + b2v[nt][1];
            const float v10 = acc[mt][nt][2] + b2v[nt][0];
            const float v11 = acc[mt][nt][3] + b2v[nt][1];
            acc[mt][nt][0] = v00; acc[mt][nt][1] = v01;
            acc[mt][nt][2] = v10; acc[mt][nt][3] = v11;
            s0 += v00 + v01; q0 += v00 * v00 + v01 * v01;
            s1 += v10 + v11; q1 += v10 * v10 + v11 * v11;
        }
#pragma unroll
        for (int off = 1; off <= 2; off <<= 1) {
            s0 += __shfl_xor_sync(0xffffffffu, s0, off);
            q0 += __shfl_xor_sync(0xffffffffu, q0, off);
            s1 += __shfl_xor_sync(0xffffffffu, s1, off);
            q1 += __shfl_xor_sync(0xffffffffu, q1, off);
        }
        if (tg == 0) {
            ps[(mt * 16 + gid) * 8 + w] = s0;     pq[(mt * 16 + gid) * 8 + w] = q0;
            ps[(mt * 16 + 8 + gid) * 8 + w] = s1; pq[(mt * 16 + 8 + gid) * 8 + w] = q1;
        }
    }
    __syncthreads();
    if (tid < 64) {
        float s = 0.f, q = 0.f;
#pragma unroll
        for (int ww = 0; ww < 8; ++ww) { s += ps[tid * 8 + ww]; q += pq[tid * 8 + ww]; }
        const float mu = s * (1.f / 512.f);
        mus[tid] = mu;
        rss[tid] = rsqrtf(q * (1.f / 512.f) - mu * mu + LN_EPS);
    }
    __syncthreads();

    float gv[8][2], bv[8][2];
#pragma unroll
    for (int nt = 0; nt < 8; ++nt) {
        gv[nt][0] = gss[colb + nt * 8];     gv[nt][1] = gss[colb + nt * 8 + 1];
        bv[nt][0] = bss[colb + nt * 8];     bv[nt][1] = bss[colb + nt * 8 + 1];
    }
#pragma unroll
    for (int mt = 0; mt < 4; ++mt) {
        const float mu0 = mus[mt * 16 + gid],     r0 = rss[mt * 16 + gid];
        const float mu1 = mus[mt * 16 + 8 + gid], r1 = rss[mt * 16 + 8 + gid];
        const bool last = (gid == 7);
#pragma unroll
        for (int nt = 0; nt < 8; ++nt) {
            const float v00 = fmaxf((acc[mt][nt][0] - mu0) * r0 * gv[nt][0] + bv[nt][0], 0.f);
            const float v01 = fmaxf((acc[mt][nt][1] - mu0) * r0 * gv[nt][1] + bv[nt][1], 0.f);
            const float v10 = last ? 0.f : fmaxf((acc[mt][nt][2] - mu1) * r1 * gv[nt][0] + bv[nt][0], 0.f);
            const float v11 = last ? 0.f : fmaxf((acc[mt][nt][3] - mu1) * r1 * gv[nt][1] + bv[nt][1], 0.f);
            float t0 = v00 + v10, t1 = v01 + v11;
#pragma unroll
            for (int off = 4; off <= 16; off <<= 1) {
                t0 += __shfl_xor_sync(0xffffffffu, t0, off);
                t1 += __shfl_xor_sync(0xffffffffu, t1, off);
            }
            if (lane < 4)
                *(float2*)&g_S[(size_t)(node_base + mt) * 512 + colb + nt * 8] =
                    make_float2(t0, t1);
        }
    }
}

// ---------------- fused tail: H1 -> H2 -> out, one kernel ----------------
#define T_OFFB   66560
#define T_OFFPS  197632
#define T_OFFPQ  199680
#define T_OFFMU  201728
#define T_OFFRS  201984
#define SMEM_TAIL 202240

__global__ void __launch_bounds__(256, 1) tail_kernel(
    const float* __restrict__ Tm, const float* __restrict__ nb2,
    const float* __restrict__ gam, const float* __restrict__ bet,
    const float* __restrict__ nb3, float* __restrict__ out)
{
    extern __shared__ __align__(16) char smem[];
    const uint32_t sbase = smem_u32(smem);
    const int tid = threadIdx.x;
    const int bm = blockIdx.x * 64;
    const int w = tid >> 5, lane = tid & 31;
    const int gid = lane >> 2, tg = lane & 3;
    const int lrow = (lane & 8) + (lane & 7);
    const uint32_t a_base = sbase + (uint32_t)lrow * A_STRIDE + ((lane & 16) ? 16u : 0u);
    const int colb = w * 64 + tg * 2;
    float* ps  = (float*)(smem + T_OFFPS);
    float* pq  = (float*)(smem + T_OFFPQ);
    float* mus = (float*)(smem + T_OFFMU);
    float* rss = (float*)(smem + T_OFFRS);

    auto stage512 = [&](const uint4* WH, const uint4* WL, int stage, int s) {
#pragma unroll
        for (int p = 0; p < 4; ++p) {
            const int jpg = w * 4 + p;
            const uint32_t d = sbase + T_OFFB +
                ((uint32_t)((stage * 32 + jpg) * 2) * 32 + lane) * 16;
            CP_ASYNC16(d, WH + ((size_t)(s * 32 + jpg) * 32 + lane));
            CP_ASYNC16(d + 512, WL + ((size_t)(s * 32 + jpg) * 32 + lane));
        }
    };

    float acc[4][8][4];

    auto run512 = [&](const uint4* WH, const uint4* WL) {
#pragma unroll
        for (int mt = 0; mt < 4; ++mt)
#pragma unroll
            for (int nt = 0; nt < 8; ++nt)
#pragma unroll
                for (int j = 0; j < 4; ++j) acc[mt][nt][j] = 0.f;
        for (int s = 0; s < 32; ++s) {
            if (s < 29) { stage512(WH, WL, (s + 3) & 3, s + 3); CP_COMMIT(); CP_WAIT3(); }
            else if (s == 29) CP_WAIT2();
            else if (s == 30) CP_WAIT1();
            else CP_WAIT0();
            const int cur = s & 3;
            uint4 vh[4], vl[4];
#pragma unroll
            for (int p = 0; p < 4; ++p) {
                const uint32_t aH = sbase + T_OFFB +
                    ((uint32_t)((cur * 32 + w * 4 + p) * 2) * 32 + lane) * 16;
                vh[p] = lds128(aH);
                vl[p] = lds128(aH + 512);
            }
            uint32_t ah[4][4];
#pragma unroll
            for (int mt = 0; mt < 4; ++mt)
                ldsm4(ah[mt], a_base + (uint32_t)mt * (16 * A_STRIDE) + (uint32_t)s * 32);
#pragma unroll
            for (int mt = 0; mt < 4; ++mt)
#pragma unroll
                for (int p = 0; p < 4; ++p) {
                    mma_f16(acc[mt][2 * p],     ah[mt], vh[p].x, vh[p].y);
                    mma_f16(acc[mt][2 * p + 1], ah[mt], vh[p].z, vh[p].w);
                }
#pragma unroll
            for (int mt = 0; mt < 4; ++mt)
#pragma unroll
                for (int p = 0; p < 4; ++p) {
                    mma_f16(acc[mt][2 * p],     ah[mt], vl[p].x, vl[p].y);
                    mma_f16(acc[mt][2 * p + 1], ah[mt], vl[p].z, vl[p].w);
                }
        }
    };

    auto write_frags = [&]() {
        __syncthreads();
#pragma unroll
        for (int mt = 0; mt < 4; ++mt) {
            const int m0 = mt * 16 + gid, m1 = m0 + 8;
#pragma unroll
            for (int nt = 0; nt < 8; ++nt) {
                const int col = colb + nt * 8;
                float d0, d1;
                *(uint32_t*)(smem + (uint32_t)m0 * A_STRIDE + col * 2) =
                    pack_h_pair(acc[mt][nt][0], acc[mt][nt][1], d0, d1);
                *(uint32_t*)(smem + (uint32_t)m1 * A_STRIDE + col * 2) =
                    pack_h_pair(acc[mt][nt][2], acc[mt][nt][3], d0, d1);
            }
        }
        __syncthreads();
    };

    // prologue staging loop1 (overlaps A build)
    stage512(g_WcH, g_WcL, 0, 0); CP_COMMIT();
    stage512(g_WcH, g_WcL, 1, 1); CP_COMMIT();
    stage512(g_WcH, g_WcL, 2, 2); CP_COMMIT();

    // build A from g_S
    for (int idx = tid; idx < 64 * 128; idx += 256) {
        const int m = idx >> 7, k4 = (idx & 127) << 2;
        const float4 v = *(const float4*)&g_S[(size_t)(bm + m) * 512 + k4];
        float rx, ry, rz, rw;
        uint2 hh;
        hh.x = pack_h_pair(v.x, v.y, rx, ry);
        hh.y = pack_h_pair(v.z, v.w, rz, rw);
        *(uint2*)(smem + (uint32_t)m * A_STRIDE + ((uint32_t)k4 << 1)) = hh;
    }
    __syncthreads();

    // ---- loop1: H1 = relu(S@Wc + T) ----
    run512(g_WcH, g_WcL);
#pragma unroll
    for (int mt = 0; mt < 4; ++mt) {
        const int r0 = bm + mt * 16 + gid, r1 = r0 + 8;
#pragma unroll
        for (int nt = 0; nt < 8; ++nt) {
            const int col = colb + nt * 8;
            const float2 a0 = *(const float2*)(Tm + (size_t)r0 * 512 + col);
            const float2 a1 = *(const float2*)(Tm + (size_t)r1 * 512 + col);
            acc[mt][nt][0] = fmaxf(acc[mt][nt][0] + a0.x, 0.f);
            acc[mt][nt][1] = fmaxf(acc[mt][nt][1] + a0.y, 0.f);
            acc[mt][nt][2] = fmaxf(acc[mt][nt][2] + a1.x, 0.f);
            acc[mt][nt][3] = fmaxf(acc[mt][nt][3] + a1.y, 0.f);
        }
    }
    write_frags();

    // ---- loop2: H2 = relu(LN(H1@nW2 + nb2)) ----
    stage512(g_nW2H, g_nW2L, 0, 0); CP_COMMIT();
    stage512(g_nW2H, g_nW2L, 1, 1); CP_COMMIT();
    stage512(g_nW2H, g_nW2L, 2, 2); CP_COMMIT();
    run512(g_nW2H, g_nW2L);

#pragma unroll
    for (int mt = 0; mt < 4; ++mt) {
        float s0 = 0.f, q0 = 0.f, s1 = 0.f, q1 = 0.f;
#pragma unroll
        for (int nt = 0; nt < 8; ++nt) {
            const int col = colb + nt * 8;
            const float b0 = __ldg(nb2 + col), b1 = __ldg(nb2 + col + 1);
            const float v00 = acc[mt][nt][0] + b0;
            const float v01 = acc[mt][nt][1] + b1;
            const float v10 = acc[mt][nt][2] + b0;
            const float v11 = acc[mt][nt][3] + b1;
            acc[mt][nt][0] = v00; acc[mt][nt][1] = v01;
            acc[mt][nt][2] = v10; acc[mt][nt][3] = v11;
            s0 += v00 + v01; q0 += v00 * v00 + v01 * v01;
            s1 += v10 + v11; q1 += v10 * v10 + v11 * v11;
        }
#pragma unroll
        for (int off = 1; off <= 2; off <<= 1) {
            s0 += __shfl_xor_sync(0xffffffffu, s0, off);
            q0 += __shfl_xor_sync(0xffffffffu, q0, off);
            s1 += __shfl_xor_sync(0xffffffffu, s1, off);
            q1 += __shfl_xor_sync(0xffffffffu, q1, off);
        }
        if (tg == 0) {
            ps[(mt * 16 + gid) * 8 + w] = s0;     pq[(mt * 16 + gid) * 8 + w] = q0;
            ps[(mt * 16 + 8 + gid) * 8 + w] = s1; pq[(mt * 16 + 8 + gid) * 8 + w] = q1;
        }
    }
    __syncthreads();
    if (tid < 64) {
        float s = 0.f, q = 0.f;
#pragma unroll
        for (int ww = 0; ww < 8; ++ww) { s += ps[tid * 8 + ww]; q += pq[tid * 8 + ww]; }
        const float mu = s * (1.f / 512.f);
        mus[tid] = mu;
        rss[tid] = rsqrtf(q * (1.f / 512.f) - mu * mu + LN_EPS);
    }
    __syncthreads();
#pragma unroll
    for (int mt = 0; mt < 4; ++mt) {
        const float mu0 = mus[mt * 16 + gid],     rv0 = rss[mt * 16 + gid];
        const float mu1 = mus[mt * 16 + 8 + gid], rv1 = rss[mt * 16 + 8 + gid];
#pragma unroll
        for (int nt = 0; nt < 8; ++nt) {
            const int col = colb + nt * 8;
            const float g0 = __ldg(gam + col), g1 = __ldg(gam + col + 1);
            const float be0 = __ldg(bet + col), be1 = __ldg(bet + col + 1);
            acc[mt][nt][0] = fmaxf((acc[mt][nt][0] - mu0) * rv0 * g0 + be0, 0.f);
            acc[mt][nt][1] = fmaxf((acc[mt][nt][1] - mu0) * rv0 * g1 + be1, 0.f);
            acc[mt][nt][2] = fmaxf((acc[mt][nt][2] - mu1) * rv1 * g0 + be0, 0.f);
            acc[mt][nt][3] = fmaxf((acc[mt][nt][3] - mu1) * rv1 * g1 + be1, 0.f);
        }
    }
    write_frags();

    // ---- loop3: out = H2@nW3 + nb3  (N=128, fp16 2-term) ----
    auto stage128 = [&](int stage, int s) {
        const uint32_t d = sbase + T_OFFB + (uint32_t)stage * 8192 +
            ((uint32_t)(w * 2) * 32 + lane) * 16;
        CP_ASYNC16(d, g_nW3H + ((size_t)(s * 8 + w) * 32 + lane));
        CP_ASYNC16(d + 512, g_nW3L + ((size_t)(s * 8 + w) * 32 + lane));
    };
    stage128(0, 0); CP_COMMIT();
    stage128(1, 1); CP_COMMIT();
    stage128(2, 2); CP_COMMIT();

    float acc3[4][2][4];
#pragma unroll
    for (int mt = 0; mt < 4; ++mt)
#pragma unroll
        for (int nt = 0; nt < 2; ++nt)
#pragma unroll
            for (int j = 0; j < 4; ++j) acc3[mt][nt][j] = 0.f;

    for (int s = 0; s < 32; ++s) {
        if (s < 29) { stage128((s + 3) & 3, s + 3); CP_COMMIT(); CP_WAIT3(); }
        else if (s == 29) CP_WAIT2();
        else if (s == 30) CP_WAIT1();
        else CP_WAIT0();
        const int cur = s & 3;
        const uint32_t aH = sbase + T_OFFB + (uint32_t)cur * 8192 +
            ((uint32_t)(w * 2) * 32 + lane) * 16;
        const uint4 vh = lds128(aH);
        const uint4 vl = lds128(aH + 512);
        uint32_t ah[4][4];
#pragma unroll
        for (int mt = 0; mt < 4; ++mt)
            ldsm4(ah[mt], a_base + (uint32_t)mt * (16 * A_STRIDE) + (uint32_t)s * 32);
#pragma unroll
        for (int mt = 0; mt < 4; ++mt) {
            mma_f16(acc3[mt][0], ah[mt], vh.x, vh.y);
            mma_f16(acc3[mt][1], ah[mt], vh.z, vh.w);
        }
#pragma unroll
        for (int mt = 0; mt < 4; ++mt) {
            mma_f16(acc3[mt][0], ah[mt], vl.x, vl.y);
            mma_f16(acc3[mt][1], ah[mt], vl.z, vl.w);
        }
    }
    const int colb3 = w * 16 + tg * 2;
#pragma unroll
    for (int mt = 0; mt < 4; ++mt) {
        const int r0 = bm + mt * 16 + gid, r1 = r0 + 8;
#pragma unroll
        for (int nt = 0; nt < 2; ++nt) {
            const int col = colb3 + nt * 8;
            const float b0 = __ldg(nb3 + col), b1 = __ldg(nb3 + col + 1);
            *(float2*)(out + (size_t)r0 * 128 + col) =
                make_float2(acc3[mt][nt][0] + b0, acc3[mt][nt][1] + b1);
            *(float2*)(out + (size_t)r1 * 128 + col) =
                make_float2(acc3[mt][nt][2] + b0, acc3[mt][nt][3] + b1);
        }
    }
}

// ---------------- launch ----------------
#define SMEM_WC (2 * 64 * 1040 + 2 * 32768 + 1024)

extern "C" void kernel_launch(void* const* d_in, const int* in_sizes, int n_in,
                              void* d_out, int out_size)
{
    const float* states = (const float*)d_in[0];
    const int*   action = (const int*)d_in[1];
    const float* eW1 = (const float*)d_in[2];
    const float* eb1 = (const float*)d_in[3];
    const float* eW2 = (const float*)d_in[4];
    const float* eb2 = (const float*)d_in[5];
    const float* eg  = (const float*)d_in[6];
    const float* ebt = (const float*)d_in[7];
    const float* eW3 = (const float*)d_in[8];
    const float* eb3 = (const float*)d_in[9];
    const float* nW1 = (const float*)d_in[10];
    const float* nb1 = (const float*)d_in[11];
    const float* nW2 = (const float*)d_in[12];
    const float* nb2 = (const float*)d_in[13];
    const float* ng  = (const float*)d_in[14];
    const float* nbt = (const float*)d_in[15];
    const float* nW3 = (const float*)d_in[16];
    const float* nb3 = (const float*)d_in[17];
    float* out = (float*)d_out;

    float *pT, *pH1;
    cudaGetSymbolAddress((void**)&pT,  g_T);
    cudaGetSymbolAddress((void**)&pH1, g_H1);

    uint4 *nW1cH, *nW1cL, *WcH, *WcL;
    cudaGetSymbolAddress((void**)&nW1cH, g_nW1cH);
    cudaGetSymbolAddress((void**)&nW1cL, g_nW1cL);
    cudaGetSymbolAddress((void**)&WcH, g_WcH);
    cudaGetSymbolAddress((void**)&WcL, g_WcL);

    static int configured = 0;
    if (!configured) {
        cudaFuncSetAttribute(edge_mma_kernel,
                             cudaFuncAttributeMaxDynamicSharedMemorySize, SMEM_EDGE);
        cudaFuncSetAttribute(pqt_kernel,
                             cudaFuncAttributeMaxDynamicSharedMemorySize, SMEM_PQT);
        cudaFuncSetAttribute(tail_kernel,
                             cudaFuncAttributeMaxDynamicSharedMemorySize, SMEM_TAIL);
        cudaFuncSetAttribute(wc_gemm_kernel,
                             cudaFuncAttributeMaxDynamicSharedMemorySize, SMEM_WC);
        configured = 1;
    }

    // 1) pack all weights + bprime
    mega_pack_kernel<<<514, 256>>>(eW1, eW2, nW1, nW2, nW3, eb3, nb1);
    // 2) Wcomb = eW3 @ nW1c (bf16 3-term), pack to fp16
    wc_gemm_kernel<<<8, 256, SMEM_WC>>>(eW3, nW1cH, nW1cL, pH1);
    pack_frag_kernel<<<128, 256>>>(pH1, 32, WcH, WcL, 1);
    // 3) fused P/Q/T
    pqt_kernel<<<NNODE / 64, 256, SMEM_PQT>>>(states, nW1 + 128 * 512, action);
    // 4) fused edge layer -> S
    edge_mma_kernel<<<NNODE / 4, 256, SMEM_EDGE>>>(eb1, eb2, eg, ebt);
    // 5) fused tail: H1 -> H2 -> out
    tail_kernel<<<NNODE / 64, 256, SMEM_TAIL>>>(pT, nb2, ng, nbt, nb3, out);
}